// round 3
// baseline (speedup 1.0000x reference)
#include <cuda_runtime.h>
#include <math.h>

// ---------------------------------------------------------------------------
// Scratch (device globals -- no runtime allocation allowed)
// ---------------------------------------------------------------------------
__device__ float g_bufA[1024u * 256u * 256u];   // 256 MB: h1 / h3 / r1 / r3
__device__ float g_bufB[512u * 256u * 256u];    // 128 MB: h2 / r2
__device__ float g_field[2 * 256 * 256];        // refinement field
__device__ float g_bin[128 * 128];              // thresholded classification

#define KC 8   // input-channel chunk per smem stage

// ---------------------------------------------------------------------------
// 3x3 SAME conv, NCHW, implicit GEMM.
// Block = 256 threads, computes 64 Cout x 64 pixels (one 64-wide row segment).
// Thread micro-tile: 4 co x 4 px.  K loop chunks 8 input channels at a time.
// Weight smem is k-major ([ci][k][co]) so compute-phase weight reads are
// float4 (FMA:LDS inst ratio ~144:15 per channel -> FMA-pipe bound).
// ---------------------------------------------------------------------------
__global__ __launch_bounds__(256) void conv3x3_kernel(
    const float* __restrict__ in, const float* __restrict__ wgt,
    const float* __restrict__ bias, float* __restrict__ out,
    int Cin, int Cout, int H, int W, int doRelu)
{
    __shared__ __align__(16) float sIn[KC][3][68];  // 66 cols used (64 + halo)
    __shared__ __align__(16) float sW[KC][9][68];   // co padded 64->68 (banks)

    const int xtiles = W >> 6;                       // 2 or 4 (power of 2)
    const int tileX  = (blockIdx.x & (xtiles - 1)) << 6;
    const int y      = blockIdx.x / xtiles;
    const int coTile = blockIdx.y << 6;

    const int tid  = threadIdx.x;
    const int co0  = (tid >> 4) << 2;   // 0..60
    const int px0  = (tid & 15) << 2;   // 0..60
    const int warp = tid >> 5;
    const int lane = tid & 31;

    float acc[4][4];
#pragma unroll
    for (int i = 0; i < 4; i++)
#pragma unroll
        for (int j = 0; j < 4; j++) acc[i][j] = 0.f;

    for (int ci0 = 0; ci0 < Cin; ci0 += KC) {
        __syncthreads();
        // ---- load input halo tile: KC channels x 3 rows x 66 cols ----
        for (int r = warp; r < KC * 3; r += 8) {
            int ci = r / 3;
            int ky = r - ci * 3;
            int gy = y + ky - 1;
            bool yok = ((unsigned)gy < (unsigned)H);
            for (int j = lane; j < 66; j += 32) {
                int gx = tileX - 1 + j;
                float v = 0.f;
                if (yok && (unsigned)gx < (unsigned)W)
                    v = in[((ci0 + ci) * H + gy) * W + gx];
                sIn[ci][ky][j] = v;
            }
        }
        // ---- load weights: 64 co x KC ci x 9, store k-major ----
        for (int idx = tid; idx < 64 * KC * 9; idx += 256) {
            int co  = idx / (KC * 9);
            int rem = idx - co * (KC * 9);
            int ci  = rem / 9;
            int k   = rem - ci * 9;
            sW[ci][k][co] = wgt[((coTile + co) * Cin + (ci0 + ci)) * 9 + k];
        }
        __syncthreads();

        // ---- compute ----
#pragma unroll
        for (int ci = 0; ci < KC; ci++) {
            float4 wr[9];
#pragma unroll
            for (int k = 0; k < 9; k++)
                wr[k] = *(const float4*)&sW[ci][k][co0];
#pragma unroll
            for (int ky = 0; ky < 3; ky++) {
                float4 a  = *(const float4*)&sIn[ci][ky][px0];
                float2 b2 = *(const float2*)&sIn[ci][ky][px0 + 4];
                float xin[6] = {a.x, a.y, a.z, a.w, b2.x, b2.y};
#pragma unroll
                for (int kx = 0; kx < 3; kx++) {
                    float4 wv = wr[ky * 3 + kx];
#pragma unroll
                    for (int p = 0; p < 4; p++) {
                        float iv = xin[p + kx];
                        acc[0][p] = fmaf(wv.x, iv, acc[0][p]);
                        acc[1][p] = fmaf(wv.y, iv, acc[1][p]);
                        acc[2][p] = fmaf(wv.z, iv, acc[2][p]);
                        acc[3][p] = fmaf(wv.w, iv, acc[3][p]);
                    }
                }
            }
        }
    }

    // ---- epilogue ----
#pragma unroll
    for (int c = 0; c < 4; c++) {
        int co = coTile + co0 + c;
        float bv = bias[co];
        float* dst = out + (co * H + y) * W + tileX + px0;
#pragma unroll
        for (int p = 0; p < 4; p++) {
            float v = acc[c][p] + bv;
            if (doRelu) v = fmaxf(v, 0.f);
            dst[p] = v;
        }
    }
}

// ---------------------------------------------------------------------------
// 1x1 conv 256->1 + sigmoid + threshold (classification head)
// ---------------------------------------------------------------------------
__global__ void cls_kernel(const float* __restrict__ h, const float* __restrict__ w,
                           const float* __restrict__ b, float* __restrict__ cls,
                           float* __restrict__ bin, int HW)
{
    int p = blockIdx.x * 256 + threadIdx.x;
    if (p >= HW) return;
    float s = b[0];
#pragma unroll 8
    for (int c = 0; c < 256; c++) s = fmaf(w[c], h[c * HW + p], s);
    float sig = 1.f / (1.f + expf(-s));
    cls[p] = sig;
    bin[p] = (sig >= 0.5f) ? 1.f : 0.f;
}

// ---------------------------------------------------------------------------
// 1x1 conv 256->2 (refinement field head)
// ---------------------------------------------------------------------------
__global__ void field_kernel(const float* __restrict__ r, const float* __restrict__ w,
                             const float* __restrict__ b, float* __restrict__ field,
                             int HW)
{
    int p = blockIdx.x * 256 + threadIdx.x;
    if (p >= HW) return;
    float s0 = b[0], s1 = b[1];
#pragma unroll 8
    for (int c = 0; c < 256; c++) {
        float v = r[c * HW + p];
        s0 = fmaf(w[c], v, s0);
        s1 = fmaf(w[256 + c], v, s1);
    }
    field[p] = s0;
    field[HW + p] = s1;
}

// ---------------------------------------------------------------------------
// 2x bilinear upsample (align-corners linspace) of binary map + round-half-even
// ---------------------------------------------------------------------------
__global__ void upsample_kernel(const float* __restrict__ bin, float* __restrict__ out)
{
    int idx = blockIdx.x * 256 + threadIdx.x;
    if (idx >= 256 * 256) return;
    int Y = idx >> 8, X = idx & 255;
    const float step = 127.0f / 255.0f;   // linspace(0,127,256) delta, fp32
    float ys = (float)Y * step;
    float xs = (float)X * step;
    int y0 = (int)floorf(ys); int y1 = min(y0 + 1, 127);
    int x0 = (int)floorf(xs); int x1 = min(x0 + 1, 127);
    float wy = ys - (float)y0;
    float wx = xs - (float)x0;
    float v00 = bin[y0 * 128 + x0], v01 = bin[y0 * 128 + x1];
    float v10 = bin[y1 * 128 + x0], v11 = bin[y1 * 128 + x1];
    float val = (v00 * (1.f - wx) + v01 * wx) * (1.f - wy)
              + (v10 * (1.f - wx) + v11 * wx) * wy;
    out[idx] = rintf(val);   // round-half-even == jnp.round
}

// ---------------------------------------------------------------------------
// Iterative contour refinement.  num_iter is a DEVICE scalar -> loop on device
// (graph-capture safe, no host readback).  Points are independent.
// ---------------------------------------------------------------------------
__global__ void contour_kernel(const float* __restrict__ cc,
                               const float* __restrict__ field,
                               const int* __restrict__ pnum_iter,
                               float* __restrict__ out, int npts)
{
    int i = blockIdx.x * 256 + threadIdx.x;
    if (i >= npts) return;
    const int W = 256, H = 256;
    float x = cc[2 * i];
    float y = cc[2 * i + 1];
    int n = pnum_iter[0];
    for (int t = 0; t < n; t++) {
        float xc = fminf(fmaxf(x, 0.f), (float)(W - 1));
        float yc = fminf(fmaxf(y, 0.f), (float)(H - 1));
        int x0 = (int)floorf(xc); int x1 = min(x0 + 1, W - 1);
        int y0 = (int)floorf(yc); int y1 = min(y0 + 1, H - 1);
        float wx = xc - (float)x0;
        float wy = yc - (float)y0;
        float ox, oy;
        {
            const float* f = field;  // channel 0 -> x offset
            float v00 = f[y0 * W + x0], v01 = f[y0 * W + x1];
            float v10 = f[y1 * W + x0], v11 = f[y1 * W + x1];
            ox = (v00 * (1.f - wx) + v01 * wx) * (1.f - wy)
               + (v10 * (1.f - wx) + v11 * wx) * wy;
        }
        {
            const float* f = field + H * W;  // channel 1 -> y offset
            float v00 = f[y0 * W + x0], v01 = f[y0 * W + x1];
            float v10 = f[y1 * W + x0], v11 = f[y1 * W + x1];
            oy = (v00 * (1.f - wx) + v01 * wx) * (1.f - wy)
               + (v10 * (1.f - wx) + v11 * wx) * wy;
        }
        x = fminf(fmaxf(x + ox, 0.f), (float)(W - 1));
        y = fminf(fmaxf(y + oy, 0.f), (float)(H - 1));
    }
    out[2 * i]     = x;
    out[2 * i + 1] = y;
}

// ---------------------------------------------------------------------------
// Launch
// ---------------------------------------------------------------------------
extern "C" void kernel_launch(void* const* d_in, const int* in_sizes, int n_in,
                              void* d_out, int out_size)
{
    const float* f1  = (const float*)d_in[0];   // (1,512,256,256)
    const float* f2  = (const float*)d_in[1];   // (1,512,128,128)
    const float* cc  = (const float*)d_in[2];   // (1,600,64,2)
    const float* cw1 = (const float*)d_in[3];
    const float* cb1 = (const float*)d_in[4];
    const float* cw2 = (const float*)d_in[5];
    const float* cb2 = (const float*)d_in[6];
    const float* cw3 = (const float*)d_in[7];
    const float* cb3 = (const float*)d_in[8];
    const float* cw4 = (const float*)d_in[9];
    const float* cb4 = (const float*)d_in[10];
    const float* rw1 = (const float*)d_in[11];
    const float* rb1 = (const float*)d_in[12];
    const float* rw2 = (const float*)d_in[13];
    const float* rb2 = (const float*)d_in[14];
    const float* rw3 = (const float*)d_in[15];
    const float* rb3 = (const float*)d_in[16];
    const float* rw4 = (const float*)d_in[17];
    const float* rb4 = (const float*)d_in[18];
    const int* pnum  = (const int*)d_in[19];

    float* out = (float*)d_out;
    float* out_cls = out;                    // 16384
    float* out_bin = out + 16384;            // 65536
    float* out_ctr = out + 16384 + 65536;    // 76800

    float *bufA, *bufB, *field, *bin;
    cudaGetSymbolAddress((void**)&bufA,  g_bufA);
    cudaGetSymbolAddress((void**)&bufB,  g_bufB);
    cudaGetSymbolAddress((void**)&field, g_field);
    cudaGetSymbolAddress((void**)&bin,   g_bin);

    // ---- classification branch (128x128) ----
    {
        dim3 g1((128 / 64) * 128, 1024 / 64);
        conv3x3_kernel<<<g1, 256>>>(f2,   cw1, cb1, bufA, 512, 1024, 128, 128, 1);
        dim3 g2((128 / 64) * 128, 512 / 64);
        conv3x3_kernel<<<g2, 256>>>(bufA, cw2, cb2, bufB, 1024, 512, 128, 128, 1);
        dim3 g3((128 / 64) * 128, 256 / 64);
        conv3x3_kernel<<<g3, 256>>>(bufB, cw3, cb3, bufA, 512, 256, 128, 128, 1);
        cls_kernel<<<(16384 + 255) / 256, 256>>>(bufA, cw4, cb4, out_cls, bin, 16384);
        upsample_kernel<<<(65536 + 255) / 256, 256>>>(bin, out_bin);
    }

    // ---- refinement branch (256x256) ----
    {
        dim3 g1((256 / 64) * 256, 1024 / 64);
        conv3x3_kernel<<<g1, 256>>>(f1,   rw1, rb1, bufA, 512, 1024, 256, 256, 1);
        dim3 g2((256 / 64) * 256, 512 / 64);
        conv3x3_kernel<<<g2, 256>>>(bufA, rw2, rb2, bufB, 1024, 512, 256, 256, 1);
        dim3 g3((256 / 64) * 256, 256 / 64);
        conv3x3_kernel<<<g3, 256>>>(bufB, rw3, rb3, bufA, 512, 256, 256, 256, 1);
        field_kernel<<<(65536 + 255) / 256, 256>>>(bufA, rw4, rb4, field, 65536);
        contour_kernel<<<(38400 + 255) / 256, 256>>>(cc, field, pnum, out_ctr, 38400);
    }
}

// round 6
// speedup vs baseline: 1.9235x; 1.9235x over previous
#include <cuda_runtime.h>
#include <math.h>
#include <stdint.h>

// ---------------------------------------------------------------------------
// Scratch (device globals -- no runtime allocation allowed)
// ---------------------------------------------------------------------------
__device__ float g_bufA[1024u * 256u * 256u];   // 256 MB
__device__ float g_bufB[512u * 256u * 256u];    // 128 MB
__device__ float g_Wt[1024u * 512u * 9u];       // transformed tf32 weights
__device__ float g_field[2 * 256 * 256];
__device__ float g_bin[128 * 128];

// ---------------------------------------------------------------------------
// tf32 helpers (portable sm_80+ -- NO 'a'-suffix features)
// cvt.rna.tf32.f32 needs a .b32 destination => "=r" constraint.
// ---------------------------------------------------------------------------
__device__ __forceinline__ uint32_t to_tf32(float x) {
    uint32_t r;
    asm("cvt.rna.tf32.f32 %0, %1;" : "=r"(r) : "f"(x));
    return r;
}
__device__ __forceinline__ void mma_tf32(float c[4],
                                         uint32_t a0, uint32_t a1, uint32_t a2, uint32_t a3,
                                         uint32_t b0, uint32_t b1) {
    asm volatile(
        "mma.sync.aligned.m16n8k8.row.col.f32.tf32.tf32.f32 "
        "{%0,%1,%2,%3}, {%4,%5,%6,%7}, {%8,%9}, {%0,%1,%2,%3};"
        : "+f"(c[0]), "+f"(c[1]), "+f"(c[2]), "+f"(c[3])
        : "r"(a0), "r"(a1), "r"(a2), "r"(a3), "r"(b0), "r"(b1));
}

// ---------------------------------------------------------------------------
// Weight transform: w[co][ci][3][3] -> Wt[(ci*9+k)*Cout + co], tf32-rounded
// ---------------------------------------------------------------------------
__global__ void wt_transform(const float* __restrict__ w, float* __restrict__ out,
                             int Cout, int Cin)
{
    int i = blockIdx.x * 256 + threadIdx.x;
    if (i >= Cout * Cin * 9) return;
    int co = i / (Cin * 9);
    int r  = i - co * (Cin * 9);     // ci*9 + k
    out[(size_t)r * Cout + co] = __uint_as_float(to_tf32(w[i]));
}

// ---------------------------------------------------------------------------
// TF32 mma.sync 3x3 SAME conv, NCHW (H=W=256), bias + ReLU.
// CTA 256 thr: tile M=128 Cout x N=128 px (one row segment).
// Warp tile 64x32 (m16n8k8 frags: 4 mfrag x 4 nfrag). K: 8 ci/chunk x 9 taps.
// ---------------------------------------------------------------------------
#define SX_STRIDE 132
#define SX_FLOATS (24 * 132)            // [ky*8+ci][132]
#define SW_FLOATS (72 * 132)            // [ci*9+k][132]
#define CMMA_SMEM ((SX_FLOATS + SW_FLOATS) * 4)   // 50688 B

__global__ __launch_bounds__(256, 2) void conv3x3_mma(
    const float* __restrict__ in, const float* __restrict__ Wt,
    const float* __restrict__ bias, float* __restrict__ out,
    int Cin, int Cout)
{
    extern __shared__ float sm[];
    float* sX = sm;                 // input halo: 3 rows x 8 ci x 130 px
    float* sW = sm + SX_FLOATS;     // weights: 72 rows x 128 co

    const int tileX  = (blockIdx.x & 1) << 7;
    const int y      = blockIdx.x >> 1;
    const int coTile = blockIdx.y << 7;
    const int tid  = threadIdx.x;
    const int lane = tid & 31;
    const int wid  = tid >> 5;
    const int mBase = (wid >> 2) << 6;   // 0 / 64
    const int nBase = (wid & 3) << 5;    // 0..96
    const int qr = lane >> 2;            // groupID
    const int qc = lane & 3;             // threadID-in-group

    float acc[4][4][4] = {};

    for (int ci0 = 0; ci0 < Cin; ci0 += 8) {
        __syncthreads();
        // ---- stage input: 3 rows x 8 ci x 130 cols, zero-padded, tf32-rounded
        for (int i = tid; i < 3120; i += 256) {
            int ky = i / 1040, rem = i - ky * 1040;
            int ci = rem / 130, j = rem - ci * 130;
            int gy = y + ky - 1, gx = tileX - 1 + j;
            float v = 0.f;
            if ((unsigned)gy < 256u && (unsigned)gx < 256u)
                v = in[((((size_t)(ci0 + ci) << 8) + gy) << 8) + gx];
            sX[(ky * 8 + ci) * SX_STRIDE + j] = __uint_as_float(to_tf32(v));
        }
        // ---- stage weights: 72 rows x 128 co (fully coalesced from Wt)
        for (int i = tid; i < 9216; i += 256) {
            int row = i >> 7, co = i & 127;
            sW[row * SX_STRIDE + co] =
                Wt[(size_t)(ci0 * 9 + row) * Cout + coTile + co];
        }
        __syncthreads();

        // ---- 9 tap-GEMMs
#pragma unroll
        for (int ky = 0; ky < 3; ky++) {
#pragma unroll
            for (int kx = 0; kx < 3; kx++) {
                const int t = ky * 3 + kx;
                uint32_t A[4][4];
#pragma unroll
                for (int mf = 0; mf < 4; mf++) {
                    int m = mBase + mf * 16 + qr;
                    const float* w0 = &sW[(qc * 9 + t) * SX_STRIDE + m];
                    const float* w4 = &sW[((qc + 4) * 9 + t) * SX_STRIDE + m];
                    A[mf][0] = __float_as_uint(w0[0]);
                    A[mf][1] = __float_as_uint(w0[8]);
                    A[mf][2] = __float_as_uint(w4[0]);
                    A[mf][3] = __float_as_uint(w4[8]);
                }
#pragma unroll
                for (int nf = 0; nf < 4; nf++) {
                    int col = nBase + nf * 8 + qr + kx;
                    uint32_t b0 = __float_as_uint(sX[(ky * 8 + qc)     * SX_STRIDE + col]);
                    uint32_t b1 = __float_as_uint(sX[(ky * 8 + qc + 4) * SX_STRIDE + col]);
#pragma unroll
                    for (int mf = 0; mf < 4; mf++)
                        mma_tf32(acc[mf][nf], A[mf][0], A[mf][1], A[mf][2], A[mf][3], b0, b1);
                }
            }
        }
    }

    // ---- epilogue: bias + ReLU, NCHW stores (float2 per frag row)
#pragma unroll
    for (int mf = 0; mf < 4; mf++) {
        int co = coTile + mBase + mf * 16 + qr;
        float bv0 = bias[co], bv1 = bias[co + 8];
#pragma unroll
        for (int nf = 0; nf < 4; nf++) {
            int px = tileX + nBase + nf * 8 + 2 * qc;
            float2 v0 = { fmaxf(acc[mf][nf][0] + bv0, 0.f),
                          fmaxf(acc[mf][nf][1] + bv0, 0.f) };
            float2 v1 = { fmaxf(acc[mf][nf][2] + bv1, 0.f),
                          fmaxf(acc[mf][nf][3] + bv1, 0.f) };
            *(float2*)&out[((((size_t)co       << 8) + y) << 8) + px] = v0;
            *(float2*)&out[((((size_t)(co + 8) << 8) + y) << 8) + px] = v1;
        }
    }
}

// ===========================================================================
// fp32 conv (classification branch -- bit-stable thresholding)
// ===========================================================================
#define KC 8
__global__ __launch_bounds__(256) void conv3x3_kernel(
    const float* __restrict__ in, const float* __restrict__ wgt,
    const float* __restrict__ bias, float* __restrict__ out,
    int Cin, int Cout, int H, int W, int doRelu)
{
    __shared__ __align__(16) float sIn[KC][3][68];
    __shared__ __align__(16) float sW2[KC][9][68];

    const int xtiles = W >> 6;
    const int tileX  = (blockIdx.x & (xtiles - 1)) << 6;
    const int y      = blockIdx.x / xtiles;
    const int coTile = blockIdx.y << 6;

    const int tid  = threadIdx.x;
    const int co0  = (tid >> 4) << 2;
    const int px0  = (tid & 15) << 2;
    const int warp = tid >> 5;
    const int lane = tid & 31;

    float acc[4][4];
#pragma unroll
    for (int i = 0; i < 4; i++)
#pragma unroll
        for (int j = 0; j < 4; j++) acc[i][j] = 0.f;

    for (int ci0 = 0; ci0 < Cin; ci0 += KC) {
        __syncthreads();
        for (int r = warp; r < KC * 3; r += 8) {
            int ci = r / 3, ky = r - ci * 3, gy = y + ky - 1;
            bool yok = ((unsigned)gy < (unsigned)H);
            for (int j = lane; j < 66; j += 32) {
                int gx = tileX - 1 + j;
                float v = 0.f;
                if (yok && (unsigned)gx < (unsigned)W)
                    v = in[((ci0 + ci) * H + gy) * W + gx];
                sIn[ci][ky][j] = v;
            }
        }
        for (int idx = tid; idx < 64 * KC * 9; idx += 256) {
            int co = idx / (KC * 9), rem = idx - co * (KC * 9);
            int ci = rem / 9, k = rem - ci * 9;
            sW2[ci][k][co] = wgt[((coTile + co) * Cin + (ci0 + ci)) * 9 + k];
        }
        __syncthreads();
#pragma unroll
        for (int ci = 0; ci < KC; ci++) {
            float4 wr[9];
#pragma unroll
            for (int k = 0; k < 9; k++) wr[k] = *(const float4*)&sW2[ci][k][co0];
#pragma unroll
            for (int ky = 0; ky < 3; ky++) {
                float4 a  = *(const float4*)&sIn[ci][ky][px0];
                float2 b2 = *(const float2*)&sIn[ci][ky][px0 + 4];
                float xin[6] = {a.x, a.y, a.z, a.w, b2.x, b2.y};
#pragma unroll
                for (int kx = 0; kx < 3; kx++) {
                    float4 wv = wr[ky * 3 + kx];
#pragma unroll
                    for (int p = 0; p < 4; p++) {
                        float iv = xin[p + kx];
                        acc[0][p] = fmaf(wv.x, iv, acc[0][p]);
                        acc[1][p] = fmaf(wv.y, iv, acc[1][p]);
                        acc[2][p] = fmaf(wv.z, iv, acc[2][p]);
                        acc[3][p] = fmaf(wv.w, iv, acc[3][p]);
                    }
                }
            }
        }
    }
#pragma unroll
    for (int cph = 0; cph < 4; cph++) {
        int co = coTile + co0 + cph;
        float bv = bias[co];
        float* dst = out + (co * H + y) * W + tileX + px0;
#pragma unroll
        for (int p = 0; p < 4; p++) {
            float v = acc[cph][p] + bv;
            if (doRelu) v = fmaxf(v, 0.f);
            dst[p] = v;
        }
    }
}

// ---------------------------------------------------------------------------
// Heads / transforms
// ---------------------------------------------------------------------------
__global__ void cls_kernel(const float* __restrict__ h, const float* __restrict__ w,
                           const float* __restrict__ b, float* __restrict__ cls,
                           float* __restrict__ bin, int HW)
{
    int p = blockIdx.x * 256 + threadIdx.x;
    if (p >= HW) return;
    float s = b[0];
#pragma unroll 8
    for (int c = 0; c < 256; c++) s = fmaf(w[c], h[c * HW + p], s);
    float sig = 1.f / (1.f + expf(-s));
    cls[p] = sig;
    bin[p] = (sig >= 0.5f) ? 1.f : 0.f;
}

__global__ void field_kernel(const float* __restrict__ r, const float* __restrict__ w,
                             const float* __restrict__ b, float* __restrict__ field,
                             int HW)
{
    int p = blockIdx.x * 256 + threadIdx.x;
    if (p >= HW) return;
    float s0 = b[0], s1 = b[1];
#pragma unroll 8
    for (int c = 0; c < 256; c++) {
        float v = r[(size_t)c * HW + p];
        s0 = fmaf(w[c], v, s0);
        s1 = fmaf(w[256 + c], v, s1);
    }
    field[p] = s0;
    field[HW + p] = s1;
}

__global__ void upsample_kernel(const float* __restrict__ bin, float* __restrict__ out)
{
    int idx = blockIdx.x * 256 + threadIdx.x;
    if (idx >= 256 * 256) return;
    int Y = idx >> 8, X = idx & 255;
    const float step = 127.0f / 255.0f;
    float ys = (float)Y * step, xs = (float)X * step;
    int y0 = (int)floorf(ys); int y1 = min(y0 + 1, 127);
    int x0 = (int)floorf(xs); int x1 = min(x0 + 1, 127);
    float wy = ys - (float)y0, wx = xs - (float)x0;
    float v00 = bin[y0 * 128 + x0], v01 = bin[y0 * 128 + x1];
    float v10 = bin[y1 * 128 + x0], v11 = bin[y1 * 128 + x1];
    out[idx] = rintf((v00 * (1.f - wx) + v01 * wx) * (1.f - wy)
                   + (v10 * (1.f - wx) + v11 * wx) * wy);
}

__global__ void contour_kernel(const float* __restrict__ cc,
                               const float* __restrict__ field,
                               const int* __restrict__ pnum_iter,
                               float* __restrict__ out, int npts)
{
    int i = blockIdx.x * 256 + threadIdx.x;
    if (i >= npts) return;
    const int W = 256, H = 256;
    float x = cc[2 * i], y = cc[2 * i + 1];
    int n = pnum_iter[0];
    for (int t = 0; t < n; t++) {
        float xc = fminf(fmaxf(x, 0.f), 255.f);
        float yc = fminf(fmaxf(y, 0.f), 255.f);
        int x0 = (int)floorf(xc); int x1 = min(x0 + 1, W - 1);
        int y0 = (int)floorf(yc); int y1 = min(y0 + 1, H - 1);
        float wx = xc - (float)x0, wy = yc - (float)y0;
        float ox, oy;
        {
            const float* f = field;
            float v00 = f[y0 * W + x0], v01 = f[y0 * W + x1];
            float v10 = f[y1 * W + x0], v11 = f[y1 * W + x1];
            ox = (v00 * (1.f - wx) + v01 * wx) * (1.f - wy)
               + (v10 * (1.f - wx) + v11 * wx) * wy;
        }
        {
            const float* f = field + H * W;
            float v00 = f[y0 * W + x0], v01 = f[y0 * W + x1];
            float v10 = f[y1 * W + x0], v11 = f[y1 * W + x1];
            oy = (v00 * (1.f - wx) + v01 * wx) * (1.f - wy)
               + (v10 * (1.f - wx) + v11 * wx) * wy;
        }
        x = fminf(fmaxf(x + ox, 0.f), 255.f);
        y = fminf(fmaxf(y + oy, 0.f), 255.f);
    }
    out[2 * i] = x;
    out[2 * i + 1] = y;
}

// ---------------------------------------------------------------------------
extern "C" void kernel_launch(void* const* d_in, const int* in_sizes, int n_in,
                              void* d_out, int out_size)
{
    const float* f1  = (const float*)d_in[0];
    const float* f2  = (const float*)d_in[1];
    const float* cc  = (const float*)d_in[2];
    const float* cw1 = (const float*)d_in[3];
    const float* cb1 = (const float*)d_in[4];
    const float* cw2 = (const float*)d_in[5];
    const float* cb2 = (const float*)d_in[6];
    const float* cw3 = (const float*)d_in[7];
    const float* cb3 = (const float*)d_in[8];
    const float* cw4 = (const float*)d_in[9];
    const float* cb4 = (const float*)d_in[10];
    const float* rw1 = (const float*)d_in[11];
    const float* rb1 = (const float*)d_in[12];
    const float* rw2 = (const float*)d_in[13];
    const float* rb2 = (const float*)d_in[14];
    const float* rw3 = (const float*)d_in[15];
    const float* rb3 = (const float*)d_in[16];
    const float* rw4 = (const float*)d_in[17];
    const float* rb4 = (const float*)d_in[18];
    const int*   pnum = (const int*)d_in[19];

    float* out = (float*)d_out;
    float* out_cls = out;
    float* out_bin = out + 16384;
    float* out_ctr = out + 16384 + 65536;

    float *bufA, *bufB, *Wt, *field, *bin;
    cudaGetSymbolAddress((void**)&bufA, g_bufA);
    cudaGetSymbolAddress((void**)&bufB, g_bufB);
    cudaGetSymbolAddress((void**)&Wt,   g_Wt);
    cudaGetSymbolAddress((void**)&field, g_field);
    cudaGetSymbolAddress((void**)&bin,  g_bin);

    cudaFuncSetAttribute(conv3x3_mma, cudaFuncAttributeMaxDynamicSharedMemorySize, CMMA_SMEM);

    // ---- classification branch (fp32, bit-stable) ----
    conv3x3_kernel<<<dim3(2 * 128, 16), 256>>>(f2,   cw1, cb1, bufA, 512, 1024, 128, 128, 1);
    conv3x3_kernel<<<dim3(2 * 128,  8), 256>>>(bufA, cw2, cb2, bufB, 1024, 512, 128, 128, 1);
    conv3x3_kernel<<<dim3(2 * 128,  4), 256>>>(bufB, cw3, cb3, bufA, 512, 256, 128, 128, 1);
    cls_kernel<<<64, 256>>>(bufA, cw4, cb4, out_cls, bin, 16384);
    upsample_kernel<<<256, 256>>>(bin, out_bin);

    // ---- refinement branch (tf32 mma.sync tensor cores) ----
    wt_transform<<<(1024 * 512 * 9 + 255) / 256, 256>>>(rw1, Wt, 1024, 512);
    conv3x3_mma<<<dim3(512, 8), 256, CMMA_SMEM>>>(f1,   Wt, rb1, bufA, 512, 1024);
    wt_transform<<<(512 * 1024 * 9 + 255) / 256, 256>>>(rw2, Wt, 512, 1024);
    conv3x3_mma<<<dim3(512, 4), 256, CMMA_SMEM>>>(bufA, Wt, rb2, bufB, 1024, 512);
    wt_transform<<<(256 * 512 * 9 + 255) / 256, 256>>>(rw3, Wt, 256, 512);
    conv3x3_mma<<<dim3(512, 2), 256, CMMA_SMEM>>>(bufB, Wt, rb3, bufA, 512, 256);
    field_kernel<<<256, 256>>>(bufA, rw4, rb4, field, 65536);
    contour_kernel<<<(38400 + 255) / 256, 256>>>(cc, field, pnum, out_ctr, 38400);
}

// round 10
// speedup vs baseline: 2.9294x; 1.5230x over previous
#include <cuda_runtime.h>
#include <math.h>
#include <stdint.h>

// ---------------------------------------------------------------------------
// Scratch (device globals -- no runtime allocation allowed)
// ---------------------------------------------------------------------------
__device__ float g_bufA[1024u * 256u * 256u];   // 256 MB
__device__ float g_bufB[512u * 256u * 256u];    // 128 MB
__device__ float g_Wt1[1024u * 512u * 9u];
__device__ float g_Wt2[512u * 1024u * 9u];
__device__ float g_Wt3[256u * 512u * 9u];
__device__ float g_field[2 * 256 * 256];
__device__ float g_bin[128 * 128];

// ---------------------------------------------------------------------------
// tf32 helpers (portable sm_80+ -- NO 'a'-suffix features)
// ---------------------------------------------------------------------------
__device__ __forceinline__ uint32_t to_tf32(float x) {
    uint32_t r;
    asm("cvt.rna.tf32.f32 %0, %1;" : "=r"(r) : "f"(x));
    return r;
}
__device__ __forceinline__ void mma_tf32(float c[4],
                                         uint32_t a0, uint32_t a1, uint32_t a2, uint32_t a3,
                                         uint32_t b0, uint32_t b1) {
    asm volatile(
        "mma.sync.aligned.m16n8k8.row.col.f32.tf32.tf32.f32 "
        "{%0,%1,%2,%3}, {%4,%5,%6,%7}, {%8,%9}, {%0,%1,%2,%3};"
        : "+f"(c[0]), "+f"(c[1]), "+f"(c[2]), "+f"(c[3])
        : "r"(a0), "r"(a1), "r"(a2), "r"(a3), "r"(b0), "r"(b1));
}
__device__ __forceinline__ uint32_t smem_u32(const void* p) {
    uint32_t a;
    asm("{ .reg .u64 t; cvta.to.shared.u64 t, %1; cvt.u32.u64 %0, t; }" : "=r"(a) : "l"(p));
    return a;
}
__device__ __forceinline__ void cpa16(uint32_t dst, const void* src) {
    asm volatile("cp.async.cg.shared.global [%0], [%1], 16;" :: "r"(dst), "l"(src) : "memory");
}
#define CP_COMMIT() asm volatile("cp.async.commit_group;" ::: "memory")
#define CP_WAIT1()  asm volatile("cp.async.wait_group 1;" ::: "memory")
#define CP_WAIT0()  asm volatile("cp.async.wait_group 0;" ::: "memory")

// ---------------------------------------------------------------------------
// Weight transform: w[co][ci][3][3] -> Wt[(ci*9+k)*Cout + co], tf32-rounded
// ---------------------------------------------------------------------------
__global__ void wt_transform(const float* __restrict__ w, float* __restrict__ out,
                             int Cout, int Cin)
{
    int i = blockIdx.x * 256 + threadIdx.x;
    if (i >= Cout * Cin * 9) return;
    int co = i / (Cin * 9);
    int r  = i - co * (Cin * 9);     // ci*9 + k
    out[(size_t)r * Cout + co] = __uint_as_float(to_tf32(w[i]));
}

// ---------------------------------------------------------------------------
// TF32 mma.sync 3x3 SAME conv v2 -- cp.async double-buffered, full-row tiles.
// CTA 256 thr: tile M=128 Cout x N=256 px (one full image row).
// 8 warps, warp tile 64x64 (4 mf x 8 nf m16n8k8 frags). K: 8 ci/chunk x 9 taps.
// x-halo is always out-of-image (full-row tile) => pre-zeroed, pure cp.async.
// ---------------------------------------------------------------------------
#define SXS 264                      // input row stride (floats); 258 used
#define SWS 136                      // weight row stride (floats); 128 used
#define STAGE_X (24 * SXS)           // 6336 floats
#define STAGE_W (72 * SWS)           // 9792 floats
#define STAGE_F (STAGE_X + STAGE_W)  // 16128 floats
#define CMMA2_SMEM (2 * STAGE_F * 4) // 129024 B

__device__ __forceinline__ void stage_chunk(
    uint32_t sx_b, uint32_t sw_b, const float* __restrict__ in,
    const float* __restrict__ Wt, int y, int coTile, int c, int Cout, int tid)
{
    // input: 24 rows (3 ky x 8 ci) x 64 x 16B  -> columns j=4..259 (x=0..255)
#pragma unroll
    for (int it = 0; it < 6; it++) {
        int i = tid + (it << 8);
        int row = i >> 6, seg = i & 63;
        int ky = row >> 3, ci = row & 7;
        int gy = y - 1 + ky;
        if ((unsigned)gy < 256u)
            cpa16(sx_b + (uint32_t)(row * SXS + 4 + seg * 4) * 4,
                  in + ((((size_t)((c << 3) + ci)) << 8) + gy << 8) + seg * 4);
    }
    // weights: 72 rows x 32 x 16B
#pragma unroll
    for (int it = 0; it < 9; it++) {
        int i = tid + (it << 8);
        int row = i >> 5, seg = i & 31;
        cpa16(sw_b + (uint32_t)(row * SWS + seg * 4) * 4,
              Wt + (size_t)(c * 72 + row) * Cout + coTile + seg * 4);
    }
}

__global__ __launch_bounds__(256, 1) void conv3x3_mma2(
    const float* __restrict__ in, const float* __restrict__ Wt,
    const float* __restrict__ bias, float* __restrict__ out,
    int Cin, int Cout)
{
    extern __shared__ float sm[];
    const uint32_t base_b = smem_u32(sm);

    const int y      = blockIdx.x;
    const int coTile = blockIdx.y << 7;
    const int tid  = threadIdx.x;
    const int lane = tid & 31;
    const int wid  = tid >> 5;
    const int mBase = (wid >> 2) << 6;   // 0 / 64
    const int nBase = (wid & 3) << 6;    // 0,64,128,192
    const int qr = lane >> 2;
    const int qc = lane & 3;

    // pre-zero both input stages (covers x-halo cols and OOB ky rows)
    for (int i = tid; i < 2 * STAGE_X / 4; i += 256) {
        uint32_t a = base_b + ((i >= STAGE_X / 4)
                     ? (uint32_t)(STAGE_F + (i - STAGE_X / 4) * 4) * 4
                     : (uint32_t)(i * 4) * 4);
        asm volatile("st.shared.v4.u32 [%0], {%1,%1,%1,%1};" :: "r"(a), "r"(0u));
    }
    __syncthreads();

    const int nch = Cin >> 3;
    stage_chunk(base_b, base_b + STAGE_X * 4, in, Wt, y, coTile, 0, Cout, tid);
    CP_COMMIT();

    float acc[4][8][4] = {};

    for (int c = 0; c < nch; c++) {
        const int s = c & 1;
        if (c + 1 < nch) {
            uint32_t sb = base_b + (uint32_t)((s ^ 1) * STAGE_F) * 4;
            stage_chunk(sb, sb + STAGE_X * 4, in, Wt, y, coTile, c + 1, Cout, tid);
            CP_COMMIT();
            CP_WAIT1();
        } else {
            CP_WAIT0();
        }
        __syncthreads();

        const float* sX = sm + s * STAGE_F;
        const float* sW = sX + STAGE_X;

#pragma unroll
        for (int ky = 0; ky < 3; ky++) {
#pragma unroll
            for (int kx = 0; kx < 3; kx++) {
                const int t = ky * 3 + kx;
                uint32_t A[4][4];
#pragma unroll
                for (int mf = 0; mf < 4; mf++) {
                    int m = mBase + mf * 16 + qr;
                    const float* w0 = &sW[(qc * 9 + t) * SWS + m];
                    const float* w4 = &sW[((qc + 4) * 9 + t) * SWS + m];
                    A[mf][0] = __float_as_uint(w0[0]);
                    A[mf][1] = __float_as_uint(w0[8]);
                    A[mf][2] = __float_as_uint(w4[0]);
                    A[mf][3] = __float_as_uint(w4[8]);
                }
#pragma unroll
                for (int nf = 0; nf < 8; nf++) {
                    int col = nBase + nf * 8 + qr + kx + 3;   // x = col-4, tap x+kx-1
                    uint32_t b0 = __float_as_uint(sX[(ky * 8 + qc)     * SXS + col]);
                    uint32_t b1 = __float_as_uint(sX[(ky * 8 + qc + 4) * SXS + col]);
#pragma unroll
                    for (int mf = 0; mf < 4; mf++)
                        mma_tf32(acc[mf][nf], A[mf][0], A[mf][1], A[mf][2], A[mf][3], b0, b1);
                }
            }
        }
        __syncthreads();
    }

    // epilogue: bias + ReLU, NCHW float2 stores
#pragma unroll
    for (int mf = 0; mf < 4; mf++) {
        int co = coTile + mBase + mf * 16 + qr;
        float bv0 = bias[co], bv1 = bias[co + 8];
#pragma unroll
        for (int nf = 0; nf < 8; nf++) {
            int px = nBase + nf * 8 + 2 * qc;
            float2 v0 = { fmaxf(acc[mf][nf][0] + bv0, 0.f),
                          fmaxf(acc[mf][nf][1] + bv0, 0.f) };
            float2 v1 = { fmaxf(acc[mf][nf][2] + bv1, 0.f),
                          fmaxf(acc[mf][nf][3] + bv1, 0.f) };
            *(float2*)&out[((((size_t)co       << 8) + y) << 8) + px] = v0;
            *(float2*)&out[((((size_t)(co + 8) << 8) + y) << 8) + px] = v1;
        }
    }
}

// ===========================================================================
// fp32 conv (classification branch -- bit-stable thresholding)
// ===========================================================================
#define KC 8
__global__ __launch_bounds__(256) void conv3x3_kernel(
    const float* __restrict__ in, const float* __restrict__ wgt,
    const float* __restrict__ bias, float* __restrict__ out,
    int Cin, int Cout, int H, int W, int doRelu)
{
    __shared__ __align__(16) float sIn[KC][3][68];
    __shared__ __align__(16) float sW2[KC][9][68];

    const int xtiles = W >> 6;
    const int tileX  = (blockIdx.x & (xtiles - 1)) << 6;
    const int y      = blockIdx.x / xtiles;
    const int coTile = blockIdx.y << 6;

    const int tid  = threadIdx.x;
    const int co0  = (tid >> 4) << 2;
    const int px0  = (tid & 15) << 2;
    const int warp = tid >> 5;
    const int lane = tid & 31;

    float acc[4][4];
#pragma unroll
    for (int i = 0; i < 4; i++)
#pragma unroll
        for (int j = 0; j < 4; j++) acc[i][j] = 0.f;

    for (int ci0 = 0; ci0 < Cin; ci0 += KC) {
        __syncthreads();
        for (int r = warp; r < KC * 3; r += 8) {
            int ci = r / 3, ky = r - ci * 3, gy = y + ky - 1;
            bool yok = ((unsigned)gy < (unsigned)H);
            for (int j = lane; j < 66; j += 32) {
                int gx = tileX - 1 + j;
                float v = 0.f;
                if (yok && (unsigned)gx < (unsigned)W)
                    v = in[((ci0 + ci) * H + gy) * W + gx];
                sIn[ci][ky][j] = v;
            }
        }
        for (int idx = tid; idx < 64 * KC * 9; idx += 256) {
            int co = idx / (KC * 9), rem = idx - co * (KC * 9);
            int ci = rem / 9, k = rem - ci * 9;
            sW2[ci][k][co] = wgt[((coTile + co) * Cin + (ci0 + ci)) * 9 + k];
        }
        __syncthreads();
#pragma unroll
        for (int ci = 0; ci < KC; ci++) {
            float4 wr[9];
#pragma unroll
            for (int k = 0; k < 9; k++) wr[k] = *(const float4*)&sW2[ci][k][co0];
#pragma unroll
            for (int ky = 0; ky < 3; ky++) {
                float4 a  = *(const float4*)&sIn[ci][ky][px0];
                float2 b2 = *(const float2*)&sIn[ci][ky][px0 + 4];
                float xin[6] = {a.x, a.y, a.z, a.w, b2.x, b2.y};
#pragma unroll
                for (int kx = 0; kx < 3; kx++) {
                    float4 wv = wr[ky * 3 + kx];
#pragma unroll
                    for (int p = 0; p < 4; p++) {
                        float iv = xin[p + kx];
                        acc[0][p] = fmaf(wv.x, iv, acc[0][p]);
                        acc[1][p] = fmaf(wv.y, iv, acc[1][p]);
                        acc[2][p] = fmaf(wv.z, iv, acc[2][p]);
                        acc[3][p] = fmaf(wv.w, iv, acc[3][p]);
                    }
                }
            }
        }
    }
#pragma unroll
    for (int cph = 0; cph < 4; cph++) {
        int co = coTile + co0 + cph;
        float bv = bias[co];
        float* dst = out + (co * H + y) * W + tileX + px0;
#pragma unroll
        for (int p = 0; p < 4; p++) {
            float v = acc[cph][p] + bv;
            if (doRelu) v = fmaxf(v, 0.f);
            dst[p] = v;
        }
    }
}

// ---------------------------------------------------------------------------
// Heads / transforms
// ---------------------------------------------------------------------------
__global__ void cls_kernel(const float* __restrict__ h, const float* __restrict__ w,
                           const float* __restrict__ b, float* __restrict__ cls,
                           float* __restrict__ bin, int HW)
{
    int p = blockIdx.x * 256 + threadIdx.x;
    if (p >= HW) return;
    float s = b[0];
#pragma unroll 8
    for (int c = 0; c < 256; c++) s = fmaf(w[c], h[c * HW + p], s);
    float sig = 1.f / (1.f + expf(-s));
    cls[p] = sig;
    bin[p] = (sig >= 0.5f) ? 1.f : 0.f;
}

__global__ void field_kernel(const float* __restrict__ r, const float* __restrict__ w,
                             const float* __restrict__ b, float* __restrict__ field,
                             int HW)
{
    int p = blockIdx.x * 256 + threadIdx.x;
    if (p >= HW) return;
    float s0 = b[0], s1 = b[1];
#pragma unroll 8
    for (int c = 0; c < 256; c++) {
        float v = r[(size_t)c * HW + p];
        s0 = fmaf(w[c], v, s0);
        s1 = fmaf(w[256 + c], v, s1);
    }
    field[p] = s0;
    field[HW + p] = s1;
}

__global__ void upsample_kernel(const float* __restrict__ bin, float* __restrict__ out)
{
    int idx = blockIdx.x * 256 + threadIdx.x;
    if (idx >= 256 * 256) return;
    int Y = idx >> 8, X = idx & 255;
    const float step = 127.0f / 255.0f;
    float ys = (float)Y * step, xs = (float)X * step;
    int y0 = (int)floorf(ys); int y1 = min(y0 + 1, 127);
    int x0 = (int)floorf(xs); int x1 = min(x0 + 1, 127);
    float wy = ys - (float)y0, wx = xs - (float)x0;
    float v00 = bin[y0 * 128 + x0], v01 = bin[y0 * 128 + x1];
    float v10 = bin[y1 * 128 + x0], v11 = bin[y1 * 128 + x1];
    out[idx] = rintf((v00 * (1.f - wx) + v01 * wx) * (1.f - wy)
                   + (v10 * (1.f - wx) + v11 * wx) * wy);
}

__global__ void contour_kernel(const float* __restrict__ cc,
                               const float* __restrict__ field,
                               const int* __restrict__ pnum_iter,
                               float* __restrict__ out, int npts)
{
    int i = blockIdx.x * 256 + threadIdx.x;
    if (i >= npts) return;
    const int W = 256, H = 256;
    float x = cc[2 * i], y = cc[2 * i + 1];
    int n = pnum_iter[0];
    for (int t = 0; t < n; t++) {
        float xc = fminf(fmaxf(x, 0.f), 255.f);
        float yc = fminf(fmaxf(y, 0.f), 255.f);
        int x0 = (int)floorf(xc); int x1 = min(x0 + 1, W - 1);
        int y0 = (int)floorf(yc); int y1 = min(y0 + 1, H - 1);
        float wx = xc - (float)x0, wy = yc - (float)y0;
        float ox, oy;
        {
            const float* f = field;
            float v00 = f[y0 * W + x0], v01 = f[y0 * W + x1];
            float v10 = f[y1 * W + x0], v11 = f[y1 * W + x1];
            ox = (v00 * (1.f - wx) + v01 * wx) * (1.f - wy)
               + (v10 * (1.f - wx) + v11 * wx) * wy;
        }
        {
            const float* f = field + H * W;
            float v00 = f[y0 * W + x0], v01 = f[y0 * W + x1];
            float v10 = f[y1 * W + x0], v11 = f[y1 * W + x1];
            oy = (v00 * (1.f - wx) + v01 * wx) * (1.f - wy)
               + (v10 * (1.f - wx) + v11 * wx) * wy;
        }
        x = fminf(fmaxf(x + ox, 0.f), 255.f);
        y = fminf(fmaxf(y + oy, 0.f), 255.f);
    }
    out[2 * i] = x;
    out[2 * i + 1] = y;
}

// ---------------------------------------------------------------------------
extern "C" void kernel_launch(void* const* d_in, const int* in_sizes, int n_in,
                              void* d_out, int out_size)
{
    const float* f1  = (const float*)d_in[0];
    const float* f2  = (const float*)d_in[1];
    const float* cc  = (const float*)d_in[2];
    const float* cw1 = (const float*)d_in[3];
    const float* cb1 = (const float*)d_in[4];
    const float* cw2 = (const float*)d_in[5];
    const float* cb2 = (const float*)d_in[6];
    const float* cw3 = (const float*)d_in[7];
    const float* cb3 = (const float*)d_in[8];
    const float* cw4 = (const float*)d_in[9];
    const float* cb4 = (const float*)d_in[10];
    const float* rw1 = (const float*)d_in[11];
    const float* rb1 = (const float*)d_in[12];
    const float* rw2 = (const float*)d_in[13];
    const float* rb2 = (const float*)d_in[14];
    const float* rw3 = (const float*)d_in[15];
    const float* rb3 = (const float*)d_in[16];
    const float* rw4 = (const float*)d_in[17];
    const float* rb4 = (const float*)d_in[18];
    const int*   pnum = (const int*)d_in[19];

    float* out = (float*)d_out;
    float* out_cls = out;
    float* out_bin = out + 16384;
    float* out_ctr = out + 16384 + 65536;

    float *bufA, *bufB, *Wt1, *Wt2, *Wt3, *field, *bin;
    cudaGetSymbolAddress((void**)&bufA, g_bufA);
    cudaGetSymbolAddress((void**)&bufB, g_bufB);
    cudaGetSymbolAddress((void**)&Wt1,  g_Wt1);
    cudaGetSymbolAddress((void**)&Wt2,  g_Wt2);
    cudaGetSymbolAddress((void**)&Wt3,  g_Wt3);
    cudaGetSymbolAddress((void**)&field, g_field);
    cudaGetSymbolAddress((void**)&bin,  g_bin);

    cudaFuncSetAttribute(conv3x3_mma2, cudaFuncAttributeMaxDynamicSharedMemorySize, CMMA2_SMEM);

    // weight transforms up front (independent of conv outputs)
    wt_transform<<<(1024 * 512 * 9 + 255) / 256, 256>>>(rw1, Wt1, 1024, 512);
    wt_transform<<<(512 * 1024 * 9 + 255) / 256, 256>>>(rw2, Wt2, 512, 1024);
    wt_transform<<<(256 * 512 * 9 + 255) / 256, 256>>>(rw3, Wt3, 256, 512);

    // ---- classification branch (fp32, bit-stable) ----
    conv3x3_kernel<<<dim3(2 * 128, 16), 256>>>(f2,   cw1, cb1, bufA, 512, 1024, 128, 128, 1);
    conv3x3_kernel<<<dim3(2 * 128,  8), 256>>>(bufA, cw2, cb2, bufB, 1024, 512, 128, 128, 1);
    conv3x3_kernel<<<dim3(2 * 128,  4), 256>>>(bufB, cw3, cb3, bufA, 512, 256, 128, 128, 1);
    cls_kernel<<<64, 256>>>(bufA, cw4, cb4, out_cls, bin, 16384);
    upsample_kernel<<<256, 256>>>(bin, out_bin);

    // ---- refinement branch (tf32 mma.sync, pipelined) ----
    conv3x3_mma2<<<dim3(256, 8), 256, CMMA2_SMEM>>>(f1,   Wt1, rb1, bufA, 512, 1024);
    conv3x3_mma2<<<dim3(256, 4), 256, CMMA2_SMEM>>>(bufA, Wt2, rb2, bufB, 1024, 512);
    conv3x3_mma2<<<dim3(256, 2), 256, CMMA2_SMEM>>>(bufB, Wt3, rb3, bufA, 512, 256);
    field_kernel<<<256, 256>>>(bufA, rw4, rb4, field, 65536);
    contour_kernel<<<(38400 + 255) / 256, 256>>>(cc, field, pnum, out_ctr, 38400);
}

// round 11
// speedup vs baseline: 4.2149x; 1.4388x over previous
#include <cuda_runtime.h>
#include <math.h>
#include <stdint.h>

// ---------------------------------------------------------------------------
// Scratch (device globals -- no runtime allocation allowed)
// ---------------------------------------------------------------------------
__device__ float g_bufA[1024u * 256u * 256u];   // 256 MB (also cls hi/lo scratch)
__device__ float g_bufB[512u * 256u * 256u];    // 128 MB
__device__ float g_Wt1[1024u * 512u * 9u];
__device__ float g_Wt2[512u * 1024u * 9u];
__device__ float g_Wt3[256u * 512u * 9u];
__device__ float g_CW1h[1024u * 512u * 9u];
__device__ float g_CW1l[1024u * 512u * 9u];
__device__ float g_CW2h[512u * 1024u * 9u];
__device__ float g_CW2l[512u * 1024u * 9u];
__device__ float g_CW3h[256u * 512u * 9u];
__device__ float g_CW3l[256u * 512u * 9u];
__device__ float g_field[2 * 256 * 256];
__device__ float g_bin[128 * 128];

// ---------------------------------------------------------------------------
// tf32 helpers (portable sm_80+ -- NO 'a'-suffix features)
// ---------------------------------------------------------------------------
__device__ __forceinline__ uint32_t to_tf32(float x) {
    uint32_t r;
    asm("cvt.rna.tf32.f32 %0, %1;" : "=r"(r) : "f"(x));
    return r;
}
__device__ __forceinline__ void mma_tf32(float c[4],
                                         uint32_t a0, uint32_t a1, uint32_t a2, uint32_t a3,
                                         uint32_t b0, uint32_t b1) {
    asm volatile(
        "mma.sync.aligned.m16n8k8.row.col.f32.tf32.tf32.f32 "
        "{%0,%1,%2,%3}, {%4,%5,%6,%7}, {%8,%9}, {%0,%1,%2,%3};"
        : "+f"(c[0]), "+f"(c[1]), "+f"(c[2]), "+f"(c[3])
        : "r"(a0), "r"(a1), "r"(a2), "r"(a3), "r"(b0), "r"(b1));
}
__device__ __forceinline__ uint32_t smem_u32(const void* p) {
    uint32_t a;
    asm("{ .reg .u64 t; cvta.to.shared.u64 t, %1; cvt.u32.u64 %0, t; }" : "=r"(a) : "l"(p));
    return a;
}
__device__ __forceinline__ void cpa16(uint32_t dst, const void* src) {
    asm volatile("cp.async.cg.shared.global [%0], [%1], 16;" :: "r"(dst), "l"(src) : "memory");
}
#define CP_COMMIT() asm volatile("cp.async.commit_group;" ::: "memory")
#define CP_WAIT1()  asm volatile("cp.async.wait_group 1;" ::: "memory")
#define CP_WAIT0()  asm volatile("cp.async.wait_group 0;" ::: "memory")

// ---------------------------------------------------------------------------
// Weight transforms
// ---------------------------------------------------------------------------
__global__ void wt_transform(const float* __restrict__ w, float* __restrict__ out,
                             int Cout, int Cin)
{
    int i = blockIdx.x * 256 + threadIdx.x;
    if (i >= Cout * Cin * 9) return;
    int co = i / (Cin * 9);
    int r  = i - co * (Cin * 9);
    out[(size_t)r * Cout + co] = __uint_as_float(to_tf32(w[i]));
}

__global__ void wt_transform_split(const float* __restrict__ w,
                                   float* __restrict__ oh, float* __restrict__ ol,
                                   int Cout, int Cin)
{
    int i = blockIdx.x * 256 + threadIdx.x;
    if (i >= Cout * Cin * 9) return;
    int co = i / (Cin * 9);
    int r  = i - co * (Cin * 9);
    float v = w[i];
    uint32_t h = to_tf32(v);
    uint32_t l = to_tf32(v - __uint_as_float(h));
    oh[(size_t)r * Cout + co] = __uint_as_float(h);
    ol[(size_t)r * Cout + co] = __uint_as_float(l);
}

// split f2 into hi/lo planes (same NCHW layout)
__global__ void split_input(const float* __restrict__ in,
                            float* __restrict__ oh, float* __restrict__ ol, int n)
{
    int i = blockIdx.x * 256 + threadIdx.x;
    if (i >= n) return;
    float v = in[i];
    uint32_t h = to_tf32(v);
    oh[i] = __uint_as_float(h);
    ol[i] = __uint_as_float(to_tf32(v - __uint_as_float(h)));
}

// ---------------------------------------------------------------------------
// TF32 mma.sync 3x3 SAME conv v2 (refinement, 256x256, single tf32)
// ---------------------------------------------------------------------------
#define SXS 264
#define SWS 136
#define STAGE_X (24 * SXS)
#define STAGE_W (72 * SWS)
#define STAGE_F (STAGE_X + STAGE_W)
#define CMMA2_SMEM (2 * STAGE_F * 4)

__device__ __forceinline__ void stage_chunk(
    uint32_t sx_b, uint32_t sw_b, const float* __restrict__ in,
    const float* __restrict__ Wt, int y, int coTile, int c, int Cout, int tid)
{
#pragma unroll
    for (int it = 0; it < 6; it++) {
        int i = tid + (it << 8);
        int row = i >> 6, seg = i & 63;
        int ky = row >> 3, ci = row & 7;
        int gy = y - 1 + ky;
        if ((unsigned)gy < 256u)
            cpa16(sx_b + (uint32_t)(row * SXS + 4 + seg * 4) * 4,
                  in + ((((size_t)((c << 3) + ci)) << 8) + gy << 8) + seg * 4);
    }
#pragma unroll
    for (int it = 0; it < 9; it++) {
        int i = tid + (it << 8);
        int row = i >> 5, seg = i & 31;
        cpa16(sw_b + (uint32_t)(row * SWS + seg * 4) * 4,
              Wt + (size_t)(c * 72 + row) * Cout + coTile + seg * 4);
    }
}

__global__ __launch_bounds__(256, 1) void conv3x3_mma2(
    const float* __restrict__ in, const float* __restrict__ Wt,
    const float* __restrict__ bias, float* __restrict__ out,
    int Cin, int Cout)
{
    extern __shared__ float sm[];
    const uint32_t base_b = smem_u32(sm);

    const int y      = blockIdx.x;
    const int coTile = blockIdx.y << 7;
    const int tid  = threadIdx.x;
    const int lane = tid & 31;
    const int wid  = tid >> 5;
    const int mBase = (wid >> 2) << 6;
    const int nBase = (wid & 3) << 6;
    const int qr = lane >> 2;
    const int qc = lane & 3;

    for (int i = tid; i < 2 * STAGE_X / 4; i += 256) {
        uint32_t a = base_b + ((i >= STAGE_X / 4)
                     ? (uint32_t)(STAGE_F + (i - STAGE_X / 4) * 4) * 4
                     : (uint32_t)(i * 4) * 4);
        asm volatile("st.shared.v4.u32 [%0], {%1,%1,%1,%1};" :: "r"(a), "r"(0u));
    }
    __syncthreads();

    const int nch = Cin >> 3;
    stage_chunk(base_b, base_b + STAGE_X * 4, in, Wt, y, coTile, 0, Cout, tid);
    CP_COMMIT();

    float acc[4][8][4] = {};

    for (int c = 0; c < nch; c++) {
        const int s = c & 1;
        if (c + 1 < nch) {
            uint32_t sb = base_b + (uint32_t)((s ^ 1) * STAGE_F) * 4;
            stage_chunk(sb, sb + STAGE_X * 4, in, Wt, y, coTile, c + 1, Cout, tid);
            CP_COMMIT();
            CP_WAIT1();
        } else {
            CP_WAIT0();
        }
        __syncthreads();

        const float* sX = sm + s * STAGE_F;
        const float* sW = sX + STAGE_X;

#pragma unroll
        for (int ky = 0; ky < 3; ky++) {
#pragma unroll
            for (int kx = 0; kx < 3; kx++) {
                const int t = ky * 3 + kx;
                uint32_t A[4][4];
#pragma unroll
                for (int mf = 0; mf < 4; mf++) {
                    int m = mBase + mf * 16 + qr;
                    const float* w0 = &sW[(qc * 9 + t) * SWS + m];
                    const float* w4 = &sW[((qc + 4) * 9 + t) * SWS + m];
                    A[mf][0] = __float_as_uint(w0[0]);
                    A[mf][1] = __float_as_uint(w0[8]);
                    A[mf][2] = __float_as_uint(w4[0]);
                    A[mf][3] = __float_as_uint(w4[8]);
                }
#pragma unroll
                for (int nf = 0; nf < 8; nf++) {
                    int col = nBase + nf * 8 + qr + kx + 3;
                    uint32_t b0 = __float_as_uint(sX[(ky * 8 + qc)     * SXS + col]);
                    uint32_t b1 = __float_as_uint(sX[(ky * 8 + qc + 4) * SXS + col]);
#pragma unroll
                    for (int mf = 0; mf < 4; mf++)
                        mma_tf32(acc[mf][nf], A[mf][0], A[mf][1], A[mf][2], A[mf][3], b0, b1);
                }
            }
        }
        __syncthreads();
    }

#pragma unroll
    for (int mf = 0; mf < 4; mf++) {
        int co = coTile + mBase + mf * 16 + qr;
        float bv0 = bias[co], bv1 = bias[co + 8];
#pragma unroll
        for (int nf = 0; nf < 8; nf++) {
            int px = nBase + nf * 8 + 2 * qc;
            float2 v0 = { fmaxf(acc[mf][nf][0] + bv0, 0.f),
                          fmaxf(acc[mf][nf][1] + bv0, 0.f) };
            float2 v1 = { fmaxf(acc[mf][nf][2] + bv1, 0.f),
                          fmaxf(acc[mf][nf][3] + bv1, 0.f) };
            *(float2*)&out[((((size_t)co       << 8) + y) << 8) + px] = v0;
            *(float2*)&out[((((size_t)(co + 8) << 8) + y) << 8) + px] = v1;
        }
    }
}

// ---------------------------------------------------------------------------
// TF32x3 split-precision conv (classification, 128x128, fp32-accurate).
// CTA: M=128 Cout x N=256 px = TWO image rows (y0, y0+1). 4 halo ky-rows.
// Per tap: acc += Ah*Bh + Ah*Bl + Al*Bh  (al*bl dropped, ~2^-24 relative).
// ---------------------------------------------------------------------------
#define SX3 136
#define STAGE_X3 (32 * SX3)             // 4352 floats (hi); lo contiguous after
#define STAGE_W3 (72 * SX3)             // 9792 floats
#define STAGE3_F (2 * STAGE_X3 + 2 * STAGE_W3)   // 28288 floats
#define CMMA3_SMEM (2 * STAGE3_F * 4)   // 226304 B

__device__ __forceinline__ void stage_chunk3(
    uint32_t st_b, const float* __restrict__ inh, const float* __restrict__ inl,
    const float* __restrict__ Wth, const float* __restrict__ Wtl,
    int y0, int coTile, int c, int Cout, int tid)
{
    const uint32_t xh = st_b;
    const uint32_t xl = st_b + STAGE_X3 * 4;
    const uint32_t wh = st_b + 2 * STAGE_X3 * 4;
    const uint32_t wl = wh + STAGE_W3 * 4;
#pragma unroll
    for (int it = 0; it < 4; it++) {            // 32 rows x 32 segs
        int i = tid + (it << 8);
        int row = i >> 5, seg = i & 31;
        int ky4 = row >> 3, ci = row & 7;
        int gy = y0 - 1 + ky4;
        if ((unsigned)gy < 128u) {
            size_t g = (size_t)((c << 3) + ci) * 16384 + gy * 128 + seg * 4;
            uint32_t d = (uint32_t)(row * SX3 + 4 + seg * 4) * 4;
            cpa16(xh + d, inh + g);
            cpa16(xl + d, inl + g);
        }
    }
#pragma unroll
    for (int it = 0; it < 9; it++) {            // 72 rows x 32 segs
        int i = tid + (it << 8);
        int row = i >> 5, seg = i & 31;
        size_t g = (size_t)(c * 72 + row) * Cout + coTile + seg * 4;
        uint32_t d = (uint32_t)(row * SX3 + seg * 4) * 4;
        cpa16(wh + d, Wth + g);
        cpa16(wl + d, Wtl + g);
    }
}

__global__ __launch_bounds__(256, 1) void conv3x3_mma3(
    const float* __restrict__ inh, const float* __restrict__ inl,
    const float* __restrict__ Wth, const float* __restrict__ Wtl,
    const float* __restrict__ bias,
    float* __restrict__ outh, float* __restrict__ outl,   // outl==null -> plain
    int Cin, int Cout)
{
    extern __shared__ float sm3[];
    const uint32_t base_b = smem_u32(sm3);

    const int y0     = blockIdx.x << 1;
    const int coTile = blockIdx.y << 7;
    const int tid  = threadIdx.x;
    const int lane = tid & 31;
    const int wid  = tid >> 5;
    const int mBase = (wid >> 2) << 6;
    const int nBase = (wid & 3) << 6;
    const int qr = lane >> 2;
    const int qc = lane & 3;

    // pre-zero X (hi+lo, both stages): halo cols + OOB rows
    for (int i = tid; i < 2 * STAGE_X3 / 4; i += 256) {
        uint32_t o = (uint32_t)(i * 4) * 4;
        asm volatile("st.shared.v4.u32 [%0], {%1,%1,%1,%1};" :: "r"(base_b + o), "r"(0u));
        asm volatile("st.shared.v4.u32 [%0], {%1,%1,%1,%1};"
                     :: "r"(base_b + (uint32_t)STAGE3_F * 4 + o), "r"(0u));
    }
    __syncthreads();

    const int nch = Cin >> 3;
    stage_chunk3(base_b, inh, inl, Wth, Wtl, y0, coTile, 0, Cout, tid);
    CP_COMMIT();

    float acc[4][8][4] = {};

    for (int c = 0; c < nch; c++) {
        const int s = c & 1;
        if (c + 1 < nch) {
            stage_chunk3(base_b + (uint32_t)((s ^ 1) * STAGE3_F) * 4,
                         inh, inl, Wth, Wtl, y0, coTile, c + 1, Cout, tid);
            CP_COMMIT();
            CP_WAIT1();
        } else {
            CP_WAIT0();
        }
        __syncthreads();

        const float* XH = sm3 + s * STAGE3_F;
        const float* XL = XH + STAGE_X3;
        const float* WH = XL + STAGE_X3;
        const float* WL = WH + STAGE_W3;

#pragma unroll
        for (int ky = 0; ky < 3; ky++) {
#pragma unroll
            for (int kx = 0; kx < 3; kx++) {
                const int t = ky * 3 + kx;
                uint32_t AH[4][4], AL[4][4];
#pragma unroll
                for (int mf = 0; mf < 4; mf++) {
                    int m = mBase + mf * 16 + qr;
                    int r0 = (qc * 9 + t) * SX3 + m;
                    int r4 = ((qc + 4) * 9 + t) * SX3 + m;
                    AH[mf][0] = __float_as_uint(WH[r0]);
                    AH[mf][1] = __float_as_uint(WH[r0 + 8]);
                    AH[mf][2] = __float_as_uint(WH[r4]);
                    AH[mf][3] = __float_as_uint(WH[r4 + 8]);
                    AL[mf][0] = __float_as_uint(WL[r0]);
                    AL[mf][1] = __float_as_uint(WL[r0 + 8]);
                    AL[mf][2] = __float_as_uint(WL[r4]);
                    AL[mf][3] = __float_as_uint(WL[r4 + 8]);
                }
#pragma unroll
                for (int nf = 0; nf < 8; nf++) {
                    int col = nBase + nf * 8 + qr;
                    int r = col >> 7, x = col & 127;
                    int rowb = (r + ky) * 8;
                    int i0 = (rowb + qc)     * SX3 + x + kx + 3;
                    int i1 = (rowb + qc + 4) * SX3 + x + kx + 3;
                    uint32_t bh0 = __float_as_uint(XH[i0]);
                    uint32_t bh1 = __float_as_uint(XH[i1]);
                    uint32_t bl0 = __float_as_uint(XL[i0]);
                    uint32_t bl1 = __float_as_uint(XL[i1]);
#pragma unroll
                    for (int mf = 0; mf < 4; mf++) {
                        mma_tf32(acc[mf][nf], AH[mf][0], AH[mf][1], AH[mf][2], AH[mf][3], bh0, bh1);
                        mma_tf32(acc[mf][nf], AH[mf][0], AH[mf][1], AH[mf][2], AH[mf][3], bl0, bl1);
                        mma_tf32(acc[mf][nf], AL[mf][0], AL[mf][1], AL[mf][2], AL[mf][3], bh0, bh1);
                    }
                }
            }
        }
        __syncthreads();
    }

    // epilogue: bias + ReLU; write split hi/lo (or plain fp32 if outl==null)
#pragma unroll
    for (int mf = 0; mf < 4; mf++) {
        int co = coTile + mBase + mf * 16 + qr;
        float bv0 = bias[co], bv1 = bias[co + 8];
#pragma unroll
        for (int nf = 0; nf < 8; nf++) {
            int n = nBase + nf * 8 + 2 * qc;
            int r = n >> 7, x = n & 127;
            size_t i0 = (size_t)co * 16384 + (y0 + r) * 128 + x;
            size_t i1 = (size_t)(co + 8) * 16384 + (y0 + r) * 128 + x;
            float a0 = fmaxf(acc[mf][nf][0] + bv0, 0.f);
            float a1 = fmaxf(acc[mf][nf][1] + bv0, 0.f);
            float a2 = fmaxf(acc[mf][nf][2] + bv1, 0.f);
            float a3 = fmaxf(acc[mf][nf][3] + bv1, 0.f);
            if (outl) {
                uint32_t h0 = to_tf32(a0), h1 = to_tf32(a1);
                uint32_t h2 = to_tf32(a2), h3 = to_tf32(a3);
                float2 vh0 = { __uint_as_float(h0), __uint_as_float(h1) };
                float2 vh1 = { __uint_as_float(h2), __uint_as_float(h3) };
                float2 vl0 = { __uint_as_float(to_tf32(a0 - vh0.x)),
                               __uint_as_float(to_tf32(a1 - vh0.y)) };
                float2 vl1 = { __uint_as_float(to_tf32(a2 - vh1.x)),
                               __uint_as_float(to_tf32(a3 - vh1.y)) };
                *(float2*)&outh[i0] = vh0;
                *(float2*)&outh[i1] = vh1;
                *(float2*)&outl[i0] = vl0;
                *(float2*)&outl[i1] = vl1;
            } else {
                float2 v0 = { a0, a1 };
                float2 v1 = { a2, a3 };
                *(float2*)&outh[i0] = v0;
                *(float2*)&outh[i1] = v1;
            }
        }
    }
}

// ---------------------------------------------------------------------------
// Heads / transforms
// ---------------------------------------------------------------------------
__global__ void cls_kernel(const float* __restrict__ h, const float* __restrict__ w,
                           const float* __restrict__ b, float* __restrict__ cls,
                           float* __restrict__ bin, int HW)
{
    int p = blockIdx.x * 256 + threadIdx.x;
    if (p >= HW) return;
    float s = b[0];
#pragma unroll 8
    for (int c = 0; c < 256; c++) s = fmaf(w[c], h[(size_t)c * HW + p], s);
    float sig = 1.f / (1.f + expf(-s));
    cls[p] = sig;
    bin[p] = (sig >= 0.5f) ? 1.f : 0.f;
}

__global__ void field_kernel(const float* __restrict__ r, const float* __restrict__ w,
                             const float* __restrict__ b, float* __restrict__ field,
                             int HW)
{
    int p = blockIdx.x * 256 + threadIdx.x;
    if (p >= HW) return;
    float s0 = b[0], s1 = b[1];
#pragma unroll 8
    for (int c = 0; c < 256; c++) {
        float v = r[(size_t)c * HW + p];
        s0 = fmaf(w[c], v, s0);
        s1 = fmaf(w[256 + c], v, s1);
    }
    field[p] = s0;
    field[HW + p] = s1;
}

__global__ void upsample_kernel(const float* __restrict__ bin, float* __restrict__ out)
{
    int idx = blockIdx.x * 256 + threadIdx.x;
    if (idx >= 256 * 256) return;
    int Y = idx >> 8, X = idx & 255;
    const float step = 127.0f / 255.0f;
    float ys = (float)Y * step, xs = (float)X * step;
    int y0 = (int)floorf(ys); int y1 = min(y0 + 1, 127);
    int x0 = (int)floorf(xs); int x1 = min(x0 + 1, 127);
    float wy = ys - (float)y0, wx = xs - (float)x0;
    float v00 = bin[y0 * 128 + x0], v01 = bin[y0 * 128 + x1];
    float v10 = bin[y1 * 128 + x0], v11 = bin[y1 * 128 + x1];
    out[idx] = rintf((v00 * (1.f - wx) + v01 * wx) * (1.f - wy)
                   + (v10 * (1.f - wx) + v11 * wx) * wy);
}

__global__ void contour_kernel(const float* __restrict__ cc,
                               const float* __restrict__ field,
                               const int* __restrict__ pnum_iter,
                               float* __restrict__ out, int npts)
{
    int i = blockIdx.x * 256 + threadIdx.x;
    if (i >= npts) return;
    const int W = 256, H = 256;
    float x = cc[2 * i], y = cc[2 * i + 1];
    int n = pnum_iter[0];
    for (int t = 0; t < n; t++) {
        float xc = fminf(fmaxf(x, 0.f), 255.f);
        float yc = fminf(fmaxf(y, 0.f), 255.f);
        int x0 = (int)floorf(xc); int x1 = min(x0 + 1, W - 1);
        int y0 = (int)floorf(yc); int y1 = min(y0 + 1, H - 1);
        float wx = xc - (float)x0, wy = yc - (float)y0;
        float ox, oy;
        {
            const float* f = field;
            float v00 = f[y0 * W + x0], v01 = f[y0 * W + x1];
            float v10 = f[y1 * W + x0], v11 = f[y1 * W + x1];
            ox = (v00 * (1.f - wx) + v01 * wx) * (1.f - wy)
               + (v10 * (1.f - wx) + v11 * wx) * wy;
        }
        {
            const float* f = field + H * W;
            float v00 = f[y0 * W + x0], v01 = f[y0 * W + x1];
            float v10 = f[y1 * W + x0], v11 = f[y1 * W + x1];
            oy = (v00 * (1.f - wx) + v01 * wx) * (1.f - wy)
               + (v10 * (1.f - wx) + v11 * wx) * wy;
        }
        x = fminf(fmaxf(x + ox, 0.f), 255.f);
        y = fminf(fmaxf(y + oy, 0.f), 255.f);
    }
    out[2 * i] = x;
    out[2 * i + 1] = y;
}

// ---------------------------------------------------------------------------
extern "C" void kernel_launch(void* const* d_in, const int* in_sizes, int n_in,
                              void* d_out, int out_size)
{
    const float* f1  = (const float*)d_in[0];
    const float* f2  = (const float*)d_in[1];
    const float* cc  = (const float*)d_in[2];
    const float* cw1 = (const float*)d_in[3];
    const float* cb1 = (const float*)d_in[4];
    const float* cw2 = (const float*)d_in[5];
    const float* cb2 = (const float*)d_in[6];
    const float* cw3 = (const float*)d_in[7];
    const float* cb3 = (const float*)d_in[8];
    const float* cw4 = (const float*)d_in[9];
    const float* cb4 = (const float*)d_in[10];
    const float* rw1 = (const float*)d_in[11];
    const float* rb1 = (const float*)d_in[12];
    const float* rw2 = (const float*)d_in[13];
    const float* rb2 = (const float*)d_in[14];
    const float* rw3 = (const float*)d_in[15];
    const float* rb3 = (const float*)d_in[16];
    const float* rw4 = (const float*)d_in[17];
    const float* rb4 = (const float*)d_in[18];
    const int*   pnum = (const int*)d_in[19];

    float* out = (float*)d_out;
    float* out_cls = out;
    float* out_bin = out + 16384;
    float* out_ctr = out + 16384 + 65536;

    float *bufA, *bufB, *Wt1, *Wt2, *Wt3, *field, *bin;
    float *CW1h, *CW1l, *CW2h, *CW2l, *CW3h, *CW3l;
    cudaGetSymbolAddress((void**)&bufA, g_bufA);
    cudaGetSymbolAddress((void**)&bufB, g_bufB);
    cudaGetSymbolAddress((void**)&Wt1,  g_Wt1);
    cudaGetSymbolAddress((void**)&Wt2,  g_Wt2);
    cudaGetSymbolAddress((void**)&Wt3,  g_Wt3);
    cudaGetSymbolAddress((void**)&CW1h, g_CW1h);
    cudaGetSymbolAddress((void**)&CW1l, g_CW1l);
    cudaGetSymbolAddress((void**)&CW2h, g_CW2h);
    cudaGetSymbolAddress((void**)&CW2l, g_CW2l);
    cudaGetSymbolAddress((void**)&CW3h, g_CW3h);
    cudaGetSymbolAddress((void**)&CW3l, g_CW3l);
    cudaGetSymbolAddress((void**)&field, g_field);
    cudaGetSymbolAddress((void**)&bin,  g_bin);

    // cls scratch carved from bufA/bufB (free until refinement phase)
    float* f2h = bufA;                      // 8M floats
    float* f2l = bufA + 8388608u;
    float* h1h = bufA + 16777216u;          // 16M floats
    float* h1l = bufA + 33554432u;
    float* c3  = bufA + 50331648u;          // 4M floats
    float* h2h = bufB;
    float* h2l = bufB + 8388608u;

    cudaFuncSetAttribute(conv3x3_mma2, cudaFuncAttributeMaxDynamicSharedMemorySize, CMMA2_SMEM);
    cudaFuncSetAttribute(conv3x3_mma3, cudaFuncAttributeMaxDynamicSharedMemorySize, CMMA3_SMEM);

    // ---- weight transforms / input split (independent prep) ----
    wt_transform<<<(1024 * 512 * 9 + 255) / 256, 256>>>(rw1, Wt1, 1024, 512);
    wt_transform<<<(512 * 1024 * 9 + 255) / 256, 256>>>(rw2, Wt2, 512, 1024);
    wt_transform<<<(256 * 512 * 9 + 255) / 256, 256>>>(rw3, Wt3, 256, 512);
    wt_transform_split<<<(1024 * 512 * 9 + 255) / 256, 256>>>(cw1, CW1h, CW1l, 1024, 512);
    wt_transform_split<<<(512 * 1024 * 9 + 255) / 256, 256>>>(cw2, CW2h, CW2l, 512, 1024);
    wt_transform_split<<<(256 * 512 * 9 + 255) / 256, 256>>>(cw3, CW3h, CW3l, 256, 512);
    split_input<<<(8388608 + 255) / 256, 256>>>(f2, f2h, f2l, 8388608);

    // ---- classification branch (tf32x3 split precision, fp32-accurate) ----
    conv3x3_mma3<<<dim3(64, 8), 256, CMMA3_SMEM>>>(f2h, f2l, CW1h, CW1l, cb1, h1h, h1l, 512, 1024);
    conv3x3_mma3<<<dim3(64, 4), 256, CMMA3_SMEM>>>(h1h, h1l, CW2h, CW2l, cb2, h2h, h2l, 1024, 512);
    conv3x3_mma3<<<dim3(64, 2), 256, CMMA3_SMEM>>>(h2h, h2l, CW3h, CW3l, cb3, c3, nullptr, 512, 256);
    cls_kernel<<<64, 256>>>(c3, cw4, cb4, out_cls, bin, 16384);
    upsample_kernel<<<256, 256>>>(bin, out_bin);

    // ---- refinement branch (tf32 mma.sync, pipelined) ----
    conv3x3_mma2<<<dim3(256, 8), 256, CMMA2_SMEM>>>(f1,   Wt1, rb1, bufA, 512, 1024);
    conv3x3_mma2<<<dim3(256, 4), 256, CMMA2_SMEM>>>(bufA, Wt2, rb2, bufB, 1024, 512);
    conv3x3_mma2<<<dim3(256, 2), 256, CMMA2_SMEM>>>(bufB, Wt3, rb3, bufA, 512, 256);
    field_kernel<<<256, 256>>>(bufA, rw4, rb4, field, 65536);
    contour_kernel<<<(38400 + 255) / 256, 256>>>(cc, field, pnum, out_ctr, 38400);
}

// round 12
// speedup vs baseline: 4.2298x; 1.0035x over previous
#include <cuda_runtime.h>
#include <math.h>
#include <stdint.h>

// ---------------------------------------------------------------------------
// Scratch (device globals -- no runtime allocation allowed)
// ---------------------------------------------------------------------------
__device__ float g_bufA[1024u * 256u * 256u];   // 256 MB (also cls hi/lo scratch)
__device__ float g_bufB[512u * 256u * 256u];    // 128 MB
__device__ float g_Wt1[1024u * 512u * 9u];
__device__ float g_Wt2[512u * 1024u * 9u];
__device__ float g_Wt3[256u * 512u * 9u];
__device__ float g_CW1h[1024u * 512u * 9u];
__device__ float g_CW1l[1024u * 512u * 9u];
__device__ float g_CW2h[512u * 1024u * 9u];
__device__ float g_CW2l[512u * 1024u * 9u];
__device__ float g_CW3h[256u * 512u * 9u];
__device__ float g_CW3l[256u * 512u * 9u];
__device__ float g_field[2 * 256 * 256];
__device__ float g_bin[128 * 128];

// ---------------------------------------------------------------------------
// tf32 helpers (portable sm_80+ -- NO 'a'-suffix features)
// ---------------------------------------------------------------------------
__device__ __forceinline__ uint32_t to_tf32(float x) {
    uint32_t r;
    asm("cvt.rna.tf32.f32 %0, %1;" : "=r"(r) : "f"(x));
    return r;
}
__device__ __forceinline__ float tf32f(float x) { return __uint_as_float(to_tf32(x)); }

__device__ __forceinline__ void mma_tf32(float c[4],
                                         uint32_t a0, uint32_t a1, uint32_t a2, uint32_t a3,
                                         uint32_t b0, uint32_t b1) {
    asm volatile(
        "mma.sync.aligned.m16n8k8.row.col.f32.tf32.tf32.f32 "
        "{%0,%1,%2,%3}, {%4,%5,%6,%7}, {%8,%9}, {%0,%1,%2,%3};"
        : "+f"(c[0]), "+f"(c[1]), "+f"(c[2]), "+f"(c[3])
        : "r"(a0), "r"(a1), "r"(a2), "r"(a3), "r"(b0), "r"(b1));
}
__device__ __forceinline__ uint32_t smem_u32(const void* p) {
    uint32_t a;
    asm("{ .reg .u64 t; cvta.to.shared.u64 t, %1; cvt.u32.u64 %0, t; }" : "=r"(a) : "l"(p));
    return a;
}
__device__ __forceinline__ void cpa16(uint32_t dst, const void* src) {
    asm volatile("cp.async.cg.shared.global [%0], [%1], 16;" :: "r"(dst), "l"(src) : "memory");
}
#define CP_COMMIT() asm volatile("cp.async.commit_group;" ::: "memory")
#define CP_WAIT1()  asm volatile("cp.async.wait_group 1;" ::: "memory")
#define CP_WAIT0()  asm volatile("cp.async.wait_group 0;" ::: "memory")

// ---------------------------------------------------------------------------
// Weight packers: fragment-major float4 layout.
// WtP[(((c*9+t)*4+qc)*(Cout/16)+g)*8+r] = {w(m,qc), w(m+8,qc), w(m,qc+4), w(m+8,qc+4)}
//   m = g*16+r;  w(m,k) = w[co=m][ci=c*8+k][tap t]   (tf32-rounded)
// One LDS.128 loads a thread's whole m16k8 A fragment.
// ---------------------------------------------------------------------------
__global__ void wt_pack4(const float* __restrict__ w, float4* __restrict__ out,
                         int Cout, int Cin)
{
    int i = blockIdx.x * 256 + threadIdx.x;
    int total = (Cin >> 3) * 9 * 4 * (Cout >> 4) * 8;
    if (i >= total) return;
    int r  = i & 7;
    int g  = (i >> 3) % (Cout >> 4);
    int rest = (i >> 3) / (Cout >> 4);
    int qc = rest & 3;
    int tc = rest >> 2;
    int t  = tc % 9;
    int c  = tc / 9;
    int m  = g * 16 + r;
    int ci = c * 8;
    float4 v;
    v.x = tf32f(w[((size_t)m       * Cin + ci + qc    ) * 9 + t]);
    v.y = tf32f(w[((size_t)(m + 8) * Cin + ci + qc    ) * 9 + t]);
    v.z = tf32f(w[((size_t)m       * Cin + ci + qc + 4) * 9 + t]);
    v.w = tf32f(w[((size_t)(m + 8) * Cin + ci + qc + 4) * 9 + t]);
    out[i] = v;
}

__global__ void wt_pack4_split(const float* __restrict__ w,
                               float4* __restrict__ oh, float4* __restrict__ ol,
                               int Cout, int Cin)
{
    int i = blockIdx.x * 256 + threadIdx.x;
    int total = (Cin >> 3) * 9 * 4 * (Cout >> 4) * 8;
    if (i >= total) return;
    int r  = i & 7;
    int g  = (i >> 3) % (Cout >> 4);
    int rest = (i >> 3) / (Cout >> 4);
    int qc = rest & 3;
    int tc = rest >> 2;
    int t  = tc % 9;
    int c  = tc / 9;
    int m  = g * 16 + r;
    int ci = c * 8;
    float s0 = w[((size_t)m       * Cin + ci + qc    ) * 9 + t];
    float s1 = w[((size_t)(m + 8) * Cin + ci + qc    ) * 9 + t];
    float s2 = w[((size_t)m       * Cin + ci + qc + 4) * 9 + t];
    float s3 = w[((size_t)(m + 8) * Cin + ci + qc + 4) * 9 + t];
    float4 h = { tf32f(s0), tf32f(s1), tf32f(s2), tf32f(s3) };
    oh[i] = h;
    ol[i] = make_float4(tf32f(s0 - h.x), tf32f(s1 - h.y),
                        tf32f(s2 - h.z), tf32f(s3 - h.w));
}

// split f2 into hi/lo planes (same NCHW layout)
__global__ void split_input(const float* __restrict__ in,
                            float* __restrict__ oh, float* __restrict__ ol, int n)
{
    int i = blockIdx.x * 256 + threadIdx.x;
    if (i >= n) return;
    float v = in[i];
    float h = tf32f(v);
    oh[i] = h;
    ol[i] = tf32f(v - h);
}

// ---------------------------------------------------------------------------
// TF32 mma.sync 3x3 SAME conv v3 (refinement, 256x256, single tf32).
// A fragments via one LDS.128 each (packed weights); B via 2 scalar LDS.
// ---------------------------------------------------------------------------
#define SXS 264                       // input row stride (floats)
#define SW4 66                        // weight row stride (float4 per (t,qc))
#define STAGE_X (24 * SXS)            // 6336 floats
#define STAGE_W (9 * 4 * SW4 * 4)     // 9504 floats
#define STAGE_F (STAGE_X + STAGE_W)   // 15840 floats
#define CMMA2_SMEM (2 * STAGE_F * 4)  // 126720 B

__device__ __forceinline__ void stage_chunk(
    uint32_t sx_b, uint32_t sw_b, const float* __restrict__ in,
    const float4* __restrict__ WtP, int y, int coTile, int c, int Cout, int tid)
{
#pragma unroll
    for (int it = 0; it < 6; it++) {
        int i = tid + (it << 8);
        int row = i >> 6, seg = i & 63;
        int ky = row >> 3, ci = row & 7;
        int gy = y - 1 + ky;
        if ((unsigned)gy < 256u)
            cpa16(sx_b + (uint32_t)(row * SXS + 4 + seg * 4) * 4,
                  in + ((((size_t)((c << 3) + ci)) << 8) + gy << 8) + seg * 4);
    }
    // weights: 2304 float4 (9 taps x 4 qc x 8 g x 8 r)
#pragma unroll
    for (int it = 0; it < 9; it++) {
        int i = tid + (it << 8);
        int r = i & 7, gl = (i >> 3) & 7, qc = (i >> 6) & 3, t = i >> 8;
        cpa16(sw_b + (uint32_t)(((t * 4 + qc) * SW4 + gl * 8 + r) * 16),
              WtP + ((((size_t)(c * 9 + t) * 4 + qc) * (Cout >> 4) + (coTile >> 4) + gl) * 8 + r));
    }
}

__global__ __launch_bounds__(256, 1) void conv3x3_mma2(
    const float* __restrict__ in, const float4* __restrict__ WtP,
    const float* __restrict__ bias, float* __restrict__ out,
    int Cin, int Cout)
{
    extern __shared__ float sm[];
    const uint32_t base_b = smem_u32(sm);

    const int y      = blockIdx.x;
    const int coTile = blockIdx.y << 7;
    const int tid  = threadIdx.x;
    const int lane = tid & 31;
    const int wid  = tid >> 5;
    const int gBase = (wid >> 2) << 2;   // g = gBase + mf  (0..7)
    const int nBase = (wid & 3) << 6;
    const int qr = lane >> 2;
    const int qc = lane & 3;

    for (int i = tid; i < 2 * STAGE_X / 4; i += 256) {
        uint32_t a = base_b + ((i >= STAGE_X / 4)
                     ? (uint32_t)(STAGE_F + (i - STAGE_X / 4) * 4) * 4
                     : (uint32_t)(i * 4) * 4);
        asm volatile("st.shared.v4.u32 [%0], {%1,%1,%1,%1};" :: "r"(a), "r"(0u));
    }
    __syncthreads();

    const int nch = Cin >> 3;
    stage_chunk(base_b, base_b + STAGE_X * 4, in, WtP, y, coTile, 0, Cout, tid);
    CP_COMMIT();

    float acc[4][8][4] = {};

    for (int c = 0; c < nch; c++) {
        const int s = c & 1;
        if (c + 1 < nch) {
            uint32_t sb = base_b + (uint32_t)((s ^ 1) * STAGE_F) * 4;
            stage_chunk(sb, sb + STAGE_X * 4, in, WtP, y, coTile, c + 1, Cout, tid);
            CP_COMMIT();
            CP_WAIT1();
        } else {
            CP_WAIT0();
        }
        __syncthreads();

        const float* sX = sm + s * STAGE_F;
        const float* sW = sX + STAGE_X;

#pragma unroll
        for (int ky = 0; ky < 3; ky++) {
#pragma unroll
            for (int kx = 0; kx < 3; kx++) {
                const int t = ky * 3 + kx;
                uint32_t A[4][4];
#pragma unroll
                for (int mf = 0; mf < 4; mf++) {
                    float4 av = *(const float4*)&sW[((t * 4 + qc) * SW4
                                                     + (gBase + mf) * 8 + qr) << 2];
                    A[mf][0] = __float_as_uint(av.x);
                    A[mf][1] = __float_as_uint(av.y);
                    A[mf][2] = __float_as_uint(av.z);
                    A[mf][3] = __float_as_uint(av.w);
                }
#pragma unroll
                for (int nf = 0; nf < 8; nf++) {
                    int col = nBase + nf * 8 + qr + kx + 3;
                    uint32_t b0 = __float_as_uint(sX[(ky * 8 + qc)     * SXS + col]);
                    uint32_t b1 = __float_as_uint(sX[(ky * 8 + qc + 4) * SXS + col]);
#pragma unroll
                    for (int mf = 0; mf < 4; mf++)
                        mma_tf32(acc[mf][nf], A[mf][0], A[mf][1], A[mf][2], A[mf][3], b0, b1);
                }
            }
        }
        __syncthreads();
    }

#pragma unroll
    for (int mf = 0; mf < 4; mf++) {
        int co = coTile + (gBase + mf) * 16 + qr;
        float bv0 = bias[co], bv1 = bias[co + 8];
#pragma unroll
        for (int nf = 0; nf < 8; nf++) {
            int px = nBase + nf * 8 + 2 * qc;
            float2 v0 = { fmaxf(acc[mf][nf][0] + bv0, 0.f),
                          fmaxf(acc[mf][nf][1] + bv0, 0.f) };
            float2 v1 = { fmaxf(acc[mf][nf][2] + bv1, 0.f),
                          fmaxf(acc[mf][nf][3] + bv1, 0.f) };
            *(float2*)&out[((((size_t)co       << 8) + y) << 8) + px] = v0;
            *(float2*)&out[((((size_t)(co + 8) << 8) + y) << 8) + px] = v1;
        }
    }
}

// ---------------------------------------------------------------------------
// TF32x3 split-precision conv v3 (classification, 128x128, fp32-accurate).
// ---------------------------------------------------------------------------
#define SX3 136
#define STAGE_X3 (32 * SX3)                       // 4352 floats
#define STAGE_W3 (9 * 4 * SW4 * 4)                // 9504 floats
#define STAGE3_F (2 * STAGE_X3 + 2 * STAGE_W3)    // 27712 floats
#define CMMA3_SMEM (2 * STAGE3_F * 4)             // 221696 B

__device__ __forceinline__ void stage_chunk3(
    uint32_t st_b, const float* __restrict__ inh, const float* __restrict__ inl,
    const float4* __restrict__ WtPh, const float4* __restrict__ WtPl,
    int y0, int coTile, int c, int Cout, int tid)
{
    const uint32_t xh = st_b;
    const uint32_t xl = st_b + STAGE_X3 * 4;
    const uint32_t wh = st_b + 2 * STAGE_X3 * 4;
    const uint32_t wl = wh + STAGE_W3 * 4;
#pragma unroll
    for (int it = 0; it < 4; it++) {
        int i = tid + (it << 8);
        int row = i >> 5, seg = i & 31;
        int ky4 = row >> 3, ci = row & 7;
        int gy = y0 - 1 + ky4;
        if ((unsigned)gy < 128u) {
            size_t g = (size_t)((c << 3) + ci) * 16384 + gy * 128 + seg * 4;
            uint32_t d = (uint32_t)(row * SX3 + 4 + seg * 4) * 4;
            cpa16(xh + d, inh + g);
            cpa16(xl + d, inl + g);
        }
    }
#pragma unroll
    for (int it = 0; it < 9; it++) {
        int i = tid + (it << 8);
        int r = i & 7, gl = (i >> 3) & 7, qc = (i >> 6) & 3, t = i >> 8;
        size_t src = (((size_t)(c * 9 + t) * 4 + qc) * (Cout >> 4) + (coTile >> 4) + gl) * 8 + r;
        uint32_t d = (uint32_t)(((t * 4 + qc) * SW4 + gl * 8 + r) * 16);
        cpa16(wh + d, WtPh + src);
        cpa16(wl + d, WtPl + src);
    }
}

__global__ __launch_bounds__(256, 1) void conv3x3_mma3(
    const float* __restrict__ inh, const float* __restrict__ inl,
    const float4* __restrict__ WtPh, const float4* __restrict__ WtPl,
    const float* __restrict__ bias,
    float* __restrict__ outh, float* __restrict__ outl,   // outl==null -> plain
    int Cin, int Cout)
{
    extern __shared__ float sm3[];
    const uint32_t base_b = smem_u32(sm3);

    const int y0     = blockIdx.x << 1;
    const int coTile = blockIdx.y << 7;
    const int tid  = threadIdx.x;
    const int lane = tid & 31;
    const int wid  = tid >> 5;
    const int gBase = (wid >> 2) << 2;
    const int nBase = (wid & 3) << 6;
    const int qr = lane >> 2;
    const int qc = lane & 3;

    for (int i = tid; i < 2 * STAGE_X3 / 4; i += 256) {
        uint32_t o = (uint32_t)(i * 4) * 4;
        asm volatile("st.shared.v4.u32 [%0], {%1,%1,%1,%1};" :: "r"(base_b + o), "r"(0u));
        asm volatile("st.shared.v4.u32 [%0], {%1,%1,%1,%1};"
                     :: "r"(base_b + (uint32_t)STAGE3_F * 4 + o), "r"(0u));
    }
    __syncthreads();

    const int nch = Cin >> 3;
    stage_chunk3(base_b, inh, inl, WtPh, WtPl, y0, coTile, 0, Cout, tid);
    CP_COMMIT();

    float acc[4][8][4] = {};

    for (int c = 0; c < nch; c++) {
        const int s = c & 1;
        if (c + 1 < nch) {
            stage_chunk3(base_b + (uint32_t)((s ^ 1) * STAGE3_F) * 4,
                         inh, inl, WtPh, WtPl, y0, coTile, c + 1, Cout, tid);
            CP_COMMIT();
            CP_WAIT1();
        } else {
            CP_WAIT0();
        }
        __syncthreads();

        const float* XH = sm3 + s * STAGE3_F;
        const float* XL = XH + STAGE_X3;
        const float* WH = XL + STAGE_X3;
        const float* WL = WH + STAGE_W3;

#pragma unroll
        for (int ky = 0; ky < 3; ky++) {
#pragma unroll
            for (int kx = 0; kx < 3; kx++) {
                const int t = ky * 3 + kx;
                uint32_t AH[4][4], AL[4][4];
#pragma unroll
                for (int mf = 0; mf < 4; mf++) {
                    int idx = ((t * 4 + qc) * SW4 + (gBase + mf) * 8 + qr) << 2;
                    float4 ah = *(const float4*)&WH[idx];
                    float4 al = *(const float4*)&WL[idx];
                    AH[mf][0] = __float_as_uint(ah.x);
                    AH[mf][1] = __float_as_uint(ah.y);
                    AH[mf][2] = __float_as_uint(ah.z);
                    AH[mf][3] = __float_as_uint(ah.w);
                    AL[mf][0] = __float_as_uint(al.x);
                    AL[mf][1] = __float_as_uint(al.y);
                    AL[mf][2] = __float_as_uint(al.z);
                    AL[mf][3] = __float_as_uint(al.w);
                }
#pragma unroll
                for (int nf = 0; nf < 8; nf++) {
                    int col = nBase + nf * 8 + qr;
                    int r = col >> 7, x = col & 127;
                    int rowb = (r + ky) * 8;
                    int i0 = (rowb + qc)     * SX3 + x + kx + 3;
                    int i1 = (rowb + qc + 4) * SX3 + x + kx + 3;
                    uint32_t bh0 = __float_as_uint(XH[i0]);
                    uint32_t bh1 = __float_as_uint(XH[i1]);
                    uint32_t bl0 = __float_as_uint(XL[i0]);
                    uint32_t bl1 = __float_as_uint(XL[i1]);
#pragma unroll
                    for (int mf = 0; mf < 4; mf++) {
                        mma_tf32(acc[mf][nf], AH[mf][0], AH[mf][1], AH[mf][2], AH[mf][3], bh0, bh1);
                        mma_tf32(acc[mf][nf], AH[mf][0], AH[mf][1], AH[mf][2], AH[mf][3], bl0, bl1);
                        mma_tf32(acc[mf][nf], AL[mf][0], AL[mf][1], AL[mf][2], AL[mf][3], bh0, bh1);
                    }
                }
            }
        }
        __syncthreads();
    }

#pragma unroll
    for (int mf = 0; mf < 4; mf++) {
        int co = coTile + (gBase + mf) * 16 + qr;
        float bv0 = bias[co], bv1 = bias[co + 8];
#pragma unroll
        for (int nf = 0; nf < 8; nf++) {
            int n = nBase + nf * 8 + 2 * qc;
            int r = n >> 7, x = n & 127;
            size_t i0 = (size_t)co * 16384 + (y0 + r) * 128 + x;
            size_t i1 = (size_t)(co + 8) * 16384 + (y0 + r) * 128 + x;
            float a0 = fmaxf(acc[mf][nf][0] + bv0, 0.f);
            float a1 = fmaxf(acc[mf][nf][1] + bv0, 0.f);
            float a2 = fmaxf(acc[mf][nf][2] + bv1, 0.f);
            float a3 = fmaxf(acc[mf][nf][3] + bv1, 0.f);
            if (outl) {
                float2 vh0 = { tf32f(a0), tf32f(a1) };
                float2 vh1 = { tf32f(a2), tf32f(a3) };
                float2 vl0 = { tf32f(a0 - vh0.x), tf32f(a1 - vh0.y) };
                float2 vl1 = { tf32f(a2 - vh1.x), tf32f(a3 - vh1.y) };
                *(float2*)&outh[i0] = vh0;
                *(float2*)&outh[i1] = vh1;
                *(float2*)&outl[i0] = vl0;
                *(float2*)&outl[i1] = vl1;
            } else {
                float2 v0 = { a0, a1 };
                float2 v1 = { a2, a3 };
                *(float2*)&outh[i0] = v0;
                *(float2*)&outh[i1] = v1;
            }
        }
    }
}

// ---------------------------------------------------------------------------
// Heads / transforms
// ---------------------------------------------------------------------------
__global__ void cls_kernel(const float* __restrict__ h, const float* __restrict__ w,
                           const float* __restrict__ b, float* __restrict__ cls,
                           float* __restrict__ bin, int HW)
{
    int p = blockIdx.x * 256 + threadIdx.x;
    if (p >= HW) return;
    float s = b[0];
#pragma unroll 8
    for (int c = 0; c < 256; c++) s = fmaf(w[c], h[(size_t)c * HW + p], s);
    float sig = 1.f / (1.f + expf(-s));
    cls[p] = sig;
    bin[p] = (sig >= 0.5f) ? 1.f : 0.f;
}

__global__ void field_kernel(const float* __restrict__ r, const float* __restrict__ w,
                             const float* __restrict__ b, float* __restrict__ field,
                             int HW)
{
    int p = blockIdx.x * 256 + threadIdx.x;
    if (p >= HW) return;
    float s0 = b[0], s1 = b[1];
#pragma unroll 8
    for (int c = 0; c < 256; c++) {
        float v = r[(size_t)c * HW + p];
        s0 = fmaf(w[c], v, s0);
        s1 = fmaf(w[256 + c], v, s1);
    }
    field[p] = s0;
    field[HW + p] = s1;
}

__global__ void upsample_kernel(const float* __restrict__ bin, float* __restrict__ out)
{
    int idx = blockIdx.x * 256 + threadIdx.x;
    if (idx >= 256 * 256) return;
    int Y = idx >> 8, X = idx & 255;
    const float step = 127.0f / 255.0f;
    float ys = (float)Y * step, xs = (float)X * step;
    int y0 = (int)floorf(ys); int y1 = min(y0 + 1, 127);
    int x0 = (int)floorf(xs); int x1 = min(x0 + 1, 127);
    float wy = ys - (float)y0, wx = xs - (float)x0;
    float v00 = bin[y0 * 128 + x0], v01 = bin[y0 * 128 + x1];
    float v10 = bin[y1 * 128 + x0], v11 = bin[y1 * 128 + x1];
    out[idx] = rintf((v00 * (1.f - wx) + v01 * wx) * (1.f - wy)
                   + (v10 * (1.f - wx) + v11 * wx) * wy);
}

__global__ void contour_kernel(const float* __restrict__ cc,
                               const float* __restrict__ field,
                               const int* __restrict__ pnum_iter,
                               float* __restrict__ out, int npts)
{
    int i = blockIdx.x * 256 + threadIdx.x;
    if (i >= npts) return;
    const int W = 256, H = 256;
    float x = cc[2 * i], y = cc[2 * i + 1];
    int n = pnum_iter[0];
    for (int t = 0; t < n; t++) {
        float xc = fminf(fmaxf(x, 0.f), 255.f);
        float yc = fminf(fmaxf(y, 0.f), 255.f);
        int x0 = (int)floorf(xc); int x1 = min(x0 + 1, W - 1);
        int y0 = (int)floorf(yc); int y1 = min(y0 + 1, H - 1);
        float wx = xc - (float)x0, wy = yc - (float)y0;
        float ox, oy;
        {
            const float* f = field;
            float v00 = f[y0 * W + x0], v01 = f[y0 * W + x1];
            float v10 = f[y1 * W + x0], v11 = f[y1 * W + x1];
            ox = (v00 * (1.f - wx) + v01 * wx) * (1.f - wy)
               + (v10 * (1.f - wx) + v11 * wx) * wy;
        }
        {
            const float* f = field + H * W;
            float v00 = f[y0 * W + x0], v01 = f[y0 * W + x1];
            float v10 = f[y1 * W + x0], v11 = f[y1 * W + x1];
            oy = (v00 * (1.f - wx) + v01 * wx) * (1.f - wy)
               + (v10 * (1.f - wx) + v11 * wx) * wy;
        }
        x = fminf(fmaxf(x + ox, 0.f), 255.f);
        y = fminf(fmaxf(y + oy, 0.f), 255.f);
    }
    out[2 * i] = x;
    out[2 * i + 1] = y;
}

// ---------------------------------------------------------------------------
extern "C" void kernel_launch(void* const* d_in, const int* in_sizes, int n_in,
                              void* d_out, int out_size)
{
    const float* f1  = (const float*)d_in[0];
    const float* f2  = (const float*)d_in[1];
    const float* cc  = (const float*)d_in[2];
    const float* cw1 = (const float*)d_in[3];
    const float* cb1 = (const float*)d_in[4];
    const float* cw2 = (const float*)d_in[5];
    const float* cb2 = (const float*)d_in[6];
    const float* cw3 = (const float*)d_in[7];
    const float* cb3 = (const float*)d_in[8];
    const float* cw4 = (const float*)d_in[9];
    const float* cb4 = (const float*)d_in[10];
    const float* rw1 = (const float*)d_in[11];
    const float* rb1 = (const float*)d_in[12];
    const float* rw2 = (const float*)d_in[13];
    const float* rb2 = (const float*)d_in[14];
    const float* rw3 = (const float*)d_in[15];
    const float* rb3 = (const float*)d_in[16];
    const float* rw4 = (const float*)d_in[17];
    const float* rb4 = (const float*)d_in[18];
    const int*   pnum = (const int*)d_in[19];

    float* out = (float*)d_out;
    float* out_cls = out;
    float* out_bin = out + 16384;
    float* out_ctr = out + 16384 + 65536;

    float *bufA, *bufB, *Wt1, *Wt2, *Wt3, *field, *bin;
    float *CW1h, *CW1l, *CW2h, *CW2l, *CW3h, *CW3l;
    cudaGetSymbolAddress((void**)&bufA, g_bufA);
    cudaGetSymbolAddress((void**)&bufB, g_bufB);
    cudaGetSymbolAddress((void**)&Wt1,  g_Wt1);
    cudaGetSymbolAddress((void**)&Wt2,  g_Wt2);
    cudaGetSymbolAddress((void**)&Wt3,  g_Wt3);
    cudaGetSymbolAddress((void**)&CW1h, g_CW1h);
    cudaGetSymbolAddress((void**)&CW1l, g_CW1l);
    cudaGetSymbolAddress((void**)&CW2h, g_CW2h);
    cudaGetSymbolAddress((void**)&CW2l, g_CW2l);
    cudaGetSymbolAddress((void**)&CW3h, g_CW3h);
    cudaGetSymbolAddress((void**)&CW3l, g_CW3l);
    cudaGetSymbolAddress((void**)&field, g_field);
    cudaGetSymbolAddress((void**)&bin,  g_bin);

    // cls scratch carved from bufA/bufB (free until refinement phase)
    float* f2h = bufA;
    float* f2l = bufA + 8388608u;
    float* h1h = bufA + 16777216u;
    float* h1l = bufA + 33554432u;
    float* c3  = bufA + 50331648u;
    float* h2h = bufB;
    float* h2l = bufB + 8388608u;

    cudaFuncSetAttribute(conv3x3_mma2, cudaFuncAttributeMaxDynamicSharedMemorySize, CMMA2_SMEM);
    cudaFuncSetAttribute(conv3x3_mma3, cudaFuncAttributeMaxDynamicSharedMemorySize, CMMA3_SMEM);

    // ---- weight packing / input split (independent prep) ----
    {
        int t1 = (512 >> 3) * 9 * 4 * (1024 >> 4) * 8;   // 1179648
        int t2 = (1024 >> 3) * 9 * 4 * (512 >> 4) * 8;
        int t3 = (512 >> 3) * 9 * 4 * (256 >> 4) * 8;
        wt_pack4<<<(t1 + 255) / 256, 256>>>(rw1, (float4*)Wt1, 1024, 512);
        wt_pack4<<<(t2 + 255) / 256, 256>>>(rw2, (float4*)Wt2, 512, 1024);
        wt_pack4<<<(t3 + 255) / 256, 256>>>(rw3, (float4*)Wt3, 256, 512);
        wt_pack4_split<<<(t1 + 255) / 256, 256>>>(cw1, (float4*)CW1h, (float4*)CW1l, 1024, 512);
        wt_pack4_split<<<(t2 + 255) / 256, 256>>>(cw2, (float4*)CW2h, (float4*)CW2l, 512, 1024);
        wt_pack4_split<<<(t3 + 255) / 256, 256>>>(cw3, (float4*)CW3h, (float4*)CW3l, 256, 512);
    }
    split_input<<<(8388608 + 255) / 256, 256>>>(f2, f2h, f2l, 8388608);

    // ---- classification branch (tf32x3 split precision, fp32-accurate) ----
    conv3x3_mma3<<<dim3(64, 8), 256, CMMA3_SMEM>>>(f2h, f2l, (const float4*)CW1h, (const float4*)CW1l, cb1, h1h, h1l, 512, 1024);
    conv3x3_mma3<<<dim3(64, 4), 256, CMMA3_SMEM>>>(h1h, h1l, (const float4*)CW2h, (const float4*)CW2l, cb2, h2h, h2l, 1024, 512);
    conv3x3_mma3<<<dim3(64, 2), 256, CMMA3_SMEM>>>(h2h, h2l, (const float4*)CW3h, (const float4*)CW3l, cb3, c3, nullptr, 512, 256);
    cls_kernel<<<64, 256>>>(c3, cw4, cb4, out_cls, bin, 16384);
    upsample_kernel<<<256, 256>>>(bin, out_bin);

    // ---- refinement branch (tf32 mma.sync, pipelined) ----
    conv3x3_mma2<<<dim3(256, 8), 256, CMMA2_SMEM>>>(f1,   (const float4*)Wt1, rb1, bufA, 512, 1024);
    conv3x3_mma2<<<dim3(256, 4), 256, CMMA2_SMEM>>>(bufA, (const float4*)Wt2, rb2, bufB, 1024, 512);
    conv3x3_mma2<<<dim3(256, 2), 256, CMMA2_SMEM>>>(bufB, (const float4*)Wt3, rb3, bufA, 512, 256);
    field_kernel<<<256, 256>>>(bufA, rw4, rb4, field, 65536);
    contour_kernel<<<(38400 + 255) / 256, 256>>>(cc, field, pnum, out_ctr, 38400);
}

// round 13
// speedup vs baseline: 5.6963x; 1.3467x over previous
#include <cuda_runtime.h>
#include <math.h>
#include <stdint.h>

// ---------------------------------------------------------------------------
// Scratch (device globals -- no runtime allocation allowed)
// ---------------------------------------------------------------------------
__device__ float g_bufA[1024u * 256u * 256u];   // 256 MB (also cls scratch)
__device__ float g_bufB[512u * 256u * 256u];    // 128 MB
__device__ float g_Wt1[1024u * 512u * 9u];
__device__ float g_Wt2[512u * 1024u * 9u];
__device__ float g_Wt3[256u * 512u * 9u];
__device__ float g_CW1[1024u * 512u * 9u];
__device__ float g_CW2[512u * 1024u * 9u];
__device__ float g_CW3[256u * 512u * 9u];
__device__ float g_field[2 * 256 * 256];
__device__ float g_bin[128 * 128];

// ---------------------------------------------------------------------------
// tf32 helpers (portable sm_80+ -- NO 'a'-suffix features)
// ---------------------------------------------------------------------------
__device__ __forceinline__ uint32_t to_tf32(float x) {
    uint32_t r;
    asm("cvt.rna.tf32.f32 %0, %1;" : "=r"(r) : "f"(x));
    return r;
}
__device__ __forceinline__ float tf32f(float x) { return __uint_as_float(to_tf32(x)); }

__device__ __forceinline__ void mma_tf32(float c[4],
                                         uint32_t a0, uint32_t a1, uint32_t a2, uint32_t a3,
                                         uint32_t b0, uint32_t b1) {
    asm volatile(
        "mma.sync.aligned.m16n8k8.row.col.f32.tf32.tf32.f32 "
        "{%0,%1,%2,%3}, {%4,%5,%6,%7}, {%8,%9}, {%0,%1,%2,%3};"
        : "+f"(c[0]), "+f"(c[1]), "+f"(c[2]), "+f"(c[3])
        : "r"(a0), "r"(a1), "r"(a2), "r"(a3), "r"(b0), "r"(b1));
}
__device__ __forceinline__ uint32_t smem_u32(const void* p) {
    uint32_t a;
    asm("{ .reg .u64 t; cvta.to.shared.u64 t, %1; cvt.u32.u64 %0, t; }" : "=r"(a) : "l"(p));
    return a;
}
__device__ __forceinline__ void cpa16(uint32_t dst, const void* src) {
    asm volatile("cp.async.cg.shared.global [%0], [%1], 16;" :: "r"(dst), "l"(src) : "memory");
}
#define CP_COMMIT() asm volatile("cp.async.commit_group;" ::: "memory")
#define CP_WAIT1()  asm volatile("cp.async.wait_group 1;" ::: "memory")
#define CP_WAIT0()  asm volatile("cp.async.wait_group 0;" ::: "memory")

// ---------------------------------------------------------------------------
// Weight packer: fragment-major float4 layout.
// WtP[(((c*9+t)*4+qc)*(Cout/16)+g)*8+r] = {w(m,qc), w(m+8,qc), w(m,qc+4), w(m+8,qc+4)}
//   m = g*16+r;  w(m,k) = w[co=m][ci=c*8+k][tap t]   (tf32-rounded)
// ---------------------------------------------------------------------------
__global__ void wt_pack4(const float* __restrict__ w, float4* __restrict__ out,
                         int Cout, int Cin)
{
    int i = blockIdx.x * 256 + threadIdx.x;
    int total = (Cin >> 3) * 9 * 4 * (Cout >> 4) * 8;
    if (i >= total) return;
    int r  = i & 7;
    int g  = (i >> 3) % (Cout >> 4);
    int rest = (i >> 3) / (Cout >> 4);
    int qc = rest & 3;
    int tc = rest >> 2;
    int t  = tc % 9;
    int c  = tc / 9;
    int m  = g * 16 + r;
    int ci = c * 8;
    float4 v;
    v.x = tf32f(w[((size_t)m       * Cin + ci + qc    ) * 9 + t]);
    v.y = tf32f(w[((size_t)(m + 8) * Cin + ci + qc    ) * 9 + t]);
    v.z = tf32f(w[((size_t)m       * Cin + ci + qc + 4) * 9 + t]);
    v.w = tf32f(w[((size_t)(m + 8) * Cin + ci + qc + 4) * 9 + t]);
    out[i] = v;
}

// ---------------------------------------------------------------------------
// TF32 mma.sync 3x3 SAME conv (refinement, 256x256). Proven R10-R12 path.
// CTA: M=128 Cout x N=256 px (one full image row), cp.async double-buffered.
// ---------------------------------------------------------------------------
#define SXS 264                       // input row stride (floats)
#define SW4 66                        // weight row stride (float4 per (t,qc))
#define STAGE_X (24 * SXS)            // 6336 floats
#define STAGE_W (9 * 4 * SW4 * 4)     // 9504 floats
#define STAGE_F (STAGE_X + STAGE_W)   // 15840 floats
#define CMMA2_SMEM (2 * STAGE_F * 4)  // 126720 B

__device__ __forceinline__ void stage_chunk(
    uint32_t sx_b, uint32_t sw_b, const float* __restrict__ in,
    const float4* __restrict__ WtP, int y, int coTile, int c, int Cout, int tid)
{
#pragma unroll
    for (int it = 0; it < 6; it++) {
        int i = tid + (it << 8);
        int row = i >> 6, seg = i & 63;
        int ky = row >> 3, ci = row & 7;
        int gy = y - 1 + ky;
        if ((unsigned)gy < 256u)
            cpa16(sx_b + (uint32_t)(row * SXS + 4 + seg * 4) * 4,
                  in + ((((size_t)((c << 3) + ci)) << 8) + gy << 8) + seg * 4);
    }
#pragma unroll
    for (int it = 0; it < 9; it++) {
        int i = tid + (it << 8);
        int r = i & 7, gl = (i >> 3) & 7, qc = (i >> 6) & 3, t = i >> 8;
        cpa16(sw_b + (uint32_t)(((t * 4 + qc) * SW4 + gl * 8 + r) * 16),
              WtP + ((((size_t)(c * 9 + t) * 4 + qc) * (Cout >> 4) + (coTile >> 4) + gl) * 8 + r));
    }
}

__global__ __launch_bounds__(256, 1) void conv3x3_mma2(
    const float* __restrict__ in, const float4* __restrict__ WtP,
    const float* __restrict__ bias, float* __restrict__ out,
    int Cin, int Cout)
{
    extern __shared__ float sm[];
    const uint32_t base_b = smem_u32(sm);

    const int y      = blockIdx.x;
    const int coTile = blockIdx.y << 7;
    const int tid  = threadIdx.x;
    const int lane = tid & 31;
    const int wid  = tid >> 5;
    const int gBase = (wid >> 2) << 2;
    const int nBase = (wid & 3) << 6;
    const int qr = lane >> 2;
    const int qc = lane & 3;

    for (int i = tid; i < 2 * STAGE_X / 4; i += 256) {
        uint32_t a = base_b + ((i >= STAGE_X / 4)
                     ? (uint32_t)(STAGE_F + (i - STAGE_X / 4) * 4) * 4
                     : (uint32_t)(i * 4) * 4);
        asm volatile("st.shared.v4.u32 [%0], {%1,%1,%1,%1};" :: "r"(a), "r"(0u));
    }
    __syncthreads();

    const int nch = Cin >> 3;
    stage_chunk(base_b, base_b + STAGE_X * 4, in, WtP, y, coTile, 0, Cout, tid);
    CP_COMMIT();

    float acc[4][8][4] = {};

    for (int c = 0; c < nch; c++) {
        const int s = c & 1;
        if (c + 1 < nch) {
            uint32_t sb = base_b + (uint32_t)((s ^ 1) * STAGE_F) * 4;
            stage_chunk(sb, sb + STAGE_X * 4, in, WtP, y, coTile, c + 1, Cout, tid);
            CP_COMMIT();
            CP_WAIT1();
        } else {
            CP_WAIT0();
        }
        __syncthreads();

        const float* sX = sm + s * STAGE_F;
        const float* sW = sX + STAGE_X;

#pragma unroll
        for (int ky = 0; ky < 3; ky++) {
#pragma unroll
            for (int kx = 0; kx < 3; kx++) {
                const int t = ky * 3 + kx;
                uint32_t A[4][4];
#pragma unroll
                for (int mf = 0; mf < 4; mf++) {
                    float4 av = *(const float4*)&sW[((t * 4 + qc) * SW4
                                                     + (gBase + mf) * 8 + qr) << 2];
                    A[mf][0] = __float_as_uint(av.x);
                    A[mf][1] = __float_as_uint(av.y);
                    A[mf][2] = __float_as_uint(av.z);
                    A[mf][3] = __float_as_uint(av.w);
                }
#pragma unroll
                for (int nf = 0; nf < 8; nf++) {
                    int col = nBase + nf * 8 + qr + kx + 3;
                    uint32_t b0 = __float_as_uint(sX[(ky * 8 + qc)     * SXS + col]);
                    uint32_t b1 = __float_as_uint(sX[(ky * 8 + qc + 4) * SXS + col]);
#pragma unroll
                    for (int mf = 0; mf < 4; mf++)
                        mma_tf32(acc[mf][nf], A[mf][0], A[mf][1], A[mf][2], A[mf][3], b0, b1);
                }
            }
        }
        __syncthreads();
    }

#pragma unroll
    for (int mf = 0; mf < 4; mf++) {
        int co = coTile + (gBase + mf) * 16 + qr;
        float bv0 = bias[co], bv1 = bias[co + 8];
#pragma unroll
        for (int nf = 0; nf < 8; nf++) {
            int px = nBase + nf * 8 + 2 * qc;
            float2 v0 = { fmaxf(acc[mf][nf][0] + bv0, 0.f),
                          fmaxf(acc[mf][nf][1] + bv0, 0.f) };
            float2 v1 = { fmaxf(acc[mf][nf][2] + bv1, 0.f),
                          fmaxf(acc[mf][nf][3] + bv1, 0.f) };
            *(float2*)&out[((((size_t)co       << 8) + y) << 8) + px] = v0;
            *(float2*)&out[((((size_t)(co + 8) << 8) + y) << 8) + px] = v1;
        }
    }
}

// ---------------------------------------------------------------------------
// Plain-tf32 conv for the classification branch (128x128 images).
// CTA: M=128 Cout x N=256 px = TWO image rows. Smaller smem (110.8 KB total)
// -> chance of 2 CTAs/SM residency on top of the proven pipeline.
// ---------------------------------------------------------------------------
#define SX3 136
#define STAGE_X3 (32 * SX3)               // 4352 floats
#define STAGE_W3 (9 * 4 * SW4 * 4)        // 9504 floats
#define STAGE_CF (STAGE_X3 + STAGE_W3)    // 13856 floats
#define CCLS_SMEM (2 * STAGE_CF * 4)      // 110848 B

__device__ __forceinline__ void stage_cls(
    uint32_t st_b, const float* __restrict__ in, const float4* __restrict__ WtP,
    int y0, int coTile, int c, int Cout, int tid)
{
    const uint32_t xb = st_b;
    const uint32_t wb = st_b + STAGE_X3 * 4;
#pragma unroll
    for (int it = 0; it < 4; it++) {
        int i = tid + (it << 8);
        int row = i >> 5, seg = i & 31;
        int ky4 = row >> 3, ci = row & 7;
        int gy = y0 - 1 + ky4;
        if ((unsigned)gy < 128u)
            cpa16(xb + (uint32_t)(row * SX3 + 4 + seg * 4) * 4,
                  in + (size_t)((c << 3) + ci) * 16384 + gy * 128 + seg * 4);
    }
#pragma unroll
    for (int it = 0; it < 9; it++) {
        int i = tid + (it << 8);
        int r = i & 7, gl = (i >> 3) & 7, qc = (i >> 6) & 3, t = i >> 8;
        cpa16(wb + (uint32_t)(((t * 4 + qc) * SW4 + gl * 8 + r) * 16),
              WtP + ((((size_t)(c * 9 + t) * 4 + qc) * (Cout >> 4) + (coTile >> 4) + gl) * 8 + r));
    }
}

__global__ __launch_bounds__(256) void conv3x3_cls(
    const float* __restrict__ in, const float4* __restrict__ WtP,
    const float* __restrict__ bias, float* __restrict__ out,
    int Cin, int Cout)
{
    extern __shared__ float smc[];
    const uint32_t base_b = smem_u32(smc);

    const int y0     = blockIdx.x << 1;
    const int coTile = blockIdx.y << 7;
    const int tid  = threadIdx.x;
    const int lane = tid & 31;
    const int wid  = tid >> 5;
    const int gBase = (wid >> 2) << 2;
    const int nBase = (wid & 3) << 6;
    const int qr = lane >> 2;
    const int qc = lane & 3;

    // pre-zero X area of both stages (halo cols + OOB rows)
    for (int i = tid; i < 2 * STAGE_X3 / 4; i += 256) {
        uint32_t a = base_b + ((i >= STAGE_X3 / 4)
                     ? (uint32_t)(STAGE_CF + (i - STAGE_X3 / 4) * 4) * 4
                     : (uint32_t)(i * 4) * 4);
        asm volatile("st.shared.v4.u32 [%0], {%1,%1,%1,%1};" :: "r"(a), "r"(0u));
    }
    __syncthreads();

    const int nch = Cin >> 3;
    stage_cls(base_b, in, WtP, y0, coTile, 0, Cout, tid);
    CP_COMMIT();

    float acc[4][8][4] = {};

    for (int c = 0; c < nch; c++) {
        const int s = c & 1;
        if (c + 1 < nch) {
            stage_cls(base_b + (uint32_t)((s ^ 1) * STAGE_CF) * 4,
                      in, WtP, y0, coTile, c + 1, Cout, tid);
            CP_COMMIT();
            CP_WAIT1();
        } else {
            CP_WAIT0();
        }
        __syncthreads();

        const float* sX = smc + s * STAGE_CF;
        const float* sW = sX + STAGE_X3;

#pragma unroll
        for (int ky = 0; ky < 3; ky++) {
#pragma unroll
            for (int kx = 0; kx < 3; kx++) {
                const int t = ky * 3 + kx;
                uint32_t A[4][4];
#pragma unroll
                for (int mf = 0; mf < 4; mf++) {
                    float4 av = *(const float4*)&sW[((t * 4 + qc) * SW4
                                                     + (gBase + mf) * 8 + qr) << 2];
                    A[mf][0] = __float_as_uint(av.x);
                    A[mf][1] = __float_as_uint(av.y);
                    A[mf][2] = __float_as_uint(av.z);
                    A[mf][3] = __float_as_uint(av.w);
                }
#pragma unroll
                for (int nf = 0; nf < 8; nf++) {
                    int col = nBase + nf * 8 + qr;
                    int r = col >> 7, x = col & 127;
                    int rowb = (r + ky) * 8;
                    uint32_t b0 = __float_as_uint(sX[(rowb + qc)     * SX3 + x + kx + 3]);
                    uint32_t b1 = __float_as_uint(sX[(rowb + qc + 4) * SX3 + x + kx + 3]);
#pragma unroll
                    for (int mf = 0; mf < 4; mf++)
                        mma_tf32(acc[mf][nf], A[mf][0], A[mf][1], A[mf][2], A[mf][3], b0, b1);
                }
            }
        }
        __syncthreads();
    }

#pragma unroll
    for (int mf = 0; mf < 4; mf++) {
        int co = coTile + (gBase + mf) * 16 + qr;
        float bv0 = bias[co], bv1 = bias[co + 8];
#pragma unroll
        for (int nf = 0; nf < 8; nf++) {
            int n = nBase + nf * 8 + 2 * qc;
            int r = n >> 7, x = n & 127;
            size_t i0 = (size_t)co * 16384 + (y0 + r) * 128 + x;
            size_t i1 = (size_t)(co + 8) * 16384 + (y0 + r) * 128 + x;
            float2 v0 = { fmaxf(acc[mf][nf][0] + bv0, 0.f),
                          fmaxf(acc[mf][nf][1] + bv0, 0.f) };
            float2 v1 = { fmaxf(acc[mf][nf][2] + bv1, 0.f),
                          fmaxf(acc[mf][nf][3] + bv1, 0.f) };
            *(float2*)&out[i0] = v0;
            *(float2*)&out[i1] = v1;
        }
    }
}

// ---------------------------------------------------------------------------
// Heads / transforms
// ---------------------------------------------------------------------------
__global__ void cls_kernel(const float* __restrict__ h, const float* __restrict__ w,
                           const float* __restrict__ b, float* __restrict__ cls,
                           float* __restrict__ bin, int HW)
{
    int p = blockIdx.x * 256 + threadIdx.x;
    if (p >= HW) return;
    float s = b[0];
#pragma unroll 8
    for (int c = 0; c < 256; c++) s = fmaf(w[c], h[(size_t)c * HW + p], s);
    float sig = 1.f / (1.f + expf(-s));
    cls[p] = sig;
    bin[p] = (sig >= 0.5f) ? 1.f : 0.f;
}

__global__ void field_kernel(const float* __restrict__ r, const float* __restrict__ w,
                             const float* __restrict__ b, float* __restrict__ field,
                             int HW)
{
    int p = blockIdx.x * 256 + threadIdx.x;
    if (p >= HW) return;
    float s0 = b[0], s1 = b[1];
#pragma unroll 8
    for (int c = 0; c < 256; c++) {
        float v = r[(size_t)c * HW + p];
        s0 = fmaf(w[c], v, s0);
        s1 = fmaf(w[256 + c], v, s1);
    }
    field[p] = s0;
    field[HW + p] = s1;
}

__global__ void upsample_kernel(const float* __restrict__ bin, float* __restrict__ out)
{
    int idx = blockIdx.x * 256 + threadIdx.x;
    if (idx >= 256 * 256) return;
    int Y = idx >> 8, X = idx & 255;
    const float step = 127.0f / 255.0f;
    float ys = (float)Y * step, xs = (float)X * step;
    int y0 = (int)floorf(ys); int y1 = min(y0 + 1, 127);
    int x0 = (int)floorf(xs); int x1 = min(x0 + 1, 127);
    float wy = ys - (float)y0, wx = xs - (float)x0;
    float v00 = bin[y0 * 128 + x0], v01 = bin[y0 * 128 + x1];
    float v10 = bin[y1 * 128 + x0], v11 = bin[y1 * 128 + x1];
    out[idx] = rintf((v00 * (1.f - wx) + v01 * wx) * (1.f - wy)
                   + (v10 * (1.f - wx) + v11 * wx) * wy);
}

__global__ void contour_kernel(const float* __restrict__ cc,
                               const float* __restrict__ field,
                               const int* __restrict__ pnum_iter,
                               float* __restrict__ out, int npts)
{
    int i = blockIdx.x * 256 + threadIdx.x;
    if (i >= npts) return;
    const int W = 256, H = 256;
    float x = cc[2 * i], y = cc[2 * i + 1];
    int n = pnum_iter[0];
    for (int t = 0; t < n; t++) {
        float xc = fminf(fmaxf(x, 0.f), 255.f);
        float yc = fminf(fmaxf(y, 0.f), 255.f);
        int x0 = (int)floorf(xc); int x1 = min(x0 + 1, W - 1);
        int y0 = (int)floorf(yc); int y1 = min(y0 + 1, H - 1);
        float wx = xc - (float)x0, wy = yc - (float)y0;
        float ox, oy;
        {
            const float* f = field;
            float v00 = f[y0 * W + x0], v01 = f[y0 * W + x1];
            float v10 = f[y1 * W + x0], v11 = f[y1 * W + x1];
            ox = (v00 * (1.f - wx) + v01 * wx) * (1.f - wy)
               + (v10 * (1.f - wx) + v11 * wx) * wy;
        }
        {
            const float* f = field + H * W;
            float v00 = f[y0 * W + x0], v01 = f[y0 * W + x1];
            float v10 = f[y1 * W + x0], v11 = f[y1 * W + x1];
            oy = (v00 * (1.f - wx) + v01 * wx) * (1.f - wy)
               + (v10 * (1.f - wx) + v11 * wx) * wy;
        }
        x = fminf(fmaxf(x + ox, 0.f), 255.f);
        y = fminf(fmaxf(y + oy, 0.f), 255.f);
    }
    out[2 * i] = x;
    out[2 * i + 1] = y;
}

// ---------------------------------------------------------------------------
extern "C" void kernel_launch(void* const* d_in, const int* in_sizes, int n_in,
                              void* d_out, int out_size)
{
    const float* f1  = (const float*)d_in[0];
    const float* f2  = (const float*)d_in[1];
    const float* cc  = (const float*)d_in[2];
    const float* cw1 = (const float*)d_in[3];
    const float* cb1 = (const float*)d_in[4];
    const float* cw2 = (const float*)d_in[5];
    const float* cb2 = (const float*)d_in[6];
    const float* cw3 = (const float*)d_in[7];
    const float* cb3 = (const float*)d_in[8];
    const float* cw4 = (const float*)d_in[9];
    const float* cb4 = (const float*)d_in[10];
    const float* rw1 = (const float*)d_in[11];
    const float* rb1 = (const float*)d_in[12];
    const float* rw2 = (const float*)d_in[13];
    const float* rb2 = (const float*)d_in[14];
    const float* rw3 = (const float*)d_in[15];
    const float* rb3 = (const float*)d_in[16];
    const float* rw4 = (const float*)d_in[17];
    const float* rb4 = (const float*)d_in[18];
    const int*   pnum = (const int*)d_in[19];

    float* out = (float*)d_out;
    float* out_cls = out;
    float* out_bin = out + 16384;
    float* out_ctr = out + 16384 + 65536;

    float *bufA, *bufB, *Wt1, *Wt2, *Wt3, *CW1, *CW2, *CW3, *field, *bin;
    cudaGetSymbolAddress((void**)&bufA, g_bufA);
    cudaGetSymbolAddress((void**)&bufB, g_bufB);
    cudaGetSymbolAddress((void**)&Wt1,  g_Wt1);
    cudaGetSymbolAddress((void**)&Wt2,  g_Wt2);
    cudaGetSymbolAddress((void**)&Wt3,  g_Wt3);
    cudaGetSymbolAddress((void**)&CW1,  g_CW1);
    cudaGetSymbolAddress((void**)&CW2,  g_CW2);
    cudaGetSymbolAddress((void**)&CW3,  g_CW3);
    cudaGetSymbolAddress((void**)&field, g_field);
    cudaGetSymbolAddress((void**)&bin,  g_bin);

    // cls intermediates carved from bufA/bufB (consumed before refinement writes)
    float* h1 = bufA;                       // 1024*16384 = 16.7M floats
    float* h2 = bufB;                       // 512*16384
    float* c3 = bufA + 16777216u;           // 256*16384

    cudaFuncSetAttribute(conv3x3_mma2, cudaFuncAttributeMaxDynamicSharedMemorySize, CMMA2_SMEM);
    cudaFuncSetAttribute(conv3x3_cls,  cudaFuncAttributeMaxDynamicSharedMemorySize, CCLS_SMEM);

    // ---- weight packing (independent prep) ----
    {
        int t1 = (512 >> 3) * 9 * 4 * (1024 >> 4) * 8;
        int t2 = (1024 >> 3) * 9 * 4 * (512 >> 4) * 8;
        int t3 = (512 >> 3) * 9 * 4 * (256 >> 4) * 8;
        wt_pack4<<<(t1 + 255) / 256, 256>>>(rw1, (float4*)Wt1, 1024, 512);
        wt_pack4<<<(t2 + 255) / 256, 256>>>(rw2, (float4*)Wt2, 512, 1024);
        wt_pack4<<<(t3 + 255) / 256, 256>>>(rw3, (float4*)Wt3, 256, 512);
        wt_pack4<<<(t1 + 255) / 256, 256>>>(cw1, (float4*)CW1, 1024, 512);
        wt_pack4<<<(t2 + 255) / 256, 256>>>(cw2, (float4*)CW2, 512, 1024);
        wt_pack4<<<(t3 + 255) / 256, 256>>>(cw3, (float4*)CW3, 256, 512);
    }

    // ---- classification branch (plain tf32 mma.sync) ----
    conv3x3_cls<<<dim3(64, 8), 256, CCLS_SMEM>>>(f2, (const float4*)CW1, cb1, h1, 512, 1024);
    conv3x3_cls<<<dim3(64, 4), 256, CCLS_SMEM>>>(h1, (const float4*)CW2, cb2, h2, 1024, 512);
    conv3x3_cls<<<dim3(64, 2), 256, CCLS_SMEM>>>(h2, (const float4*)CW3, cb3, c3, 512, 256);
    cls_kernel<<<64, 256>>>(c3, cw4, cb4, out_cls, bin, 16384);
    upsample_kernel<<<256, 256>>>(bin, out_bin);

    // ---- refinement branch (tf32 mma.sync, pipelined) ----
    conv3x3_mma2<<<dim3(256, 8), 256, CMMA2_SMEM>>>(f1,   (const float4*)Wt1, rb1, bufA, 512, 1024);
    conv3x3_mma2<<<dim3(256, 4), 256, CMMA2_SMEM>>>(bufA, (const float4*)Wt2, rb2, bufB, 1024, 512);
    conv3x3_mma2<<<dim3(256, 2), 256, CMMA2_SMEM>>>(bufB, (const float4*)Wt3, rb3, bufA, 512, 256);
    field_kernel<<<256, 256>>>(bufA, rw4, rb4, field, 65536);
    contour_kernel<<<(38400 + 255) / 256, 256>>>(cc, field, pnum, out_ctr, 38400);
}

// round 14
// speedup vs baseline: 9.1943x; 1.6141x over previous
#include <cuda_runtime.h>
#include <cuda_bf16.h>
#include <math.h>
#include <stdint.h>

// ---------------------------------------------------------------------------
// Scratch (device globals -- no runtime allocation allowed)
// ---------------------------------------------------------------------------
__device__ float g_bufA[1024u * 256u * 256u];   // 256 MiB
__device__ float g_bufB[512u * 256u * 256u];    // 128 MiB
__device__ float g_Wt1[1024u * 512u * 9u];      // refinement packed bf16 weights
__device__ float g_Wt2[512u * 1024u * 9u];
__device__ float g_Wt3[256u * 512u * 9u];
__device__ float g_CW1[1024u * 512u * 9u];      // cls packed tf32 weights
__device__ float g_CW2[512u * 1024u * 9u];
__device__ float g_CW3[256u * 512u * 9u];
__device__ float g_field[2 * 256 * 256];
__device__ float g_bin[128 * 128];

// ---------------------------------------------------------------------------
// Helpers (portable sm_80+ -- NO 'a'-suffix features)
// ---------------------------------------------------------------------------
__device__ __forceinline__ uint32_t to_tf32(float x) {
    uint32_t r;
    asm("cvt.rna.tf32.f32 %0, %1;" : "=r"(r) : "f"(x));
    return r;
}
__device__ __forceinline__ float tf32f(float x) { return __uint_as_float(to_tf32(x)); }

__device__ __forceinline__ uint32_t pk_bf2(float a, float b) {
    unsigned short lo = __bfloat16_as_ushort(__float2bfloat16_rn(a));
    unsigned short hi = __bfloat16_as_ushort(__float2bfloat16_rn(b));
    return ((uint32_t)hi << 16) | lo;
}
__device__ __forceinline__ float bf_lo(uint32_t u) {
    return __bfloat162float(__ushort_as_bfloat16((unsigned short)(u & 0xFFFFu)));
}
__device__ __forceinline__ float bf_hi(uint32_t u) {
    return __bfloat162float(__ushort_as_bfloat16((unsigned short)(u >> 16)));
}

__device__ __forceinline__ void mma_tf32(float c[4],
                                         uint32_t a0, uint32_t a1, uint32_t a2, uint32_t a3,
                                         uint32_t b0, uint32_t b1) {
    asm volatile(
        "mma.sync.aligned.m16n8k8.row.col.f32.tf32.tf32.f32 "
        "{%0,%1,%2,%3}, {%4,%5,%6,%7}, {%8,%9}, {%0,%1,%2,%3};"
        : "+f"(c[0]), "+f"(c[1]), "+f"(c[2]), "+f"(c[3])
        : "r"(a0), "r"(a1), "r"(a2), "r"(a3), "r"(b0), "r"(b1));
}
__device__ __forceinline__ void mma_bf16(float c[4],
                                         uint32_t a0, uint32_t a1, uint32_t a2, uint32_t a3,
                                         uint32_t b0, uint32_t b1) {
    asm volatile(
        "mma.sync.aligned.m16n8k16.row.col.f32.bf16.bf16.f32 "
        "{%0,%1,%2,%3}, {%4,%5,%6,%7}, {%8,%9}, {%0,%1,%2,%3};"
        : "+f"(c[0]), "+f"(c[1]), "+f"(c[2]), "+f"(c[3])
        : "r"(a0), "r"(a1), "r"(a2), "r"(a3), "r"(b0), "r"(b1));
}
__device__ __forceinline__ uint32_t smem_u32(const void* p) {
    uint32_t a;
    asm("{ .reg .u64 t; cvta.to.shared.u64 t, %1; cvt.u32.u64 %0, t; }" : "=r"(a) : "l"(p));
    return a;
}
__device__ __forceinline__ void cpa16(uint32_t dst, const void* src) {
    asm volatile("cp.async.cg.shared.global [%0], [%1], 16;" :: "r"(dst), "l"(src) : "memory");
}
#define CP_COMMIT() asm volatile("cp.async.commit_group;" ::: "memory")
#define CP_WAIT1()  asm volatile("cp.async.wait_group 1;" ::: "memory")
#define CP_WAIT0()  asm volatile("cp.async.wait_group 0;" ::: "memory")

// ---------------------------------------------------------------------------
// Weight packers
// ---------------------------------------------------------------------------
// tf32 (cls): WtP[(((c*9+t)*4+qc)*(Cout/16)+g)*8+r] -> one float4 = A frag
__global__ void wt_pack4(const float* __restrict__ w, float4* __restrict__ out,
                         int Cout, int Cin)
{
    int i = blockIdx.x * 256 + threadIdx.x;
    int total = (Cin >> 3) * 9 * 4 * (Cout >> 4) * 8;
    if (i >= total) return;
    int r  = i & 7;
    int g  = (i >> 3) % (Cout >> 4);
    int rest = (i >> 3) / (Cout >> 4);
    int qc = rest & 3;
    int tc = rest >> 2;
    int t  = tc % 9;
    int c  = tc / 9;
    int m  = g * 16 + r;
    int ci = c * 8;
    float4 v;
    v.x = tf32f(w[((size_t)m       * Cin + ci + qc    ) * 9 + t]);
    v.y = tf32f(w[((size_t)(m + 8) * Cin + ci + qc    ) * 9 + t]);
    v.z = tf32f(w[((size_t)m       * Cin + ci + qc + 4) * 9 + t]);
    v.w = tf32f(w[((size_t)(m + 8) * Cin + ci + qc + 4) * 9 + t]);
    out[i] = v;
}

// bf16 (refinement): 16-channel chunks; k-slot 2p -> ch base+p, 2p+1 -> base+p+8
__global__ void wt_pack_bf16(const float* __restrict__ w, float4* __restrict__ out,
                             int Cout, int Cin)
{
    int i = blockIdx.x * 256 + threadIdx.x;
    int total = (Cin >> 4) * 9 * 4 * (Cout >> 4) * 8;
    if (i >= total) return;
    int r  = i & 7;
    int g  = (i >> 3) % (Cout >> 4);
    int rest = (i >> 3) / (Cout >> 4);
    int qc = rest & 3;
    int tc = rest >> 2;
    int t  = tc % 9;
    int c  = tc / 9;
    int m  = g * 16 + r;
    int base = c * 16;
#define WV(mm, ci) w[((size_t)(mm) * Cin + (ci)) * 9 + t]
    uint32_t u0 = pk_bf2(WV(m,     base + qc),     WV(m,     base + qc + 8));
    uint32_t u1 = pk_bf2(WV(m + 8, base + qc),     WV(m + 8, base + qc + 8));
    uint32_t u2 = pk_bf2(WV(m,     base + qc + 4), WV(m,     base + qc + 12));
    uint32_t u3 = pk_bf2(WV(m + 8, base + qc + 4), WV(m + 8, base + qc + 12));
#undef WV
    out[i] = make_float4(__uint_as_float(u0), __uint_as_float(u1),
                         __uint_as_float(u2), __uint_as_float(u3));
}

// f1 (NCHW fp32, 512x256x256) -> pair-interleaved bf16 planes (256 cp rows)
__global__ void to_bf16_pairs(const float* __restrict__ in, uint32_t* __restrict__ out)
{
    int i = blockIdx.x * 256 + threadIdx.x;
    if (i >= 256 * 65536) return;
    int cp = i >> 16, pix = i & 65535;
    int c_lo = ((cp >> 3) << 4) + (cp & 7);
    out[i] = pk_bf2(in[((size_t)c_lo << 16) + pix],
                    in[((size_t)(c_lo + 8) << 16) + pix]);
}

// ---------------------------------------------------------------------------
// BF16 mma.sync 3x3 SAME conv (refinement, 256x256), m16n8k16.
// CTA: M=128 Cout x N=256 px (one full image row), cp.async double-buffered.
// Activations: pair-interleaved half2 planes (pair p = channels base+p, base+p+8).
// ---------------------------------------------------------------------------
#define SXB 264                        // X row stride (half2 units)
#define SWB4 66                        // W row stride (float4 per (t,qc))
#define STAGE_XB (24 * SXB)            // 6336 uints (25344 B)
#define STAGE_WB (9 * 4 * SWB4 * 4)    // 9504 uints (38016 B)
#define STAGE_FB (STAGE_XB + STAGE_WB) // 15840 uints
#define CBF_SMEM (2 * STAGE_FB * 4)    // 126720 B

__device__ __forceinline__ void stage_bf(
    uint32_t sx_b, uint32_t sw_b, const uint32_t* __restrict__ in,
    const float4* __restrict__ WtP, int y, int coTile, int c, int Cout, int tid)
{
    // X: 24 rows (3 ky x 8 cp) x 64 segs of 16B
#pragma unroll
    for (int it = 0; it < 6; it++) {
        int i = tid + (it << 8);
        int row = i >> 6, seg = i & 63;
        int ky = row >> 3, cpl = row & 7;
        int gy = y - 1 + ky;
        if ((unsigned)gy < 256u)
            cpa16(sx_b + (uint32_t)(row * SXB + 4 + seg * 4) * 4,
                  in + (((size_t)(c * 8 + cpl) * 256 + gy) * 256 + seg * 4));
    }
    // W: 2304 float4
#pragma unroll
    for (int it = 0; it < 9; it++) {
        int i = tid + (it << 8);
        int r = i & 7, gl = (i >> 3) & 7, qc = (i >> 6) & 3, t = i >> 8;
        cpa16(sw_b + (uint32_t)(((t * 4 + qc) * SWB4 + gl * 8 + r) * 16),
              WtP + ((((size_t)(c * 9 + t) * 4 + qc) * (Cout >> 4) + (coTile >> 4) + gl) * 8 + r));
    }
}

__global__ __launch_bounds__(256, 1) void conv3x3_bf(
    const uint32_t* __restrict__ in, const float4* __restrict__ WtP,
    const float* __restrict__ bias, uint32_t* __restrict__ out,
    int Cin, int Cout)
{
    extern __shared__ uint32_t smb[];
    const uint32_t base_b = smem_u32(smb);

    const int y      = blockIdx.x;
    const int coTile = blockIdx.y << 7;
    const int tid  = threadIdx.x;
    const int lane = tid & 31;
    const int wid  = tid >> 5;
    const int gBase = (wid >> 2) << 2;
    const int nBase = (wid & 3) << 6;
    const int qr = lane >> 2;
    const int qc = lane & 3;

    // pre-zero X areas of both stages (halo cols + OOB ky rows)
    for (int i = tid; i < 2 * STAGE_XB / 4; i += 256) {
        uint32_t a = base_b + ((i >= STAGE_XB / 4)
                     ? (uint32_t)(STAGE_FB + (i - STAGE_XB / 4) * 4) * 4
                     : (uint32_t)(i * 4) * 4);
        asm volatile("st.shared.v4.u32 [%0], {%1,%1,%1,%1};" :: "r"(a), "r"(0u));
    }
    __syncthreads();

    const int nch = Cin >> 4;
    stage_bf(base_b, base_b + STAGE_XB * 4, in, WtP, y, coTile, 0, Cout, tid);
    CP_COMMIT();

    float acc[4][8][4] = {};

    for (int c = 0; c < nch; c++) {
        const int s = c & 1;
        if (c + 1 < nch) {
            uint32_t sb = base_b + (uint32_t)((s ^ 1) * STAGE_FB) * 4;
            stage_bf(sb, sb + STAGE_XB * 4, in, WtP, y, coTile, c + 1, Cout, tid);
            CP_COMMIT();
            CP_WAIT1();
        } else {
            CP_WAIT0();
        }
        __syncthreads();

        const uint32_t* sX = smb + s * STAGE_FB;
        const uint32_t* sW = sX + STAGE_XB;

#pragma unroll
        for (int ky = 0; ky < 3; ky++) {
#pragma unroll
            for (int kx = 0; kx < 3; kx++) {
                const int t = ky * 3 + kx;
                uint32_t A[4][4];
#pragma unroll
                for (int mf = 0; mf < 4; mf++) {
                    float4 av = *(const float4*)&sW[((t * 4 + qc) * SWB4
                                                     + (gBase + mf) * 8 + qr) << 2];
                    A[mf][0] = __float_as_uint(av.x);
                    A[mf][1] = __float_as_uint(av.y);
                    A[mf][2] = __float_as_uint(av.z);
                    A[mf][3] = __float_as_uint(av.w);
                }
#pragma unroll
                for (int nf = 0; nf < 8; nf++) {
                    int col = nBase + nf * 8 + qr + kx + 3;
                    uint32_t b0 = sX[(ky * 8 + qc)     * SXB + col];
                    uint32_t b1 = sX[(ky * 8 + qc + 4) * SXB + col];
#pragma unroll
                    for (int mf = 0; mf < 4; mf++)
                        mma_bf16(acc[mf][nf], A[mf][0], A[mf][1], A[mf][2], A[mf][3], b0, b1);
                }
            }
        }
        __syncthreads();
    }

    // epilogue: bias + ReLU -> packed bf16 pair planes (pair = co, co+8)
#pragma unroll
    for (int mf = 0; mf < 4; mf++) {
        int co = coTile + (gBase + mf) * 16 + qr;
        int cpg = ((co >> 4) << 3) + (co & 7);
        float bv0 = bias[co], bv1 = bias[co + 8];
#pragma unroll
        for (int nf = 0; nf < 8; nf++) {
            int px = nBase + nf * 8 + 2 * qc;
            uint32_t p0 = pk_bf2(fmaxf(acc[mf][nf][0] + bv0, 0.f),
                                 fmaxf(acc[mf][nf][2] + bv1, 0.f));
            uint32_t p1 = pk_bf2(fmaxf(acc[mf][nf][1] + bv0, 0.f),
                                 fmaxf(acc[mf][nf][3] + bv1, 0.f));
            uint2 v = { p0, p1 };
            *(uint2*)&out[((size_t)cpg << 16) + (y << 8) + px] = v;
        }
    }
}

// ---------------------------------------------------------------------------
// Plain-tf32 conv for the classification branch (128x128 images). Proven R13.
// ---------------------------------------------------------------------------
#define SW4 66
#define SX3 136
#define STAGE_X3 (32 * SX3)               // 4352 floats
#define STAGE_W3 (9 * 4 * SW4 * 4)        // 9504 floats
#define STAGE_CF (STAGE_X3 + STAGE_W3)    // 13856 floats
#define CCLS_SMEM (2 * STAGE_CF * 4)      // 110848 B

__device__ __forceinline__ void stage_cls(
    uint32_t st_b, const float* __restrict__ in, const float4* __restrict__ WtP,
    int y0, int coTile, int c, int Cout, int tid)
{
    const uint32_t xb = st_b;
    const uint32_t wb = st_b + STAGE_X3 * 4;
#pragma unroll
    for (int it = 0; it < 4; it++) {
        int i = tid + (it << 8);
        int row = i >> 5, seg = i & 31;
        int ky4 = row >> 3, ci = row & 7;
        int gy = y0 - 1 + ky4;
        if ((unsigned)gy < 128u)
            cpa16(xb + (uint32_t)(row * SX3 + 4 + seg * 4) * 4,
                  in + (size_t)((c << 3) + ci) * 16384 + gy * 128 + seg * 4);
    }
#pragma unroll
    for (int it = 0; it < 9; it++) {
        int i = tid + (it << 8);
        int r = i & 7, gl = (i >> 3) & 7, qc = (i >> 6) & 3, t = i >> 8;
        cpa16(wb + (uint32_t)(((t * 4 + qc) * SW4 + gl * 8 + r) * 16),
              WtP + ((((size_t)(c * 9 + t) * 4 + qc) * (Cout >> 4) + (coTile >> 4) + gl) * 8 + r));
    }
}

__global__ __launch_bounds__(256) void conv3x3_cls(
    const float* __restrict__ in, const float4* __restrict__ WtP,
    const float* __restrict__ bias, float* __restrict__ out,
    int Cin, int Cout)
{
    extern __shared__ uint32_t smcu[];
    float* smc = (float*)smcu;
    const uint32_t base_b = smem_u32(smc);

    const int y0     = blockIdx.x << 1;
    const int coTile = blockIdx.y << 7;
    const int tid  = threadIdx.x;
    const int lane = tid & 31;
    const int wid  = tid >> 5;
    const int gBase = (wid >> 2) << 2;
    const int nBase = (wid & 3) << 6;
    const int qr = lane >> 2;
    const int qc = lane & 3;

    for (int i = tid; i < 2 * STAGE_X3 / 4; i += 256) {
        uint32_t a = base_b + ((i >= STAGE_X3 / 4)
                     ? (uint32_t)(STAGE_CF + (i - STAGE_X3 / 4) * 4) * 4
                     : (uint32_t)(i * 4) * 4);
        asm volatile("st.shared.v4.u32 [%0], {%1,%1,%1,%1};" :: "r"(a), "r"(0u));
    }
    __syncthreads();

    const int nch = Cin >> 3;
    stage_cls(base_b, in, WtP, y0, coTile, 0, Cout, tid);
    CP_COMMIT();

    float acc[4][8][4] = {};

    for (int c = 0; c < nch; c++) {
        const int s = c & 1;
        if (c + 1 < nch) {
            stage_cls(base_b + (uint32_t)((s ^ 1) * STAGE_CF) * 4,
                      in, WtP, y0, coTile, c + 1, Cout, tid);
            CP_COMMIT();
            CP_WAIT1();
        } else {
            CP_WAIT0();
        }
        __syncthreads();

        const float* sX = smc + s * STAGE_CF;
        const float* sW = sX + STAGE_X3;

#pragma unroll
        for (int ky = 0; ky < 3; ky++) {
#pragma unroll
            for (int kx = 0; kx < 3; kx++) {
                const int t = ky * 3 + kx;
                uint32_t A[4][4];
#pragma unroll
                for (int mf = 0; mf < 4; mf++) {
                    float4 av = *(const float4*)&sW[((t * 4 + qc) * SW4
                                                     + (gBase + mf) * 8 + qr) << 2];
                    A[mf][0] = __float_as_uint(av.x);
                    A[mf][1] = __float_as_uint(av.y);
                    A[mf][2] = __float_as_uint(av.z);
                    A[mf][3] = __float_as_uint(av.w);
                }
#pragma unroll
                for (int nf = 0; nf < 8; nf++) {
                    int col = nBase + nf * 8 + qr;
                    int r = col >> 7, x = col & 127;
                    int rowb = (r + ky) * 8;
                    uint32_t b0 = __float_as_uint(sX[(rowb + qc)     * SX3 + x + kx + 3]);
                    uint32_t b1 = __float_as_uint(sX[(rowb + qc + 4) * SX3 + x + kx + 3]);
#pragma unroll
                    for (int mf = 0; mf < 4; mf++)
                        mma_tf32(acc[mf][nf], A[mf][0], A[mf][1], A[mf][2], A[mf][3], b0, b1);
                }
            }
        }
        __syncthreads();
    }

#pragma unroll
    for (int mf = 0; mf < 4; mf++) {
        int co = coTile + (gBase + mf) * 16 + qr;
        float bv0 = bias[co], bv1 = bias[co + 8];
#pragma unroll
        for (int nf = 0; nf < 8; nf++) {
            int n = nBase + nf * 8 + 2 * qc;
            int r = n >> 7, x = n & 127;
            size_t i0 = (size_t)co * 16384 + (y0 + r) * 128 + x;
            size_t i1 = (size_t)(co + 8) * 16384 + (y0 + r) * 128 + x;
            float2 v0 = { fmaxf(acc[mf][nf][0] + bv0, 0.f),
                          fmaxf(acc[mf][nf][1] + bv0, 0.f) };
            float2 v1 = { fmaxf(acc[mf][nf][2] + bv1, 0.f),
                          fmaxf(acc[mf][nf][3] + bv1, 0.f) };
            *(float2*)&out[i0] = v0;
            *(float2*)&out[i1] = v1;
        }
    }
}

// ---------------------------------------------------------------------------
// Heads / transforms
// ---------------------------------------------------------------------------
__global__ void cls_kernel(const float* __restrict__ h, const float* __restrict__ w,
                           const float* __restrict__ b, float* __restrict__ cls,
                           float* __restrict__ bin, int HW)
{
    int p = blockIdx.x * 256 + threadIdx.x;
    if (p >= HW) return;
    float s = b[0];
#pragma unroll 8
    for (int c = 0; c < 256; c++) s = fmaf(w[c], h[(size_t)c * HW + p], s);
    float sig = 1.f / (1.f + expf(-s));
    cls[p] = sig;
    bin[p] = (sig >= 0.5f) ? 1.f : 0.f;
}

// field head reading bf16 pair-interleaved r3 (128 cp rows)
__global__ void field_kernel_bf(const uint32_t* __restrict__ r, const float* __restrict__ w,
                                const float* __restrict__ b, float* __restrict__ field)
{
    int p = blockIdx.x * 256 + threadIdx.x;   // 65536
    float s0 = b[0], s1 = b[1];
#pragma unroll 8
    for (int cp = 0; cp < 128; cp++) {
        uint32_t u = r[((size_t)cp << 16) + p];
        float vlo = bf_lo(u), vhi = bf_hi(u);
        int c_lo = ((cp >> 3) << 4) + (cp & 7);
        s0 = fmaf(w[c_lo], vlo, fmaf(w[c_lo + 8], vhi, s0));
        s1 = fmaf(w[256 + c_lo], vlo, fmaf(w[256 + c_lo + 8], vhi, s1));
    }
    field[p] = s0;
    field[65536 + p] = s1;
}

__global__ void upsample_kernel(const float* __restrict__ bin, float* __restrict__ out)
{
    int idx = blockIdx.x * 256 + threadIdx.x;
    if (idx >= 256 * 256) return;
    int Y = idx >> 8, X = idx & 255;
    const float step = 127.0f / 255.0f;
    float ys = (float)Y * step, xs = (float)X * step;
    int y0 = (int)floorf(ys); int y1 = min(y0 + 1, 127);
    int x0 = (int)floorf(xs); int x1 = min(x0 + 1, 127);
    float wy = ys - (float)y0, wx = xs - (float)x0;
    float v00 = bin[y0 * 128 + x0], v01 = bin[y0 * 128 + x1];
    float v10 = bin[y1 * 128 + x0], v11 = bin[y1 * 128 + x1];
    out[idx] = rintf((v00 * (1.f - wx) + v01 * wx) * (1.f - wy)
                   + (v10 * (1.f - wx) + v11 * wx) * wy);
}

__global__ void contour_kernel(const float* __restrict__ cc,
                               const float* __restrict__ field,
                               const int* __restrict__ pnum_iter,
                               float* __restrict__ out, int npts)
{
    int i = blockIdx.x * 256 + threadIdx.x;
    if (i >= npts) return;
    const int W = 256, H = 256;
    float x = cc[2 * i], y = cc[2 * i + 1];
    int n = pnum_iter[0];
    for (int t = 0; t < n; t++) {
        float xc = fminf(fmaxf(x, 0.f), 255.f);
        float yc = fminf(fmaxf(y, 0.f), 255.f);
        int x0 = (int)floorf(xc); int x1 = min(x0 + 1, W - 1);
        int y0 = (int)floorf(yc); int y1 = min(y0 + 1, H - 1);
        float wx = xc - (float)x0, wy = yc - (float)y0;
        float ox, oy;
        {
            const float* f = field;
            float v00 = f[y0 * W + x0], v01 = f[y0 * W + x1];
            float v10 = f[y1 * W + x0], v11 = f[y1 * W + x1];
            ox = (v00 * (1.f - wx) + v01 * wx) * (1.f - wy)
               + (v10 * (1.f - wx) + v11 * wx) * wy;
        }
        {
            const float* f = field + H * W;
            float v00 = f[y0 * W + x0], v01 = f[y0 * W + x1];
            float v10 = f[y1 * W + x0], v11 = f[y1 * W + x1];
            oy = (v00 * (1.f - wx) + v01 * wx) * (1.f - wy)
               + (v10 * (1.f - wx) + v11 * wx) * wy;
        }
        x = fminf(fmaxf(x + ox, 0.f), 255.f);
        y = fminf(fmaxf(y + oy, 0.f), 255.f);
    }
    out[2 * i] = x;
    out[2 * i + 1] = y;
}

// ---------------------------------------------------------------------------
extern "C" void kernel_launch(void* const* d_in, const int* in_sizes, int n_in,
                              void* d_out, int out_size)
{
    const float* f1  = (const float*)d_in[0];
    const float* f2  = (const float*)d_in[1];
    const float* cc  = (const float*)d_in[2];
    const float* cw1 = (const float*)d_in[3];
    const float* cb1 = (const float*)d_in[4];
    const float* cw2 = (const float*)d_in[5];
    const float* cb2 = (const float*)d_in[6];
    const float* cw3 = (const float*)d_in[7];
    const float* cb3 = (const float*)d_in[8];
    const float* cw4 = (const float*)d_in[9];
    const float* cb4 = (const float*)d_in[10];
    const float* rw1 = (const float*)d_in[11];
    const float* rb1 = (const float*)d_in[12];
    const float* rw2 = (const float*)d_in[13];
    const float* rb2 = (const float*)d_in[14];
    const float* rw3 = (const float*)d_in[15];
    const float* rb3 = (const float*)d_in[16];
    const float* rw4 = (const float*)d_in[17];
    const float* rb4 = (const float*)d_in[18];
    const int*   pnum = (const int*)d_in[19];

    float* out = (float*)d_out;
    float* out_cls = out;
    float* out_bin = out + 16384;
    float* out_ctr = out + 16384 + 65536;

    float *bufA, *bufB, *Wt1, *Wt2, *Wt3, *CW1, *CW2, *CW3, *field, *bin;
    cudaGetSymbolAddress((void**)&bufA, g_bufA);
    cudaGetSymbolAddress((void**)&bufB, g_bufB);
    cudaGetSymbolAddress((void**)&Wt1,  g_Wt1);
    cudaGetSymbolAddress((void**)&Wt2,  g_Wt2);
    cudaGetSymbolAddress((void**)&Wt3,  g_Wt3);
    cudaGetSymbolAddress((void**)&CW1,  g_CW1);
    cudaGetSymbolAddress((void**)&CW2,  g_CW2);
    cudaGetSymbolAddress((void**)&CW3,  g_CW3);
    cudaGetSymbolAddress((void**)&field, g_field);
    cudaGetSymbolAddress((void**)&bin,  g_bin);

    // cls intermediates (fp32): consumed before refinement writes same regions
    float* h1 = bufA;                       // 64 MiB
    float* h2 = bufB;                       // 32 MiB
    float* c3 = bufA + 16777216u;           // 16 MiB at +64 MiB

    // refinement bf16 pair-planes (as uint32 arrays)
    uint32_t* f1bf = (uint32_t*)(bufA + 33554432u);   // +128 MiB, 64 MiB
    uint32_t* r1bf = (uint32_t*)bufA;                 // 128 MiB (after cls done)
    uint32_t* r2bf = (uint32_t*)bufB;                 // 64 MiB (after h2 consumed)
    uint32_t* r3bf = (uint32_t*)(bufB + 16777216u);   // +64 MiB, 32 MiB

    cudaFuncSetAttribute(conv3x3_bf,  cudaFuncAttributeMaxDynamicSharedMemorySize, CBF_SMEM);
    cudaFuncSetAttribute(conv3x3_cls, cudaFuncAttributeMaxDynamicSharedMemorySize, CCLS_SMEM);

    // ---- prep: weight packing + f1 conversion ----
    {
        int b1 = (512 >> 4) * 9 * 4 * (1024 >> 4) * 8;
        int b2 = (1024 >> 4) * 9 * 4 * (512 >> 4) * 8;
        int b3 = (512 >> 4) * 9 * 4 * (256 >> 4) * 8;
        wt_pack_bf16<<<(b1 + 255) / 256, 256>>>(rw1, (float4*)Wt1, 1024, 512);
        wt_pack_bf16<<<(b2 + 255) / 256, 256>>>(rw2, (float4*)Wt2, 512, 1024);
        wt_pack_bf16<<<(b3 + 255) / 256, 256>>>(rw3, (float4*)Wt3, 256, 512);
        int t1 = (512 >> 3) * 9 * 4 * (1024 >> 4) * 8;
        int t2 = (1024 >> 3) * 9 * 4 * (512 >> 4) * 8;
        int t3 = (512 >> 3) * 9 * 4 * (256 >> 4) * 8;
        wt_pack4<<<(t1 + 255) / 256, 256>>>(cw1, (float4*)CW1, 1024, 512);
        wt_pack4<<<(t2 + 255) / 256, 256>>>(cw2, (float4*)CW2, 512, 1024);
        wt_pack4<<<(t3 + 255) / 256, 256>>>(cw3, (float4*)CW3, 256, 512);
        to_bf16_pairs<<<65536, 256>>>(f1, f1bf);
    }

    // ---- classification branch (plain tf32 mma.sync) ----
    conv3x3_cls<<<dim3(64, 8), 256, CCLS_SMEM>>>(f2, (const float4*)CW1, cb1, h1, 512, 1024);
    conv3x3_cls<<<dim3(64, 4), 256, CCLS_SMEM>>>(h1, (const float4*)CW2, cb2, h2, 1024, 512);
    conv3x3_cls<<<dim3(64, 2), 256, CCLS_SMEM>>>(h2, (const float4*)CW3, cb3, c3, 512, 256);
    cls_kernel<<<64, 256>>>(c3, cw4, cb4, out_cls, bin, 16384);
    upsample_kernel<<<256, 256>>>(bin, out_bin);

    // ---- refinement branch (bf16 m16n8k16 mma.sync, pipelined) ----
    conv3x3_bf<<<dim3(256, 8), 256, CBF_SMEM>>>(f1bf, (const float4*)Wt1, rb1, r1bf, 512, 1024);
    conv3x3_bf<<<dim3(256, 4), 256, CBF_SMEM>>>(r1bf, (const float4*)Wt2, rb2, r2bf, 1024, 512);
    conv3x3_bf<<<dim3(256, 2), 256, CBF_SMEM>>>(r2bf, (const float4*)Wt3, rb3, r3bf, 512, 256);
    field_kernel_bf<<<256, 256>>>(r3bf, rw4, rb4, field);
    contour_kernel<<<(38400 + 255) / 256, 256>>>(cc, field, pnum, out_ctr, 38400);
}

// round 15
// speedup vs baseline: 10.9784x; 1.1940x over previous
#include <cuda_runtime.h>
#include <cuda_bf16.h>
#include <cuda_fp16.h>
#include <math.h>
#include <stdint.h>

// ---------------------------------------------------------------------------
// Scratch (device globals -- no runtime allocation allowed)
// ---------------------------------------------------------------------------
__device__ float g_bufA[1024u * 256u * 256u];   // 256 MiB
__device__ float g_bufB[512u * 256u * 256u];    // 128 MiB
__device__ float g_Wt1[1024u * 512u * 9u];      // refinement packed bf16 weights
__device__ float g_Wt2[512u * 1024u * 9u];
__device__ float g_Wt3[256u * 512u * 9u];
__device__ float g_CW1[1024u * 512u * 9u];      // cls packed fp16 weights
__device__ float g_CW2[512u * 1024u * 9u];
__device__ float g_CW3[256u * 512u * 9u];
__device__ float g_field[2 * 256 * 256];
__device__ float g_bin[128 * 128];

// ---------------------------------------------------------------------------
// Helpers (portable sm_80+ -- NO 'a'-suffix features)
// ---------------------------------------------------------------------------
__device__ __forceinline__ uint32_t pk_bf2(float a, float b) {
    unsigned short lo = __bfloat16_as_ushort(__float2bfloat16_rn(a));
    unsigned short hi = __bfloat16_as_ushort(__float2bfloat16_rn(b));
    return ((uint32_t)hi << 16) | lo;
}
__device__ __forceinline__ float bf_lo(uint32_t u) {
    return __bfloat162float(__ushort_as_bfloat16((unsigned short)(u & 0xFFFFu)));
}
__device__ __forceinline__ float bf_hi(uint32_t u) {
    return __bfloat162float(__ushort_as_bfloat16((unsigned short)(u >> 16)));
}
__device__ __forceinline__ uint32_t pk_h2(float a, float b) {
    unsigned short lo = __half_as_ushort(__float2half_rn(a));
    unsigned short hi = __half_as_ushort(__float2half_rn(b));
    return ((uint32_t)hi << 16) | lo;
}
__device__ __forceinline__ float h_lo(uint32_t u) {
    return __half2float(__ushort_as_half((unsigned short)(u & 0xFFFFu)));
}
__device__ __forceinline__ float h_hi(uint32_t u) {
    return __half2float(__ushort_as_half((unsigned short)(u >> 16)));
}

__device__ __forceinline__ void mma_bf16(float c[4],
                                         uint32_t a0, uint32_t a1, uint32_t a2, uint32_t a3,
                                         uint32_t b0, uint32_t b1) {
    asm volatile(
        "mma.sync.aligned.m16n8k16.row.col.f32.bf16.bf16.f32 "
        "{%0,%1,%2,%3}, {%4,%5,%6,%7}, {%8,%9}, {%0,%1,%2,%3};"
        : "+f"(c[0]), "+f"(c[1]), "+f"(c[2]), "+f"(c[3])
        : "r"(a0), "r"(a1), "r"(a2), "r"(a3), "r"(b0), "r"(b1));
}
__device__ __forceinline__ void mma_f16(float c[4],
                                        uint32_t a0, uint32_t a1, uint32_t a2, uint32_t a3,
                                        uint32_t b0, uint32_t b1) {
    asm volatile(
        "mma.sync.aligned.m16n8k16.row.col.f32.f16.f16.f32 "
        "{%0,%1,%2,%3}, {%4,%5,%6,%7}, {%8,%9}, {%0,%1,%2,%3};"
        : "+f"(c[0]), "+f"(c[1]), "+f"(c[2]), "+f"(c[3])
        : "r"(a0), "r"(a1), "r"(a2), "r"(a3), "r"(b0), "r"(b1));
}
__device__ __forceinline__ uint32_t smem_u32(const void* p) {
    uint32_t a;
    asm("{ .reg .u64 t; cvta.to.shared.u64 t, %1; cvt.u32.u64 %0, t; }" : "=r"(a) : "l"(p));
    return a;
}
__device__ __forceinline__ void cpa16(uint32_t dst, const void* src) {
    asm volatile("cp.async.cg.shared.global [%0], [%1], 16;" :: "r"(dst), "l"(src) : "memory");
}
#define CP_COMMIT() asm volatile("cp.async.commit_group;" ::: "memory")
#define CP_WAIT1()  asm volatile("cp.async.wait_group 1;" ::: "memory")
#define CP_WAIT0()  asm volatile("cp.async.wait_group 0;" ::: "memory")

// ---------------------------------------------------------------------------
// Weight packers: 16-ch chunks; k-slot 2p -> ch base+p, 2p+1 -> ch base+p+8.
// One float4 (4 regs) = a thread's whole m16k16 A fragment.
// ---------------------------------------------------------------------------
__global__ void wt_pack_bf16(const float* __restrict__ w, float4* __restrict__ out,
                             int Cout, int Cin)
{
    int i = blockIdx.x * 256 + threadIdx.x;
    int total = (Cin >> 4) * 9 * 4 * (Cout >> 4) * 8;
    if (i >= total) return;
    int r  = i & 7;
    int g  = (i >> 3) % (Cout >> 4);
    int rest = (i >> 3) / (Cout >> 4);
    int qc = rest & 3;
    int tc = rest >> 2;
    int t  = tc % 9;
    int c  = tc / 9;
    int m  = g * 16 + r;
    int base = c * 16;
#define WV(mm, ci) w[((size_t)(mm) * Cin + (ci)) * 9 + t]
    uint32_t u0 = pk_bf2(WV(m,     base + qc),     WV(m,     base + qc + 8));
    uint32_t u1 = pk_bf2(WV(m + 8, base + qc),     WV(m + 8, base + qc + 8));
    uint32_t u2 = pk_bf2(WV(m,     base + qc + 4), WV(m,     base + qc + 12));
    uint32_t u3 = pk_bf2(WV(m + 8, base + qc + 4), WV(m + 8, base + qc + 12));
#undef WV
    out[i] = make_float4(__uint_as_float(u0), __uint_as_float(u1),
                         __uint_as_float(u2), __uint_as_float(u3));
}

__global__ void wt_pack_f16(const float* __restrict__ w, float4* __restrict__ out,
                            int Cout, int Cin)
{
    int i = blockIdx.x * 256 + threadIdx.x;
    int total = (Cin >> 4) * 9 * 4 * (Cout >> 4) * 8;
    if (i >= total) return;
    int r  = i & 7;
    int g  = (i >> 3) % (Cout >> 4);
    int rest = (i >> 3) / (Cout >> 4);
    int qc = rest & 3;
    int tc = rest >> 2;
    int t  = tc % 9;
    int c  = tc / 9;
    int m  = g * 16 + r;
    int base = c * 16;
#define WV(mm, ci) w[((size_t)(mm) * Cin + (ci)) * 9 + t]
    uint32_t u0 = pk_h2(WV(m,     base + qc),     WV(m,     base + qc + 8));
    uint32_t u1 = pk_h2(WV(m + 8, base + qc),     WV(m + 8, base + qc + 8));
    uint32_t u2 = pk_h2(WV(m,     base + qc + 4), WV(m,     base + qc + 12));
    uint32_t u3 = pk_h2(WV(m + 8, base + qc + 4), WV(m + 8, base + qc + 12));
#undef WV
    out[i] = make_float4(__uint_as_float(u0), __uint_as_float(u1),
                         __uint_as_float(u2), __uint_as_float(u3));
}

// f1 (NCHW fp32, 512x256x256) -> pair-interleaved bf16 planes (256 cp rows)
__global__ void to_bf16_pairs(const float* __restrict__ in, uint32_t* __restrict__ out)
{
    int i = blockIdx.x * 256 + threadIdx.x;
    if (i >= 256 * 65536) return;
    int cp = i >> 16, pix = i & 65535;
    int c_lo = ((cp >> 3) << 4) + (cp & 7);
    out[i] = pk_bf2(in[((size_t)c_lo << 16) + pix],
                    in[((size_t)(c_lo + 8) << 16) + pix]);
}

// f2 (NCHW fp32, 512x128x128) -> pair-interleaved fp16 planes (256 cp rows)
__global__ void to_f16_pairs(const float* __restrict__ in, uint32_t* __restrict__ out)
{
    int i = blockIdx.x * 256 + threadIdx.x;
    if (i >= 256 * 16384) return;
    int cp = i >> 14, pix = i & 16383;
    int c_lo = ((cp >> 3) << 4) + (cp & 7);
    out[i] = pk_h2(in[(size_t)c_lo * 16384 + pix],
                   in[(size_t)(c_lo + 8) * 16384 + pix]);
}

// ---------------------------------------------------------------------------
// BF16 mma.sync 3x3 SAME conv (refinement, 256x256), m16n8k16. Proven R14.
// ---------------------------------------------------------------------------
#define SXB 264
#define SWB4 66
#define STAGE_XB (24 * SXB)
#define STAGE_WB (9 * 4 * SWB4 * 4)
#define STAGE_FB (STAGE_XB + STAGE_WB)
#define CBF_SMEM (2 * STAGE_FB * 4)    // 126720 B

__device__ __forceinline__ void stage_bf(
    uint32_t sx_b, uint32_t sw_b, const uint32_t* __restrict__ in,
    const float4* __restrict__ WtP, int y, int coTile, int c, int Cout, int tid)
{
#pragma unroll
    for (int it = 0; it < 6; it++) {
        int i = tid + (it << 8);
        int row = i >> 6, seg = i & 63;
        int ky = row >> 3, cpl = row & 7;
        int gy = y - 1 + ky;
        if ((unsigned)gy < 256u)
            cpa16(sx_b + (uint32_t)(row * SXB + 4 + seg * 4) * 4,
                  in + (((size_t)(c * 8 + cpl) * 256 + gy) * 256 + seg * 4));
    }
#pragma unroll
    for (int it = 0; it < 9; it++) {
        int i = tid + (it << 8);
        int r = i & 7, gl = (i >> 3) & 7, qc = (i >> 6) & 3, t = i >> 8;
        cpa16(sw_b + (uint32_t)(((t * 4 + qc) * SWB4 + gl * 8 + r) * 16),
              WtP + ((((size_t)(c * 9 + t) * 4 + qc) * (Cout >> 4) + (coTile >> 4) + gl) * 8 + r));
    }
}

__global__ __launch_bounds__(256, 1) void conv3x3_bf(
    const uint32_t* __restrict__ in, const float4* __restrict__ WtP,
    const float* __restrict__ bias, uint32_t* __restrict__ out,
    int Cin, int Cout)
{
    extern __shared__ uint32_t smb[];
    const uint32_t base_b = smem_u32(smb);

    const int y      = blockIdx.x;
    const int coTile = blockIdx.y << 7;
    const int tid  = threadIdx.x;
    const int lane = tid & 31;
    const int wid  = tid >> 5;
    const int gBase = (wid >> 2) << 2;
    const int nBase = (wid & 3) << 6;
    const int qr = lane >> 2;
    const int qc = lane & 3;

    for (int i = tid; i < 2 * STAGE_XB / 4; i += 256) {
        uint32_t a = base_b + ((i >= STAGE_XB / 4)
                     ? (uint32_t)(STAGE_FB + (i - STAGE_XB / 4) * 4) * 4
                     : (uint32_t)(i * 4) * 4);
        asm volatile("st.shared.v4.u32 [%0], {%1,%1,%1,%1};" :: "r"(a), "r"(0u));
    }
    __syncthreads();

    const int nch = Cin >> 4;
    stage_bf(base_b, base_b + STAGE_XB * 4, in, WtP, y, coTile, 0, Cout, tid);
    CP_COMMIT();

    float acc[4][8][4] = {};

    for (int c = 0; c < nch; c++) {
        const int s = c & 1;
        if (c + 1 < nch) {
            uint32_t sb = base_b + (uint32_t)((s ^ 1) * STAGE_FB) * 4;
            stage_bf(sb, sb + STAGE_XB * 4, in, WtP, y, coTile, c + 1, Cout, tid);
            CP_COMMIT();
            CP_WAIT1();
        } else {
            CP_WAIT0();
        }
        __syncthreads();

        const uint32_t* sX = smb + s * STAGE_FB;
        const uint32_t* sW = sX + STAGE_XB;

#pragma unroll
        for (int ky = 0; ky < 3; ky++) {
#pragma unroll
            for (int kx = 0; kx < 3; kx++) {
                const int t = ky * 3 + kx;
                uint32_t A[4][4];
#pragma unroll
                for (int mf = 0; mf < 4; mf++) {
                    float4 av = *(const float4*)&sW[((t * 4 + qc) * SWB4
                                                     + (gBase + mf) * 8 + qr) << 2];
                    A[mf][0] = __float_as_uint(av.x);
                    A[mf][1] = __float_as_uint(av.y);
                    A[mf][2] = __float_as_uint(av.z);
                    A[mf][3] = __float_as_uint(av.w);
                }
#pragma unroll
                for (int nf = 0; nf < 8; nf++) {
                    int col = nBase + nf * 8 + qr + kx + 3;
                    uint32_t b0 = sX[(ky * 8 + qc)     * SXB + col];
                    uint32_t b1 = sX[(ky * 8 + qc + 4) * SXB + col];
#pragma unroll
                    for (int mf = 0; mf < 4; mf++)
                        mma_bf16(acc[mf][nf], A[mf][0], A[mf][1], A[mf][2], A[mf][3], b0, b1);
                }
            }
        }
        __syncthreads();
    }

#pragma unroll
    for (int mf = 0; mf < 4; mf++) {
        int co = coTile + (gBase + mf) * 16 + qr;
        int cpg = ((co >> 4) << 3) + (co & 7);
        float bv0 = bias[co], bv1 = bias[co + 8];
#pragma unroll
        for (int nf = 0; nf < 8; nf++) {
            int px = nBase + nf * 8 + 2 * qc;
            uint32_t p0 = pk_bf2(fmaxf(acc[mf][nf][0] + bv0, 0.f),
                                 fmaxf(acc[mf][nf][2] + bv1, 0.f));
            uint32_t p1 = pk_bf2(fmaxf(acc[mf][nf][1] + bv0, 0.f),
                                 fmaxf(acc[mf][nf][3] + bv1, 0.f));
            uint2 v = { p0, p1 };
            *(uint2*)&out[((size_t)cpg << 16) + (y << 8) + px] = v;
        }
    }
}

// ---------------------------------------------------------------------------
// FP16 mma.sync 3x3 SAME conv (classification, 128x128), m16n8k16.
// fp16 mantissa == tf32 mantissa (10 bits) -> tf32-level bin-flip behavior
// at half the MMA instruction count. CTA: M=128 Cout x N=256 px = 2 rows.
// Pair-interleaved half2 planes in/out (pair p = channels base+p, base+p+8).
// ---------------------------------------------------------------------------
#define SXH 136
#define STAGE_XH (32 * SXH)               // 4352 uints (17408 B)
#define STAGE_WH (9 * 4 * SWB4 * 4)       // 9504 uints (38016 B)
#define STAGE_FH (STAGE_XH + STAGE_WH)    // 13856 uints
#define CH_SMEM (2 * STAGE_FH * 4)        // 110848 B

__device__ __forceinline__ void stage_h(
    uint32_t st_b, const uint32_t* __restrict__ in, const float4* __restrict__ WtP,
    int y0, int coTile, int c, int Cout, int tid)
{
    const uint32_t xb = st_b;
    const uint32_t wb = st_b + STAGE_XH * 4;
    // X: 32 rows (4 ky4 x 8 cp) x 32 segs of 16B (cols 4..131 = px 0..127)
#pragma unroll
    for (int it = 0; it < 4; it++) {
        int i = tid + (it << 8);
        int row = i >> 5, seg = i & 31;
        int ky4 = row >> 3, cpl = row & 7;
        int gy = y0 - 1 + ky4;
        if ((unsigned)gy < 128u)
            cpa16(xb + (uint32_t)(row * SXH + 4 + seg * 4) * 4,
                  in + ((size_t)(c * 8 + cpl) * 16384 + gy * 128 + seg * 4));
    }
#pragma unroll
    for (int it = 0; it < 9; it++) {
        int i = tid + (it << 8);
        int r = i & 7, gl = (i >> 3) & 7, qc = (i >> 6) & 3, t = i >> 8;
        cpa16(wb + (uint32_t)(((t * 4 + qc) * SWB4 + gl * 8 + r) * 16),
              WtP + ((((size_t)(c * 9 + t) * 4 + qc) * (Cout >> 4) + (coTile >> 4) + gl) * 8 + r));
    }
}

__global__ __launch_bounds__(256) void conv3x3_h(
    const uint32_t* __restrict__ in, const float4* __restrict__ WtP,
    const float* __restrict__ bias, uint32_t* __restrict__ out,
    int Cin, int Cout)
{
    extern __shared__ uint32_t smh[];
    const uint32_t base_b = smem_u32(smh);

    const int y0     = blockIdx.x << 1;
    const int coTile = blockIdx.y << 7;
    const int tid  = threadIdx.x;
    const int lane = tid & 31;
    const int wid  = tid >> 5;
    const int gBase = (wid >> 2) << 2;
    const int nBase = (wid & 3) << 6;
    const int qr = lane >> 2;
    const int qc = lane & 3;

    // pre-zero X areas of both stages (halo cols + OOB rows)
    for (int i = tid; i < 2 * STAGE_XH / 4; i += 256) {
        uint32_t a = base_b + ((i >= STAGE_XH / 4)
                     ? (uint32_t)(STAGE_FH + (i - STAGE_XH / 4) * 4) * 4
                     : (uint32_t)(i * 4) * 4);
        asm volatile("st.shared.v4.u32 [%0], {%1,%1,%1,%1};" :: "r"(a), "r"(0u));
    }
    __syncthreads();

    const int nch = Cin >> 4;
    stage_h(base_b, in, WtP, y0, coTile, 0, Cout, tid);
    CP_COMMIT();

    float acc[4][8][4] = {};

    for (int c = 0; c < nch; c++) {
        const int s = c & 1;
        if (c + 1 < nch) {
            stage_h(base_b + (uint32_t)((s ^ 1) * STAGE_FH) * 4,
                    in, WtP, y0, coTile, c + 1, Cout, tid);
            CP_COMMIT();
            CP_WAIT1();
        } else {
            CP_WAIT0();
        }
        __syncthreads();

        const uint32_t* sX = smh + s * STAGE_FH;
        const uint32_t* sW = sX + STAGE_XH;

#pragma unroll
        for (int ky = 0; ky < 3; ky++) {
#pragma unroll
            for (int kx = 0; kx < 3; kx++) {
                const int t = ky * 3 + kx;
                uint32_t A[4][4];
#pragma unroll
                for (int mf = 0; mf < 4; mf++) {
                    float4 av = *(const float4*)&sW[((t * 4 + qc) * SWB4
                                                     + (gBase + mf) * 8 + qr) << 2];
                    A[mf][0] = __float_as_uint(av.x);
                    A[mf][1] = __float_as_uint(av.y);
                    A[mf][2] = __float_as_uint(av.z);
                    A[mf][3] = __float_as_uint(av.w);
                }
#pragma unroll
                for (int nf = 0; nf < 8; nf++) {
                    int col = nBase + nf * 8 + qr;
                    int r = col >> 7, x = col & 127;
                    int rowb = (r + ky) * 8;
                    uint32_t b0 = sX[(rowb + qc)     * SXH + x + kx + 3];
                    uint32_t b1 = sX[(rowb + qc + 4) * SXH + x + kx + 3];
#pragma unroll
                    for (int mf = 0; mf < 4; mf++)
                        mma_f16(acc[mf][nf], A[mf][0], A[mf][1], A[mf][2], A[mf][3], b0, b1);
                }
            }
        }
        __syncthreads();
    }

    // epilogue: bias + ReLU -> packed fp16 pair planes (pair = co, co+8)
#pragma unroll
    for (int mf = 0; mf < 4; mf++) {
        int co = coTile + (gBase + mf) * 16 + qr;
        int cpg = ((co >> 4) << 3) + (co & 7);
        float bv0 = bias[co], bv1 = bias[co + 8];
#pragma unroll
        for (int nf = 0; nf < 8; nf++) {
            int n = nBase + nf * 8 + 2 * qc;
            int r = n >> 7, x = n & 127;
            uint32_t p0 = pk_h2(fmaxf(acc[mf][nf][0] + bv0, 0.f),
                                fmaxf(acc[mf][nf][2] + bv1, 0.f));
            uint32_t p1 = pk_h2(fmaxf(acc[mf][nf][1] + bv0, 0.f),
                                fmaxf(acc[mf][nf][3] + bv1, 0.f));
            uint2 v = { p0, p1 };
            *(uint2*)&out[(size_t)cpg * 16384 + (y0 + r) * 128 + x] = v;
        }
    }
}

// ---------------------------------------------------------------------------
// Heads / transforms
// ---------------------------------------------------------------------------
// cls head reading fp16 pair-interleaved h3 (128 cp planes, 256 channels)
__global__ void cls_kernel_h(const uint32_t* __restrict__ h, const float* __restrict__ w,
                             const float* __restrict__ b, float* __restrict__ cls,
                             float* __restrict__ bin)
{
    int p = blockIdx.x * 256 + threadIdx.x;   // 16384
    float s = b[0];
#pragma unroll 8
    for (int cp = 0; cp < 128; cp++) {
        uint32_t u = h[(size_t)cp * 16384 + p];
        int c_lo = ((cp >> 3) << 4) + (cp & 7);
        s = fmaf(w[c_lo], h_lo(u), fmaf(w[c_lo + 8], h_hi(u), s));
    }
    float sig = 1.f / (1.f + expf(-s));
    cls[p] = sig;
    bin[p] = (sig >= 0.5f) ? 1.f : 0.f;
}

// field head reading bf16 pair-interleaved r3 (128 cp planes)
__global__ void field_kernel_bf(const uint32_t* __restrict__ r, const float* __restrict__ w,
                                const float* __restrict__ b, float* __restrict__ field)
{
    int p = blockIdx.x * 256 + threadIdx.x;   // 65536
    float s0 = b[0], s1 = b[1];
#pragma unroll 8
    for (int cp = 0; cp < 128; cp++) {
        uint32_t u = r[((size_t)cp << 16) + p];
        float vlo = bf_lo(u), vhi = bf_hi(u);
        int c_lo = ((cp >> 3) << 4) + (cp & 7);
        s0 = fmaf(w[c_lo], vlo, fmaf(w[c_lo + 8], vhi, s0));
        s1 = fmaf(w[256 + c_lo], vlo, fmaf(w[256 + c_lo + 8], vhi, s1));
    }
    field[p] = s0;
    field[65536 + p] = s1;
}

__global__ void upsample_kernel(const float* __restrict__ bin, float* __restrict__ out)
{
    int idx = blockIdx.x * 256 + threadIdx.x;
    if (idx >= 256 * 256) return;
    int Y = idx >> 8, X = idx & 255;
    const float step = 127.0f / 255.0f;
    float ys = (float)Y * step, xs = (float)X * step;
    int y0 = (int)floorf(ys); int y1 = min(y0 + 1, 127);
    int x0 = (int)floorf(xs); int x1 = min(x0 + 1, 127);
    float wy = ys - (float)y0, wx = xs - (float)x0;
    float v00 = bin[y0 * 128 + x0], v01 = bin[y0 * 128 + x1];
    float v10 = bin[y1 * 128 + x0], v11 = bin[y1 * 128 + x1];
    out[idx] = rintf((v00 * (1.f - wx) + v01 * wx) * (1.f - wy)
                   + (v10 * (1.f - wx) + v11 * wx) * wy);
}

__global__ void contour_kernel(const float* __restrict__ cc,
                               const float* __restrict__ field,
                               const int* __restrict__ pnum_iter,
                               float* __restrict__ out, int npts)
{
    int i = blockIdx.x * 256 + threadIdx.x;
    if (i >= npts) return;
    const int W = 256, H = 256;
    float x = cc[2 * i], y = cc[2 * i + 1];
    int n = pnum_iter[0];
    for (int t = 0; t < n; t++) {
        float xc = fminf(fmaxf(x, 0.f), 255.f);
        float yc = fminf(fmaxf(y, 0.f), 255.f);
        int x0 = (int)floorf(xc); int x1 = min(x0 + 1, W - 1);
        int y0 = (int)floorf(yc); int y1 = min(y0 + 1, H - 1);
        float wx = xc - (float)x0, wy = yc - (float)y0;
        float ox, oy;
        {
            const float* f = field;
            float v00 = f[y0 * W + x0], v01 = f[y0 * W + x1];
            float v10 = f[y1 * W + x0], v11 = f[y1 * W + x1];
            ox = (v00 * (1.f - wx) + v01 * wx) * (1.f - wy)
               + (v10 * (1.f - wx) + v11 * wx) * wy;
        }
        {
            const float* f = field + H * W;
            float v00 = f[y0 * W + x0], v01 = f[y0 * W + x1];
            float v10 = f[y1 * W + x0], v11 = f[y1 * W + x1];
            oy = (v00 * (1.f - wx) + v01 * wx) * (1.f - wy)
               + (v10 * (1.f - wx) + v11 * wx) * wy;
        }
        x = fminf(fmaxf(x + ox, 0.f), 255.f);
        y = fminf(fmaxf(y + oy, 0.f), 255.f);
    }
    out[2 * i] = x;
    out[2 * i + 1] = y;
}

// ---------------------------------------------------------------------------
extern "C" void kernel_launch(void* const* d_in, const int* in_sizes, int n_in,
                              void* d_out, int out_size)
{
    const float* f1  = (const float*)d_in[0];
    const float* f2  = (const float*)d_in[1];
    const float* cc  = (const float*)d_in[2];
    const float* cw1 = (const float*)d_in[3];
    const float* cb1 = (const float*)d_in[4];
    const float* cw2 = (const float*)d_in[5];
    const float* cb2 = (const float*)d_in[6];
    const float* cw3 = (const float*)d_in[7];
    const float* cb3 = (const float*)d_in[8];
    const float* cw4 = (const float*)d_in[9];
    const float* cb4 = (const float*)d_in[10];
    const float* rw1 = (const float*)d_in[11];
    const float* rb1 = (const float*)d_in[12];
    const float* rw2 = (const float*)d_in[13];
    const float* rb2 = (const float*)d_in[14];
    const float* rw3 = (const float*)d_in[15];
    const float* rb3 = (const float*)d_in[16];
    const float* rw4 = (const float*)d_in[17];
    const float* rb4 = (const float*)d_in[18];
    const int*   pnum = (const int*)d_in[19];

    float* out = (float*)d_out;
    float* out_cls = out;
    float* out_bin = out + 16384;
    float* out_ctr = out + 16384 + 65536;

    float *bufA, *bufB, *Wt1, *Wt2, *Wt3, *CW1, *CW2, *CW3, *field, *bin;
    cudaGetSymbolAddress((void**)&bufA, g_bufA);
    cudaGetSymbolAddress((void**)&bufB, g_bufB);
    cudaGetSymbolAddress((void**)&Wt1,  g_Wt1);
    cudaGetSymbolAddress((void**)&Wt2,  g_Wt2);
    cudaGetSymbolAddress((void**)&Wt3,  g_Wt3);
    cudaGetSymbolAddress((void**)&CW1,  g_CW1);
    cudaGetSymbolAddress((void**)&CW2,  g_CW2);
    cudaGetSymbolAddress((void**)&CW3,  g_CW3);
    cudaGetSymbolAddress((void**)&field, g_field);
    cudaGetSymbolAddress((void**)&bin,  g_bin);

    // cls fp16 pair-plane intermediates (consumed before refinement overwrites)
    uint32_t* f2h = (uint32_t*)(bufB + 8388608u);     // [32,48) MiB of bufB, 16 MiB
    uint32_t* h1  = (uint32_t*)bufA;                  // 32 MiB
    uint32_t* h2  = (uint32_t*)bufB;                  // 16 MiB
    uint32_t* h3  = (uint32_t*)(bufA + 16777216u);    // +64 MiB, 8 MiB

    // refinement bf16 pair-planes
    uint32_t* f1bf = (uint32_t*)(bufA + 33554432u);   // +128 MiB, 64 MiB
    uint32_t* r1bf = (uint32_t*)bufA;                 // 128 MiB (after cls done)
    uint32_t* r2bf = (uint32_t*)bufB;                 // 64 MiB (after cls done)
    uint32_t* r3bf = (uint32_t*)(bufB + 16777216u);   // +64 MiB, 32 MiB

    cudaFuncSetAttribute(conv3x3_bf, cudaFuncAttributeMaxDynamicSharedMemorySize, CBF_SMEM);
    cudaFuncSetAttribute(conv3x3_h,  cudaFuncAttributeMaxDynamicSharedMemorySize, CH_SMEM);

    // ---- prep: weight packing + input conversions ----
    {
        int b1 = (512 >> 4) * 9 * 4 * (1024 >> 4) * 8;
        int b2 = (1024 >> 4) * 9 * 4 * (512 >> 4) * 8;
        int b3 = (512 >> 4) * 9 * 4 * (256 >> 4) * 8;
        wt_pack_bf16<<<(b1 + 255) / 256, 256>>>(rw1, (float4*)Wt1, 1024, 512);
        wt_pack_bf16<<<(b2 + 255) / 256, 256>>>(rw2, (float4*)Wt2, 512, 1024);
        wt_pack_bf16<<<(b3 + 255) / 256, 256>>>(rw3, (float4*)Wt3, 256, 512);
        wt_pack_f16<<<(b1 + 255) / 256, 256>>>(cw1, (float4*)CW1, 1024, 512);
        wt_pack_f16<<<(b2 + 255) / 256, 256>>>(cw2, (float4*)CW2, 512, 1024);
        wt_pack_f16<<<(b3 + 255) / 256, 256>>>(cw3, (float4*)CW3, 256, 512);
        to_bf16_pairs<<<65536, 256>>>(f1, f1bf);
        to_f16_pairs<<<16384, 256>>>(f2, f2h);
    }

    // ---- classification branch (fp16 m16n8k16 mma.sync) ----
    conv3x3_h<<<dim3(64, 8), 256, CH_SMEM>>>(f2h, (const float4*)CW1, cb1, h1, 512, 1024);
    conv3x3_h<<<dim3(64, 4), 256, CH_SMEM>>>(h1,  (const float4*)CW2, cb2, h2, 1024, 512);
    conv3x3_h<<<dim3(64, 2), 256, CH_SMEM>>>(h2,  (const float4*)CW3, cb3, h3, 512, 256);
    cls_kernel_h<<<64, 256>>>(h3, cw4, cb4, out_cls, bin);
    upsample_kernel<<<256, 256>>>(bin, out_bin);

    // ---- refinement branch (bf16 m16n8k16 mma.sync, pipelined) ----
    conv3x3_bf<<<dim3(256, 8), 256, CBF_SMEM>>>(f1bf, (const float4*)Wt1, rb1, r1bf, 512, 1024);
    conv3x3_bf<<<dim3(256, 4), 256, CBF_SMEM>>>(r1bf, (const float4*)Wt2, rb2, r2bf, 1024, 512);
    conv3x3_bf<<<dim3(256, 2), 256, CBF_SMEM>>>(r2bf, (const float4*)Wt3, rb3, r3bf, 512, 256);
    field_kernel_bf<<<256, 256>>>(r3bf, rw4, rb4, field);
    contour_kernel<<<(38400 + 255) / 256, 256>>>(cc, field, pnum, out_ctr, 38400);
}

// round 16
// speedup vs baseline: 11.7614x; 1.0713x over previous
#include <cuda_runtime.h>
#include <cuda_bf16.h>
#include <cuda_fp16.h>
#include <math.h>
#include <stdint.h>

// ---------------------------------------------------------------------------
// Scratch (device globals -- no runtime allocation allowed)
// ---------------------------------------------------------------------------
__device__ float g_bufA[1024u * 256u * 256u];   // 256 MiB
__device__ float g_bufB[512u * 256u * 256u];    // 128 MiB
__device__ float g_Wt1[1024u * 512u * 9u];      // refinement packed bf16 weights
__device__ float g_Wt2[512u * 1024u * 9u];
__device__ float g_Wt3[256u * 512u * 9u];
__device__ float g_CW1[1024u * 512u * 9u];      // cls packed fp16 weights
__device__ float g_CW2[512u * 1024u * 9u];
__device__ float g_CW3[256u * 512u * 9u];
__device__ float g_field[2 * 256 * 256];
__device__ float g_bin[128 * 128];

// ---------------------------------------------------------------------------
// Helpers (portable sm_80+ -- NO 'a'-suffix features)
// ---------------------------------------------------------------------------
__device__ __forceinline__ uint32_t pk_bf2(float a, float b) {
    unsigned short lo = __bfloat16_as_ushort(__float2bfloat16_rn(a));
    unsigned short hi = __bfloat16_as_ushort(__float2bfloat16_rn(b));
    return ((uint32_t)hi << 16) | lo;
}
__device__ __forceinline__ float bf_lo(uint32_t u) {
    return __bfloat162float(__ushort_as_bfloat16((unsigned short)(u & 0xFFFFu)));
}
__device__ __forceinline__ float bf_hi(uint32_t u) {
    return __bfloat162float(__ushort_as_bfloat16((unsigned short)(u >> 16)));
}
__device__ __forceinline__ uint32_t pk_h2(float a, float b) {
    unsigned short lo = __half_as_ushort(__float2half_rn(a));
    unsigned short hi = __half_as_ushort(__float2half_rn(b));
    return ((uint32_t)hi << 16) | lo;
}
__device__ __forceinline__ float h_lo(uint32_t u) {
    return __half2float(__ushort_as_half((unsigned short)(u & 0xFFFFu)));
}
__device__ __forceinline__ float h_hi(uint32_t u) {
    return __half2float(__ushort_as_half((unsigned short)(u >> 16)));
}

__device__ __forceinline__ void mma_bf16(float c[4],
                                         uint32_t a0, uint32_t a1, uint32_t a2, uint32_t a3,
                                         uint32_t b0, uint32_t b1) {
    asm volatile(
        "mma.sync.aligned.m16n8k16.row.col.f32.bf16.bf16.f32 "
        "{%0,%1,%2,%3}, {%4,%5,%6,%7}, {%8,%9}, {%0,%1,%2,%3};"
        : "+f"(c[0]), "+f"(c[1]), "+f"(c[2]), "+f"(c[3])
        : "r"(a0), "r"(a1), "r"(a2), "r"(a3), "r"(b0), "r"(b1));
}
__device__ __forceinline__ void mma_f16(float c[4],
                                        uint32_t a0, uint32_t a1, uint32_t a2, uint32_t a3,
                                        uint32_t b0, uint32_t b1) {
    asm volatile(
        "mma.sync.aligned.m16n8k16.row.col.f32.f16.f16.f32 "
        "{%0,%1,%2,%3}, {%4,%5,%6,%7}, {%8,%9}, {%0,%1,%2,%3};"
        : "+f"(c[0]), "+f"(c[1]), "+f"(c[2]), "+f"(c[3])
        : "r"(a0), "r"(a1), "r"(a2), "r"(a3), "r"(b0), "r"(b1));
}
__device__ __forceinline__ uint32_t smem_u32(const void* p) {
    uint32_t a;
    asm("{ .reg .u64 t; cvta.to.shared.u64 t, %1; cvt.u32.u64 %0, t; }" : "=r"(a) : "l"(p));
    return a;
}
__device__ __forceinline__ void cpa16(uint32_t dst, const void* src) {
    asm volatile("cp.async.cg.shared.global [%0], [%1], 16;" :: "r"(dst), "l"(src) : "memory");
}
#define CP_COMMIT() asm volatile("cp.async.commit_group;" ::: "memory")
#define CP_WAIT1()  asm volatile("cp.async.wait_group 1;" ::: "memory")
#define CP_WAIT0()  asm volatile("cp.async.wait_group 0;" ::: "memory")

// ---------------------------------------------------------------------------
// Weight packers: 16-ch chunks; k-slot 2p -> ch base+p, 2p+1 -> ch base+p+8.
// ---------------------------------------------------------------------------
__global__ void wt_pack_bf16(const float* __restrict__ w, float4* __restrict__ out,
                             int Cout, int Cin)
{
    int i = blockIdx.x * 256 + threadIdx.x;
    int total = (Cin >> 4) * 9 * 4 * (Cout >> 4) * 8;
    if (i >= total) return;
    int r  = i & 7;
    int g  = (i >> 3) % (Cout >> 4);
    int rest = (i >> 3) / (Cout >> 4);
    int qc = rest & 3;
    int tc = rest >> 2;
    int t  = tc % 9;
    int c  = tc / 9;
    int m  = g * 16 + r;
    int base = c * 16;
#define WV(mm, ci) w[((size_t)(mm) * Cin + (ci)) * 9 + t]
    uint32_t u0 = pk_bf2(WV(m,     base + qc),     WV(m,     base + qc + 8));
    uint32_t u1 = pk_bf2(WV(m + 8, base + qc),     WV(m + 8, base + qc + 8));
    uint32_t u2 = pk_bf2(WV(m,     base + qc + 4), WV(m,     base + qc + 12));
    uint32_t u3 = pk_bf2(WV(m + 8, base + qc + 4), WV(m + 8, base + qc + 12));
#undef WV
    out[i] = make_float4(__uint_as_float(u0), __uint_as_float(u1),
                         __uint_as_float(u2), __uint_as_float(u3));
}

__global__ void wt_pack_f16(const float* __restrict__ w, float4* __restrict__ out,
                            int Cout, int Cin)
{
    int i = blockIdx.x * 256 + threadIdx.x;
    int total = (Cin >> 4) * 9 * 4 * (Cout >> 4) * 8;
    if (i >= total) return;
    int r  = i & 7;
    int g  = (i >> 3) % (Cout >> 4);
    int rest = (i >> 3) / (Cout >> 4);
    int qc = rest & 3;
    int tc = rest >> 2;
    int t  = tc % 9;
    int c  = tc / 9;
    int m  = g * 16 + r;
    int base = c * 16;
#define WV(mm, ci) w[((size_t)(mm) * Cin + (ci)) * 9 + t]
    uint32_t u0 = pk_h2(WV(m,     base + qc),     WV(m,     base + qc + 8));
    uint32_t u1 = pk_h2(WV(m + 8, base + qc),     WV(m + 8, base + qc + 8));
    uint32_t u2 = pk_h2(WV(m,     base + qc + 4), WV(m,     base + qc + 12));
    uint32_t u3 = pk_h2(WV(m + 8, base + qc + 4), WV(m + 8, base + qc + 12));
#undef WV
    out[i] = make_float4(__uint_as_float(u0), __uint_as_float(u1),
                         __uint_as_float(u2), __uint_as_float(u3));
}

// f1 (NCHW fp32, 512x256x256) -> pair-interleaved bf16 planes (256 cp rows)
__global__ void to_bf16_pairs(const float* __restrict__ in, uint32_t* __restrict__ out)
{
    int i = blockIdx.x * 256 + threadIdx.x;
    if (i >= 256 * 65536) return;
    int cp = i >> 16, pix = i & 65535;
    int c_lo = ((cp >> 3) << 4) + (cp & 7);
    out[i] = pk_bf2(in[((size_t)c_lo << 16) + pix],
                    in[((size_t)(c_lo + 8) << 16) + pix]);
}

// f2 (NCHW fp32, 512x128x128) -> pair-interleaved fp16 planes (256 cp rows)
__global__ void to_f16_pairs(const float* __restrict__ in, uint32_t* __restrict__ out)
{
    int i = blockIdx.x * 256 + threadIdx.x;
    if (i >= 256 * 16384) return;
    int cp = i >> 14, pix = i & 16383;
    int c_lo = ((cp >> 3) << 4) + (cp & 7);
    out[i] = pk_h2(in[(size_t)c_lo * 16384 + pix],
                   in[(size_t)(c_lo + 8) * 16384 + pix]);
}

// ---------------------------------------------------------------------------
// BF16 mma.sync 3x3 SAME conv (refinement, 256x256), m16n8k16.
// 3-stage cp.async ring, ONE __syncthreads per chunk.
// ---------------------------------------------------------------------------
#define SXB 264
#define SWB4 66
#define STAGE_XB (24 * SXB)
#define STAGE_WB (9 * 4 * SWB4 * 4)
#define STAGE_FB (STAGE_XB + STAGE_WB)
#define CBF_SMEM (3 * STAGE_FB * 4)    // 190080 B

__device__ __forceinline__ void stage_bf(
    uint32_t sx_b, uint32_t sw_b, const uint32_t* __restrict__ in,
    const float4* __restrict__ WtP, int y, int coTile, int c, int Cout, int tid)
{
#pragma unroll
    for (int it = 0; it < 6; it++) {
        int i = tid + (it << 8);
        int row = i >> 6, seg = i & 63;
        int ky = row >> 3, cpl = row & 7;
        int gy = y - 1 + ky;
        if ((unsigned)gy < 256u)
            cpa16(sx_b + (uint32_t)(row * SXB + 4 + seg * 4) * 4,
                  in + (((size_t)(c * 8 + cpl) * 256 + gy) * 256 + seg * 4));
    }
#pragma unroll
    for (int it = 0; it < 9; it++) {
        int i = tid + (it << 8);
        int r = i & 7, gl = (i >> 3) & 7, qc = (i >> 6) & 3, t = i >> 8;
        cpa16(sw_b + (uint32_t)(((t * 4 + qc) * SWB4 + gl * 8 + r) * 16),
              WtP + ((((size_t)(c * 9 + t) * 4 + qc) * (Cout >> 4) + (coTile >> 4) + gl) * 8 + r));
    }
}

__global__ __launch_bounds__(256, 1) void conv3x3_bf(
    const uint32_t* __restrict__ in, const float4* __restrict__ WtP,
    const float* __restrict__ bias, uint32_t* __restrict__ out,
    int Cin, int Cout)
{
    extern __shared__ uint32_t smb[];
    const uint32_t base_b = smem_u32(smb);

    const int y      = blockIdx.x;
    const int coTile = blockIdx.y << 7;
    const int tid  = threadIdx.x;
    const int lane = tid & 31;
    const int wid  = tid >> 5;
    const int gBase = (wid >> 2) << 2;
    const int nBase = (wid & 3) << 6;
    const int qr = lane >> 2;
    const int qc = lane & 3;

    // pre-zero X areas of all 3 stages (halo cols + OOB ky rows)
    for (int i = tid; i < 3 * STAGE_XB / 4; i += 256) {
        int st = i / (STAGE_XB / 4);
        int j  = i - st * (STAGE_XB / 4);
        uint32_t a = base_b + (uint32_t)(st * STAGE_FB + j * 4) * 4;
        asm volatile("st.shared.v4.u32 [%0], {%1,%1,%1,%1};" :: "r"(a), "r"(0u));
    }
    __syncthreads();

    const int nch = Cin >> 4;
    stage_bf(base_b, base_b + STAGE_XB * 4, in, WtP, y, coTile, 0, Cout, tid);
    CP_COMMIT();
    {
        uint32_t sb = base_b + (uint32_t)STAGE_FB * 4;
        stage_bf(sb, sb + STAGE_XB * 4, in, WtP, y, coTile, 1, Cout, tid);
        CP_COMMIT();
    }

    float acc[4][8][4] = {};

    for (int c = 0; c < nch; c++) {
        if (c + 1 < nch) CP_WAIT1(); else CP_WAIT0();
        __syncthreads();
        if (c + 2 < nch) {
            uint32_t sb = base_b + (uint32_t)(((c + 2) % 3) * STAGE_FB) * 4;
            stage_bf(sb, sb + STAGE_XB * 4, in, WtP, y, coTile, c + 2, Cout, tid);
            CP_COMMIT();
        }

        const uint32_t* sX = smb + (c % 3) * STAGE_FB;
        const uint32_t* sW = sX + STAGE_XB;

#pragma unroll
        for (int ky = 0; ky < 3; ky++) {
#pragma unroll
            for (int kx = 0; kx < 3; kx++) {
                const int t = ky * 3 + kx;
                uint32_t A[4][4];
#pragma unroll
                for (int mf = 0; mf < 4; mf++) {
                    float4 av = *(const float4*)&sW[((t * 4 + qc) * SWB4
                                                     + (gBase + mf) * 8 + qr) << 2];
                    A[mf][0] = __float_as_uint(av.x);
                    A[mf][1] = __float_as_uint(av.y);
                    A[mf][2] = __float_as_uint(av.z);
                    A[mf][3] = __float_as_uint(av.w);
                }
#pragma unroll
                for (int nf = 0; nf < 8; nf++) {
                    int col = nBase + nf * 8 + qr + kx + 3;
                    uint32_t b0 = sX[(ky * 8 + qc)     * SXB + col];
                    uint32_t b1 = sX[(ky * 8 + qc + 4) * SXB + col];
#pragma unroll
                    for (int mf = 0; mf < 4; mf++)
                        mma_bf16(acc[mf][nf], A[mf][0], A[mf][1], A[mf][2], A[mf][3], b0, b1);
                }
            }
        }
    }

#pragma unroll
    for (int mf = 0; mf < 4; mf++) {
        int co = coTile + (gBase + mf) * 16 + qr;
        int cpg = ((co >> 4) << 3) + (co & 7);
        float bv0 = bias[co], bv1 = bias[co + 8];
#pragma unroll
        for (int nf = 0; nf < 8; nf++) {
            int px = nBase + nf * 8 + 2 * qc;
            uint32_t p0 = pk_bf2(fmaxf(acc[mf][nf][0] + bv0, 0.f),
                                 fmaxf(acc[mf][nf][2] + bv1, 0.f));
            uint32_t p1 = pk_bf2(fmaxf(acc[mf][nf][1] + bv0, 0.f),
                                 fmaxf(acc[mf][nf][3] + bv1, 0.f));
            uint2 v = { p0, p1 };
            *(uint2*)&out[((size_t)cpg << 16) + (y << 8) + px] = v;
        }
    }
}

// ---------------------------------------------------------------------------
// FP16 mma.sync 3x3 SAME conv (classification, 128x128), m16n8k16.
// 3-stage ring, one sync per chunk. CTA: 128 Cout x 256 px (2 rows).
// ---------------------------------------------------------------------------
#define SXH 136
#define STAGE_XH (32 * SXH)
#define STAGE_WH (9 * 4 * SWB4 * 4)
#define STAGE_FH (STAGE_XH + STAGE_WH)
#define CH_SMEM (3 * STAGE_FH * 4)        // 166272 B

__device__ __forceinline__ void stage_h(
    uint32_t st_b, const uint32_t* __restrict__ in, const float4* __restrict__ WtP,
    int y0, int coTile, int c, int Cout, int tid)
{
    const uint32_t xb = st_b;
    const uint32_t wb = st_b + STAGE_XH * 4;
#pragma unroll
    for (int it = 0; it < 4; it++) {
        int i = tid + (it << 8);
        int row = i >> 5, seg = i & 31;
        int ky4 = row >> 3, cpl = row & 7;
        int gy = y0 - 1 + ky4;
        if ((unsigned)gy < 128u)
            cpa16(xb + (uint32_t)(row * SXH + 4 + seg * 4) * 4,
                  in + ((size_t)(c * 8 + cpl) * 16384 + gy * 128 + seg * 4));
    }
#pragma unroll
    for (int it = 0; it < 9; it++) {
        int i = tid + (it << 8);
        int r = i & 7, gl = (i >> 3) & 7, qc = (i >> 6) & 3, t = i >> 8;
        cpa16(wb + (uint32_t)(((t * 4 + qc) * SWB4 + gl * 8 + r) * 16),
              WtP + ((((size_t)(c * 9 + t) * 4 + qc) * (Cout >> 4) + (coTile >> 4) + gl) * 8 + r));
    }
}

__global__ __launch_bounds__(256) void conv3x3_h(
    const uint32_t* __restrict__ in, const float4* __restrict__ WtP,
    const float* __restrict__ bias, uint32_t* __restrict__ out,
    int Cin, int Cout)
{
    extern __shared__ uint32_t smh[];
    const uint32_t base_b = smem_u32(smh);

    const int y0     = blockIdx.x << 1;
    const int coTile = blockIdx.y << 7;
    const int tid  = threadIdx.x;
    const int lane = tid & 31;
    const int wid  = tid >> 5;
    const int gBase = (wid >> 2) << 2;
    const int nBase = (wid & 3) << 6;
    const int qr = lane >> 2;
    const int qc = lane & 3;

    for (int i = tid; i < 3 * STAGE_XH / 4; i += 256) {
        int st = i / (STAGE_XH / 4);
        int j  = i - st * (STAGE_XH / 4);
        uint32_t a = base_b + (uint32_t)(st * STAGE_FH + j * 4) * 4;
        asm volatile("st.shared.v4.u32 [%0], {%1,%1,%1,%1};" :: "r"(a), "r"(0u));
    }
    __syncthreads();

    const int nch = Cin >> 4;
    stage_h(base_b, in, WtP, y0, coTile, 0, Cout, tid);
    CP_COMMIT();
    stage_h(base_b + (uint32_t)STAGE_FH * 4, in, WtP, y0, coTile, 1, Cout, tid);
    CP_COMMIT();

    float acc[4][8][4] = {};

    for (int c = 0; c < nch; c++) {
        if (c + 1 < nch) CP_WAIT1(); else CP_WAIT0();
        __syncthreads();
        if (c + 2 < nch) {
            stage_h(base_b + (uint32_t)(((c + 2) % 3) * STAGE_FH) * 4,
                    in, WtP, y0, coTile, c + 2, Cout, tid);
            CP_COMMIT();
        }

        const uint32_t* sX = smh + (c % 3) * STAGE_FH;
        const uint32_t* sW = sX + STAGE_XH;

#pragma unroll
        for (int ky = 0; ky < 3; ky++) {
#pragma unroll
            for (int kx = 0; kx < 3; kx++) {
                const int t = ky * 3 + kx;
                uint32_t A[4][4];
#pragma unroll
                for (int mf = 0; mf < 4; mf++) {
                    float4 av = *(const float4*)&sW[((t * 4 + qc) * SWB4
                                                     + (gBase + mf) * 8 + qr) << 2];
                    A[mf][0] = __float_as_uint(av.x);
                    A[mf][1] = __float_as_uint(av.y);
                    A[mf][2] = __float_as_uint(av.z);
                    A[mf][3] = __float_as_uint(av.w);
                }
#pragma unroll
                for (int nf = 0; nf < 8; nf++) {
                    int col = nBase + nf * 8 + qr;
                    int r = col >> 7, x = col & 127;
                    int rowb = (r + ky) * 8;
                    uint32_t b0 = sX[(rowb + qc)     * SXH + x + kx + 3];
                    uint32_t b1 = sX[(rowb + qc + 4) * SXH + x + kx + 3];
#pragma unroll
                    for (int mf = 0; mf < 4; mf++)
                        mma_f16(acc[mf][nf], A[mf][0], A[mf][1], A[mf][2], A[mf][3], b0, b1);
                }
            }
        }
    }

#pragma unroll
    for (int mf = 0; mf < 4; mf++) {
        int co = coTile + (gBase + mf) * 16 + qr;
        int cpg = ((co >> 4) << 3) + (co & 7);
        float bv0 = bias[co], bv1 = bias[co + 8];
#pragma unroll
        for (int nf = 0; nf < 8; nf++) {
            int n = nBase + nf * 8 + 2 * qc;
            int r = n >> 7, x = n & 127;
            uint32_t p0 = pk_h2(fmaxf(acc[mf][nf][0] + bv0, 0.f),
                                fmaxf(acc[mf][nf][2] + bv1, 0.f));
            uint32_t p1 = pk_h2(fmaxf(acc[mf][nf][1] + bv0, 0.f),
                                fmaxf(acc[mf][nf][3] + bv1, 0.f));
            uint2 v = { p0, p1 };
            *(uint2*)&out[(size_t)cpg * 16384 + (y0 + r) * 128 + x] = v;
        }
    }
}

// ---------------------------------------------------------------------------
// Heads / transforms
// ---------------------------------------------------------------------------
__global__ void cls_kernel_h(const uint32_t* __restrict__ h, const float* __restrict__ w,
                             const float* __restrict__ b, float* __restrict__ cls,
                             float* __restrict__ bin)
{
    int p = blockIdx.x * 256 + threadIdx.x;
    float s = b[0];
#pragma unroll 8
    for (int cp = 0; cp < 128; cp++) {
        uint32_t u = h[(size_t)cp * 16384 + p];
        int c_lo = ((cp >> 3) << 4) + (cp & 7);
        s = fmaf(w[c_lo], h_lo(u), fmaf(w[c_lo + 8], h_hi(u), s));
    }
    float sig = 1.f / (1.f + expf(-s));
    cls[p] = sig;
    bin[p] = (sig >= 0.5f) ? 1.f : 0.f;
}

__global__ void field_kernel_bf(const uint32_t* __restrict__ r, const float* __restrict__ w,
                                const float* __restrict__ b, float* __restrict__ field)
{
    int p = blockIdx.x * 256 + threadIdx.x;
    float s0 = b[0], s1 = b[1];
#pragma unroll 8
    for (int cp = 0; cp < 128; cp++) {
        uint32_t u = r[((size_t)cp << 16) + p];
        float vlo = bf_lo(u), vhi = bf_hi(u);
        int c_lo = ((cp >> 3) << 4) + (cp & 7);
        s0 = fmaf(w[c_lo], vlo, fmaf(w[c_lo + 8], vhi, s0));
        s1 = fmaf(w[256 + c_lo], vlo, fmaf(w[256 + c_lo + 8], vhi, s1));
    }
    field[p] = s0;
    field[65536 + p] = s1;
}

__global__ void upsample_kernel(const float* __restrict__ bin, float* __restrict__ out)
{
    int idx = blockIdx.x * 256 + threadIdx.x;
    if (idx >= 256 * 256) return;
    int Y = idx >> 8, X = idx & 255;
    const float step = 127.0f / 255.0f;
    float ys = (float)Y * step, xs = (float)X * step;
    int y0 = (int)floorf(ys); int y1 = min(y0 + 1, 127);
    int x0 = (int)floorf(xs); int x1 = min(x0 + 1, 127);
    float wy = ys - (float)y0, wx = xs - (float)x0;
    float v00 = bin[y0 * 128 + x0], v01 = bin[y0 * 128 + x1];
    float v10 = bin[y1 * 128 + x0], v11 = bin[y1 * 128 + x1];
    out[idx] = rintf((v00 * (1.f - wx) + v01 * wx) * (1.f - wy)
                   + (v10 * (1.f - wx) + v11 * wx) * wy);
}

__global__ void contour_kernel(const float* __restrict__ cc,
                               const float* __restrict__ field,
                               const int* __restrict__ pnum_iter,
                               float* __restrict__ out, int npts)
{
    int i = blockIdx.x * 256 + threadIdx.x;
    if (i >= npts) return;
    const int W = 256, H = 256;
    float x = cc[2 * i], y = cc[2 * i + 1];
    int n = pnum_iter[0];
    for (int t = 0; t < n; t++) {
        float xc = fminf(fmaxf(x, 0.f), 255.f);
        float yc = fminf(fmaxf(y, 0.f), 255.f);
        int x0 = (int)floorf(xc); int x1 = min(x0 + 1, W - 1);
        int y0 = (int)floorf(yc); int y1 = min(y0 + 1, H - 1);
        float wx = xc - (float)x0, wy = yc - (float)y0;
        float ox, oy;
        {
            const float* f = field;
            float v00 = f[y0 * W + x0], v01 = f[y0 * W + x1];
            float v10 = f[y1 * W + x0], v11 = f[y1 * W + x1];
            ox = (v00 * (1.f - wx) + v01 * wx) * (1.f - wy)
               + (v10 * (1.f - wx) + v11 * wx) * wy;
        }
        {
            const float* f = field + H * W;
            float v00 = f[y0 * W + x0], v01 = f[y0 * W + x1];
            float v10 = f[y1 * W + x0], v11 = f[y1 * W + x1];
            oy = (v00 * (1.f - wx) + v01 * wx) * (1.f - wy)
               + (v10 * (1.f - wx) + v11 * wx) * wy;
        }
        x = fminf(fmaxf(x + ox, 0.f), 255.f);
        y = fminf(fmaxf(y + oy, 0.f), 255.f);
    }
    out[2 * i] = x;
    out[2 * i + 1] = y;
}

// ---------------------------------------------------------------------------
extern "C" void kernel_launch(void* const* d_in, const int* in_sizes, int n_in,
                              void* d_out, int out_size)
{
    const float* f1  = (const float*)d_in[0];
    const float* f2  = (const float*)d_in[1];
    const float* cc  = (const float*)d_in[2];
    const float* cw1 = (const float*)d_in[3];
    const float* cb1 = (const float*)d_in[4];
    const float* cw2 = (const float*)d_in[5];
    const float* cb2 = (const float*)d_in[6];
    const float* cw3 = (const float*)d_in[7];
    const float* cb3 = (const float*)d_in[8];
    const float* cw4 = (const float*)d_in[9];
    const float* cb4 = (const float*)d_in[10];
    const float* rw1 = (const float*)d_in[11];
    const float* rb1 = (const float*)d_in[12];
    const float* rw2 = (const float*)d_in[13];
    const float* rb2 = (const float*)d_in[14];
    const float* rw3 = (const float*)d_in[15];
    const float* rb3 = (const float*)d_in[16];
    const float* rw4 = (const float*)d_in[17];
    const float* rb4 = (const float*)d_in[18];
    const int*   pnum = (const int*)d_in[19];

    float* out = (float*)d_out;
    float* out_cls = out;
    float* out_bin = out + 16384;
    float* out_ctr = out + 16384 + 65536;

    float *bufA, *bufB, *Wt1, *Wt2, *Wt3, *CW1, *CW2, *CW3, *field, *bin;
    cudaGetSymbolAddress((void**)&bufA, g_bufA);
    cudaGetSymbolAddress((void**)&bufB, g_bufB);
    cudaGetSymbolAddress((void**)&Wt1,  g_Wt1);
    cudaGetSymbolAddress((void**)&Wt2,  g_Wt2);
    cudaGetSymbolAddress((void**)&Wt3,  g_Wt3);
    cudaGetSymbolAddress((void**)&CW1,  g_CW1);
    cudaGetSymbolAddress((void**)&CW2,  g_CW2);
    cudaGetSymbolAddress((void**)&CW3,  g_CW3);
    cudaGetSymbolAddress((void**)&field, g_field);
    cudaGetSymbolAddress((void**)&bin,  g_bin);

    // DISJOINT buffer carving (branches run concurrently now):
    // bufA: [0,128)MiB r1bf | [128,192) f1bf | [192,224) h1 | [224,240) h2
    // bufB: [0,64)MiB r2bf  | [64,96) r3bf   | [96,112) f2h | [112,120) h3
    uint32_t* r1bf = (uint32_t*)bufA;
    uint32_t* f1bf = (uint32_t*)(bufA + 33554432u);
    uint32_t* h1   = (uint32_t*)(bufA + 50331648u);
    uint32_t* h2   = (uint32_t*)(bufA + 58720256u);
    uint32_t* r2bf = (uint32_t*)bufB;
    uint32_t* r3bf = (uint32_t*)(bufB + 16777216u);
    uint32_t* f2h  = (uint32_t*)(bufB + 25165824u);
    uint32_t* h3   = (uint32_t*)(bufB + 29360128u);

    cudaFuncSetAttribute(conv3x3_bf, cudaFuncAttributeMaxDynamicSharedMemorySize, CBF_SMEM);
    cudaFuncSetAttribute(conv3x3_h,  cudaFuncAttributeMaxDynamicSharedMemorySize, CH_SMEM);

    // ---- fork: cls chain on s2 (non-blocking), refine chain on default ----
    cudaStream_t s2;
    cudaStreamCreateWithFlags(&s2, cudaStreamNonBlocking);
    cudaEvent_t evF, evJ;
    cudaEventCreateWithFlags(&evF, cudaEventDisableTiming);
    cudaEventCreateWithFlags(&evJ, cudaEventDisableTiming);
    cudaEventRecord(evF, 0);
    cudaStreamWaitEvent(s2, evF, 0);

    {   // cls chain (s2)
        int b1 = (512 >> 4) * 9 * 4 * (1024 >> 4) * 8;
        int b2 = (1024 >> 4) * 9 * 4 * (512 >> 4) * 8;
        int b3 = (512 >> 4) * 9 * 4 * (256 >> 4) * 8;
        to_f16_pairs<<<16384, 256, 0, s2>>>(f2, f2h);
        wt_pack_f16<<<(b1 + 255) / 256, 256, 0, s2>>>(cw1, (float4*)CW1, 1024, 512);
        wt_pack_f16<<<(b2 + 255) / 256, 256, 0, s2>>>(cw2, (float4*)CW2, 512, 1024);
        wt_pack_f16<<<(b3 + 255) / 256, 256, 0, s2>>>(cw3, (float4*)CW3, 256, 512);
        conv3x3_h<<<dim3(64, 8), 256, CH_SMEM, s2>>>(f2h, (const float4*)CW1, cb1, h1, 512, 1024);
        conv3x3_h<<<dim3(64, 4), 256, CH_SMEM, s2>>>(h1,  (const float4*)CW2, cb2, h2, 1024, 512);
        conv3x3_h<<<dim3(64, 2), 256, CH_SMEM, s2>>>(h2,  (const float4*)CW3, cb3, h3, 512, 256);
        cls_kernel_h<<<64, 256, 0, s2>>>(h3, cw4, cb4, out_cls, bin);
        upsample_kernel<<<256, 256, 0, s2>>>(bin, out_bin);
    }
    {   // refine chain (default stream)
        int b1 = (512 >> 4) * 9 * 4 * (1024 >> 4) * 8;
        int b2 = (1024 >> 4) * 9 * 4 * (512 >> 4) * 8;
        int b3 = (512 >> 4) * 9 * 4 * (256 >> 4) * 8;
        wt_pack_bf16<<<(b1 + 255) / 256, 256>>>(rw1, (float4*)Wt1, 1024, 512);
        wt_pack_bf16<<<(b2 + 255) / 256, 256>>>(rw2, (float4*)Wt2, 512, 1024);
        wt_pack_bf16<<<(b3 + 255) / 256, 256>>>(rw3, (float4*)Wt3, 256, 512);
        to_bf16_pairs<<<65536, 256>>>(f1, f1bf);
        conv3x3_bf<<<dim3(256, 8), 256, CBF_SMEM>>>(f1bf, (const float4*)Wt1, rb1, r1bf, 512, 1024);
        conv3x3_bf<<<dim3(256, 4), 256, CBF_SMEM>>>(r1bf, (const float4*)Wt2, rb2, r2bf, 1024, 512);
        conv3x3_bf<<<dim3(256, 2), 256, CBF_SMEM>>>(r2bf, (const float4*)Wt3, rb3, r3bf, 512, 256);
        field_kernel_bf<<<256, 256>>>(r3bf, rw4, rb4, field);
        contour_kernel<<<(38400 + 255) / 256, 256>>>(cc, field, pnum, out_ctr, 38400);
    }

    // ---- join ----
    cudaEventRecord(evJ, s2);
    cudaStreamWaitEvent(0, evJ, 0);
}

// round 17
// speedup vs baseline: 12.1803x; 1.0356x over previous
#include <cuda_runtime.h>
#include <cuda_bf16.h>
#include <cuda_fp16.h>
#include <math.h>
#include <stdint.h>

// ---------------------------------------------------------------------------
// Scratch (device globals -- no runtime allocation allowed)
// ---------------------------------------------------------------------------
__device__ float g_bufA[1024u * 256u * 256u];   // 256 MiB
__device__ float g_bufB[512u * 256u * 256u];    // 128 MiB
__device__ float g_Wt1[1024u * 512u * 9u];      // refinement packed bf16 weights
__device__ float g_Wt2[512u * 1024u * 9u];
__device__ float g_Wt3[256u * 512u * 9u];
__device__ float g_CW1[1024u * 512u * 9u];      // cls packed fp16 weights
__device__ float g_CW2[512u * 1024u * 9u];
__device__ float g_CW3[256u * 512u * 9u];
__device__ float g_field[2 * 256 * 256];
__device__ float g_bin[128 * 128];

// ---------------------------------------------------------------------------
// Helpers (portable sm_80+ -- NO 'a'-suffix features)
// ---------------------------------------------------------------------------
__device__ __forceinline__ uint32_t pk_bf2(float a, float b) {
    unsigned short lo = __bfloat16_as_ushort(__float2bfloat16_rn(a));
    unsigned short hi = __bfloat16_as_ushort(__float2bfloat16_rn(b));
    return ((uint32_t)hi << 16) | lo;
}
__device__ __forceinline__ float bf_lo(uint32_t u) {
    return __bfloat162float(__ushort_as_bfloat16((unsigned short)(u & 0xFFFFu)));
}
__device__ __forceinline__ float bf_hi(uint32_t u) {
    return __bfloat162float(__ushort_as_bfloat16((unsigned short)(u >> 16)));
}
__device__ __forceinline__ uint32_t pk_h2(float a, float b) {
    unsigned short lo = __half_as_ushort(__float2half_rn(a));
    unsigned short hi = __half_as_ushort(__float2half_rn(b));
    return ((uint32_t)hi << 16) | lo;
}
__device__ __forceinline__ float h_lo(uint32_t u) {
    return __half2float(__ushort_as_half((unsigned short)(u & 0xFFFFu)));
}
__device__ __forceinline__ float h_hi(uint32_t u) {
    return __half2float(__ushort_as_half((unsigned short)(u >> 16)));
}

__device__ __forceinline__ void mma_bf16(float c[4],
                                         uint32_t a0, uint32_t a1, uint32_t a2, uint32_t a3,
                                         uint32_t b0, uint32_t b1) {
    asm volatile(
        "mma.sync.aligned.m16n8k16.row.col.f32.bf16.bf16.f32 "
        "{%0,%1,%2,%3}, {%4,%5,%6,%7}, {%8,%9}, {%0,%1,%2,%3};"
        : "+f"(c[0]), "+f"(c[1]), "+f"(c[2]), "+f"(c[3])
        : "r"(a0), "r"(a1), "r"(a2), "r"(a3), "r"(b0), "r"(b1));
}
__device__ __forceinline__ void mma_f16(float c[4],
                                        uint32_t a0, uint32_t a1, uint32_t a2, uint32_t a3,
                                        uint32_t b0, uint32_t b1) {
    asm volatile(
        "mma.sync.aligned.m16n8k16.row.col.f32.f16.f16.f32 "
        "{%0,%1,%2,%3}, {%4,%5,%6,%7}, {%8,%9}, {%0,%1,%2,%3};"
        : "+f"(c[0]), "+f"(c[1]), "+f"(c[2]), "+f"(c[3])
        : "r"(a0), "r"(a1), "r"(a2), "r"(a3), "r"(b0), "r"(b1));
}
__device__ __forceinline__ uint32_t smem_u32(const void* p) {
    uint32_t a;
    asm("{ .reg .u64 t; cvta.to.shared.u64 t, %1; cvt.u32.u64 %0, t; }" : "=r"(a) : "l"(p));
    return a;
}
__device__ __forceinline__ void cpa16(uint32_t dst, const void* src) {
    asm volatile("cp.async.cg.shared.global [%0], [%1], 16;" :: "r"(dst), "l"(src) : "memory");
}
#define CP_COMMIT() asm volatile("cp.async.commit_group;" ::: "memory")
#define CP_WAIT1()  asm volatile("cp.async.wait_group 1;" ::: "memory")
#define CP_WAIT0()  asm volatile("cp.async.wait_group 0;" ::: "memory")

// ---------------------------------------------------------------------------
// Weight packers: 16-ch chunks; k-slot 2p -> ch base+p, 2p+1 -> ch base+p+8.
// ---------------------------------------------------------------------------
__global__ void wt_pack_bf16(const float* __restrict__ w, float4* __restrict__ out,
                             int Cout, int Cin)
{
    int i = blockIdx.x * 256 + threadIdx.x;
    int total = (Cin >> 4) * 9 * 4 * (Cout >> 4) * 8;
    if (i >= total) return;
    int r  = i & 7;
    int g  = (i >> 3) % (Cout >> 4);
    int rest = (i >> 3) / (Cout >> 4);
    int qc = rest & 3;
    int tc = rest >> 2;
    int t  = tc % 9;
    int c  = tc / 9;
    int m  = g * 16 + r;
    int base = c * 16;
#define WV(mm, ci) w[((size_t)(mm) * Cin + (ci)) * 9 + t]
    uint32_t u0 = pk_bf2(WV(m,     base + qc),     WV(m,     base + qc + 8));
    uint32_t u1 = pk_bf2(WV(m + 8, base + qc),     WV(m + 8, base + qc + 8));
    uint32_t u2 = pk_bf2(WV(m,     base + qc + 4), WV(m,     base + qc + 12));
    uint32_t u3 = pk_bf2(WV(m + 8, base + qc + 4), WV(m + 8, base + qc + 12));
#undef WV
    out[i] = make_float4(__uint_as_float(u0), __uint_as_float(u1),
                         __uint_as_float(u2), __uint_as_float(u3));
}

__global__ void wt_pack_f16(const float* __restrict__ w, float4* __restrict__ out,
                            int Cout, int Cin)
{
    int i = blockIdx.x * 256 + threadIdx.x;
    int total = (Cin >> 4) * 9 * 4 * (Cout >> 4) * 8;
    if (i >= total) return;
    int r  = i & 7;
    int g  = (i >> 3) % (Cout >> 4);
    int rest = (i >> 3) / (Cout >> 4);
    int qc = rest & 3;
    int tc = rest >> 2;
    int t  = tc % 9;
    int c  = tc / 9;
    int m  = g * 16 + r;
    int base = c * 16;
#define WV(mm, ci) w[((size_t)(mm) * Cin + (ci)) * 9 + t]
    uint32_t u0 = pk_h2(WV(m,     base + qc),     WV(m,     base + qc + 8));
    uint32_t u1 = pk_h2(WV(m + 8, base + qc),     WV(m + 8, base + qc + 8));
    uint32_t u2 = pk_h2(WV(m,     base + qc + 4), WV(m,     base + qc + 12));
    uint32_t u3 = pk_h2(WV(m + 8, base + qc + 4), WV(m + 8, base + qc + 12));
#undef WV
    out[i] = make_float4(__uint_as_float(u0), __uint_as_float(u1),
                         __uint_as_float(u2), __uint_as_float(u3));
}

// f1 (NCHW fp32, 512x256x256) -> pair-interleaved bf16 planes (256 cp rows)
__global__ void to_bf16_pairs(const float* __restrict__ in, uint32_t* __restrict__ out)
{
    int i = blockIdx.x * 256 + threadIdx.x;
    if (i >= 256 * 65536) return;
    int cp = i >> 16, pix = i & 65535;
    int c_lo = ((cp >> 3) << 4) + (cp & 7);
    out[i] = pk_bf2(in[((size_t)c_lo << 16) + pix],
                    in[((size_t)(c_lo + 8) << 16) + pix]);
}

// f2 (NCHW fp32, 512x128x128) -> pair-interleaved fp16 planes (256 cp rows)
__global__ void to_f16_pairs(const float* __restrict__ in, uint32_t* __restrict__ out)
{
    int i = blockIdx.x * 256 + threadIdx.x;
    if (i >= 256 * 16384) return;
    int cp = i >> 14, pix = i & 16383;
    int c_lo = ((cp >> 3) << 4) + (cp & 7);
    out[i] = pk_h2(in[(size_t)c_lo * 16384 + pix],
                   in[(size_t)(c_lo + 8) * 16384 + pix]);
}

// ---------------------------------------------------------------------------
// BF16 mma.sync 3x3 SAME conv (refinement, 256x256), m16n8k16.
// 512 threads (16 warps = 4/SMSP), 3-stage cp.async ring, 1 sync/chunk.
// Warp tile 64x32 (4 mf x 4 nf). Same MMA order as R16 -> bit-identical.
// ---------------------------------------------------------------------------
#define SXB 264
#define SWB4 66
#define STAGE_XB (24 * SXB)
#define STAGE_WB (9 * 4 * SWB4 * 4)
#define STAGE_FB (STAGE_XB + STAGE_WB)
#define CBF_SMEM (3 * STAGE_FB * 4)    // 190080 B

__device__ __forceinline__ void stage_bf(
    uint32_t sx_b, uint32_t sw_b, const uint32_t* __restrict__ in,
    const float4* __restrict__ WtP, int y, int coTile, int c, int Cout, int tid)
{
#pragma unroll
    for (int it = 0; it < 3; it++) {            // 1536 items / 512
        int i = tid + (it << 9);
        int row = i >> 6, seg = i & 63;
        int ky = row >> 3, cpl = row & 7;
        int gy = y - 1 + ky;
        if ((unsigned)gy < 256u)
            cpa16(sx_b + (uint32_t)(row * SXB + 4 + seg * 4) * 4,
                  in + (((size_t)(c * 8 + cpl) * 256 + gy) * 256 + seg * 4));
    }
    for (int i = tid; i < 2304; i += 512) {     // weights: 2304 float4
        int r = i & 7, gl = (i >> 3) & 7, qc = (i >> 6) & 3, t = i >> 8;
        cpa16(sw_b + (uint32_t)(((t * 4 + qc) * SWB4 + gl * 8 + r) * 16),
              WtP + ((((size_t)(c * 9 + t) * 4 + qc) * (Cout >> 4) + (coTile >> 4) + gl) * 8 + r));
    }
}

__global__ __launch_bounds__(512, 1) void conv3x3_bf(
    const uint32_t* __restrict__ in, const float4* __restrict__ WtP,
    const float* __restrict__ bias, uint32_t* __restrict__ out,
    int Cin, int Cout)
{
    extern __shared__ uint32_t smb[];
    const uint32_t base_b = smem_u32(smb);

    const int y      = blockIdx.x;
    const int coTile = blockIdx.y << 7;
    const int tid  = threadIdx.x;
    const int lane = tid & 31;
    const int wid  = tid >> 5;                 // 0..15
    const int gBase = (wid >> 3) << 2;         // 0 / 4
    const int nBase = (wid & 7) << 5;          // 0..224
    const int qr = lane >> 2;
    const int qc = lane & 3;

    // pre-zero X areas of all 3 stages (halo cols + OOB ky rows)
    for (int i = tid; i < 3 * STAGE_XB / 4; i += 512) {
        int st = i / (STAGE_XB / 4);
        int j  = i - st * (STAGE_XB / 4);
        uint32_t a = base_b + (uint32_t)(st * STAGE_FB + j * 4) * 4;
        asm volatile("st.shared.v4.u32 [%0], {%1,%1,%1,%1};" :: "r"(a), "r"(0u));
    }
    __syncthreads();

    const int nch = Cin >> 4;
    stage_bf(base_b, base_b + STAGE_XB * 4, in, WtP, y, coTile, 0, Cout, tid);
    CP_COMMIT();
    {
        uint32_t sb = base_b + (uint32_t)STAGE_FB * 4;
        stage_bf(sb, sb + STAGE_XB * 4, in, WtP, y, coTile, 1, Cout, tid);
        CP_COMMIT();
    }

    float acc[4][4][4] = {};

    for (int c = 0; c < nch; c++) {
        if (c + 1 < nch) CP_WAIT1(); else CP_WAIT0();
        __syncthreads();
        if (c + 2 < nch) {
            uint32_t sb = base_b + (uint32_t)(((c + 2) % 3) * STAGE_FB) * 4;
            stage_bf(sb, sb + STAGE_XB * 4, in, WtP, y, coTile, c + 2, Cout, tid);
            CP_COMMIT();
        }

        const uint32_t* sX = smb + (c % 3) * STAGE_FB;
        const uint32_t* sW = sX + STAGE_XB;

#pragma unroll
        for (int ky = 0; ky < 3; ky++) {
#pragma unroll
            for (int kx = 0; kx < 3; kx++) {
                const int t = ky * 3 + kx;
                uint32_t A[4][4];
#pragma unroll
                for (int mf = 0; mf < 4; mf++) {
                    float4 av = *(const float4*)&sW[((t * 4 + qc) * SWB4
                                                     + (gBase + mf) * 8 + qr) << 2];
                    A[mf][0] = __float_as_uint(av.x);
                    A[mf][1] = __float_as_uint(av.y);
                    A[mf][2] = __float_as_uint(av.z);
                    A[mf][3] = __float_as_uint(av.w);
                }
#pragma unroll
                for (int nf = 0; nf < 4; nf++) {
                    int col = nBase + nf * 8 + qr + kx + 3;
                    uint32_t b0 = sX[(ky * 8 + qc)     * SXB + col];
                    uint32_t b1 = sX[(ky * 8 + qc + 4) * SXB + col];
#pragma unroll
                    for (int mf = 0; mf < 4; mf++)
                        mma_bf16(acc[mf][nf], A[mf][0], A[mf][1], A[mf][2], A[mf][3], b0, b1);
                }
            }
        }
    }

#pragma unroll
    for (int mf = 0; mf < 4; mf++) {
        int co = coTile + (gBase + mf) * 16 + qr;
        int cpg = ((co >> 4) << 3) + (co & 7);
        float bv0 = bias[co], bv1 = bias[co + 8];
#pragma unroll
        for (int nf = 0; nf < 4; nf++) {
            int px = nBase + nf * 8 + 2 * qc;
            uint32_t p0 = pk_bf2(fmaxf(acc[mf][nf][0] + bv0, 0.f),
                                 fmaxf(acc[mf][nf][2] + bv1, 0.f));
            uint32_t p1 = pk_bf2(fmaxf(acc[mf][nf][1] + bv0, 0.f),
                                 fmaxf(acc[mf][nf][3] + bv1, 0.f));
            uint2 v = { p0, p1 };
            *(uint2*)&out[((size_t)cpg << 16) + (y << 8) + px] = v;
        }
    }
}

// ---------------------------------------------------------------------------
// FP16 mma.sync 3x3 SAME conv (classification, 128x128), m16n8k16.
// 512 threads, 3-stage ring. CTA: 128 Cout x 256 px (2 rows).
// ---------------------------------------------------------------------------
#define SXH 136
#define STAGE_XH (32 * SXH)
#define STAGE_WH (9 * 4 * SWB4 * 4)
#define STAGE_FH (STAGE_XH + STAGE_WH)
#define CH_SMEM (3 * STAGE_FH * 4)        // 166272 B

__device__ __forceinline__ void stage_h(
    uint32_t st_b, const uint32_t* __restrict__ in, const float4* __restrict__ WtP,
    int y0, int coTile, int c, int Cout, int tid)
{
    const uint32_t xb = st_b;
    const uint32_t wb = st_b + STAGE_XH * 4;
#pragma unroll
    for (int it = 0; it < 2; it++) {            // 1024 items / 512
        int i = tid + (it << 9);
        int row = i >> 5, seg = i & 31;
        int ky4 = row >> 3, cpl = row & 7;
        int gy = y0 - 1 + ky4;
        if ((unsigned)gy < 128u)
            cpa16(xb + (uint32_t)(row * SXH + 4 + seg * 4) * 4,
                  in + ((size_t)(c * 8 + cpl) * 16384 + gy * 128 + seg * 4));
    }
    for (int i = tid; i < 2304; i += 512) {
        int r = i & 7, gl = (i >> 3) & 7, qc = (i >> 6) & 3, t = i >> 8;
        cpa16(wb + (uint32_t)(((t * 4 + qc) * SWB4 + gl * 8 + r) * 16),
              WtP + ((((size_t)(c * 9 + t) * 4 + qc) * (Cout >> 4) + (coTile >> 4) + gl) * 8 + r));
    }
}

__global__ __launch_bounds__(512) void conv3x3_h(
    const uint32_t* __restrict__ in, const float4* __restrict__ WtP,
    const float* __restrict__ bias, uint32_t* __restrict__ out,
    int Cin, int Cout)
{
    extern __shared__ uint32_t smh[];
    const uint32_t base_b = smem_u32(smh);

    const int y0     = blockIdx.x << 1;
    const int coTile = blockIdx.y << 7;
    const int tid  = threadIdx.x;
    const int lane = tid & 31;
    const int wid  = tid >> 5;
    const int gBase = (wid >> 3) << 2;
    const int nBase = (wid & 7) << 5;
    const int qr = lane >> 2;
    const int qc = lane & 3;

    for (int i = tid; i < 3 * STAGE_XH / 4; i += 512) {
        int st = i / (STAGE_XH / 4);
        int j  = i - st * (STAGE_XH / 4);
        uint32_t a = base_b + (uint32_t)(st * STAGE_FH + j * 4) * 4;
        asm volatile("st.shared.v4.u32 [%0], {%1,%1,%1,%1};" :: "r"(a), "r"(0u));
    }
    __syncthreads();

    const int nch = Cin >> 4;
    stage_h(base_b, in, WtP, y0, coTile, 0, Cout, tid);
    CP_COMMIT();
    stage_h(base_b + (uint32_t)STAGE_FH * 4, in, WtP, y0, coTile, 1, Cout, tid);
    CP_COMMIT();

    float acc[4][4][4] = {};

    for (int c = 0; c < nch; c++) {
        if (c + 1 < nch) CP_WAIT1(); else CP_WAIT0();
        __syncthreads();
        if (c + 2 < nch) {
            stage_h(base_b + (uint32_t)(((c + 2) % 3) * STAGE_FH) * 4,
                    in, WtP, y0, coTile, c + 2, Cout, tid);
            CP_COMMIT();
        }

        const uint32_t* sX = smh + (c % 3) * STAGE_FH;
        const uint32_t* sW = sX + STAGE_XH;

#pragma unroll
        for (int ky = 0; ky < 3; ky++) {
#pragma unroll
            for (int kx = 0; kx < 3; kx++) {
                const int t = ky * 3 + kx;
                uint32_t A[4][4];
#pragma unroll
                for (int mf = 0; mf < 4; mf++) {
                    float4 av = *(const float4*)&sW[((t * 4 + qc) * SWB4
                                                     + (gBase + mf) * 8 + qr) << 2];
                    A[mf][0] = __float_as_uint(av.x);
                    A[mf][1] = __float_as_uint(av.y);
                    A[mf][2] = __float_as_uint(av.z);
                    A[mf][3] = __float_as_uint(av.w);
                }
#pragma unroll
                for (int nf = 0; nf < 4; nf++) {
                    int col = nBase + nf * 8 + qr;
                    int r = col >> 7, x = col & 127;
                    int rowb = (r + ky) * 8;
                    uint32_t b0 = sX[(rowb + qc)     * SXH + x + kx + 3];
                    uint32_t b1 = sX[(rowb + qc + 4) * SXH + x + kx + 3];
#pragma unroll
                    for (int mf = 0; mf < 4; mf++)
                        mma_f16(acc[mf][nf], A[mf][0], A[mf][1], A[mf][2], A[mf][3], b0, b1);
                }
            }
        }
    }

#pragma unroll
    for (int mf = 0; mf < 4; mf++) {
        int co = coTile + (gBase + mf) * 16 + qr;
        int cpg = ((co >> 4) << 3) + (co & 7);
        float bv0 = bias[co], bv1 = bias[co + 8];
#pragma unroll
        for (int nf = 0; nf < 4; nf++) {
            int n = nBase + nf * 8 + 2 * qc;
            int r = n >> 7, x = n & 127;
            uint32_t p0 = pk_h2(fmaxf(acc[mf][nf][0] + bv0, 0.f),
                                fmaxf(acc[mf][nf][2] + bv1, 0.f));
            uint32_t p1 = pk_h2(fmaxf(acc[mf][nf][1] + bv0, 0.f),
                                fmaxf(acc[mf][nf][3] + bv1, 0.f));
            uint2 v = { p0, p1 };
            *(uint2*)&out[(size_t)cpg * 16384 + (y0 + r) * 128 + x] = v;
        }
    }
}

// ---------------------------------------------------------------------------
// Heads / transforms
// ---------------------------------------------------------------------------
__global__ void cls_kernel_h(const uint32_t* __restrict__ h, const float* __restrict__ w,
                             const float* __restrict__ b, float* __restrict__ cls,
                             float* __restrict__ bin)
{
    int p = blockIdx.x * 256 + threadIdx.x;
    float s = b[0];
#pragma unroll 8
    for (int cp = 0; cp < 128; cp++) {
        uint32_t u = h[(size_t)cp * 16384 + p];
        int c_lo = ((cp >> 3) << 4) + (cp & 7);
        s = fmaf(w[c_lo], h_lo(u), fmaf(w[c_lo + 8], h_hi(u), s));
    }
    float sig = 1.f / (1.f + expf(-s));
    cls[p] = sig;
    bin[p] = (sig >= 0.5f) ? 1.f : 0.f;
}

__global__ void field_kernel_bf(const uint32_t* __restrict__ r, const float* __restrict__ w,
                                const float* __restrict__ b, float* __restrict__ field)
{
    int p = blockIdx.x * 256 + threadIdx.x;
    float s0 = b[0], s1 = b[1];
#pragma unroll 8
    for (int cp = 0; cp < 128; cp++) {
        uint32_t u = r[((size_t)cp << 16) + p];
        float vlo = bf_lo(u), vhi = bf_hi(u);
        int c_lo = ((cp >> 3) << 4) + (cp & 7);
        s0 = fmaf(w[c_lo], vlo, fmaf(w[c_lo + 8], vhi, s0));
        s1 = fmaf(w[256 + c_lo], vlo, fmaf(w[256 + c_lo + 8], vhi, s1));
    }
    field[p] = s0;
    field[65536 + p] = s1;
}

__global__ void upsample_kernel(const float* __restrict__ bin, float* __restrict__ out)
{
    int idx = blockIdx.x * 256 + threadIdx.x;
    if (idx >= 256 * 256) return;
    int Y = idx >> 8, X = idx & 255;
    const float step = 127.0f / 255.0f;
    float ys = (float)Y * step, xs = (float)X * step;
    int y0 = (int)floorf(ys); int y1 = min(y0 + 1, 127);
    int x0 = (int)floorf(xs); int x1 = min(x0 + 1, 127);
    float wy = ys - (float)y0, wx = xs - (float)x0;
    float v00 = bin[y0 * 128 + x0], v01 = bin[y0 * 128 + x1];
    float v10 = bin[y1 * 128 + x0], v11 = bin[y1 * 128 + x1];
    out[idx] = rintf((v00 * (1.f - wx) + v01 * wx) * (1.f - wy)
                   + (v10 * (1.f - wx) + v11 * wx) * wy);
}

__global__ void contour_kernel(const float* __restrict__ cc,
                               const float* __restrict__ field,
                               const int* __restrict__ pnum_iter,
                               float* __restrict__ out, int npts)
{
    int i = blockIdx.x * 256 + threadIdx.x;
    if (i >= npts) return;
    const int W = 256, H = 256;
    float x = cc[2 * i], y = cc[2 * i + 1];
    int n = pnum_iter[0];
    for (int t = 0; t < n; t++) {
        float xc = fminf(fmaxf(x, 0.f), 255.f);
        float yc = fminf(fmaxf(y, 0.f), 255.f);
        int x0 = (int)floorf(xc); int x1 = min(x0 + 1, W - 1);
        int y0 = (int)floorf(yc); int y1 = min(y0 + 1, H - 1);
        float wx = xc - (float)x0, wy = yc - (float)y0;
        float ox, oy;
        {
            const float* f = field;
            float v00 = f[y0 * W + x0], v01 = f[y0 * W + x1];
            float v10 = f[y1 * W + x0], v11 = f[y1 * W + x1];
            ox = (v00 * (1.f - wx) + v01 * wx) * (1.f - wy)
               + (v10 * (1.f - wx) + v11 * wx) * wy;
        }
        {
            const float* f = field + H * W;
            float v00 = f[y0 * W + x0], v01 = f[y0 * W + x1];
            float v10 = f[y1 * W + x0], v11 = f[y1 * W + x1];
            oy = (v00 * (1.f - wx) + v01 * wx) * (1.f - wy)
               + (v10 * (1.f - wx) + v11 * wx) * wy;
        }
        x = fminf(fmaxf(x + ox, 0.f), 255.f);
        y = fminf(fmaxf(y + oy, 0.f), 255.f);
    }
    out[2 * i] = x;
    out[2 * i + 1] = y;
}

// ---------------------------------------------------------------------------
extern "C" void kernel_launch(void* const* d_in, const int* in_sizes, int n_in,
                              void* d_out, int out_size)
{
    const float* f1  = (const float*)d_in[0];
    const float* f2  = (const float*)d_in[1];
    const float* cc  = (const float*)d_in[2];
    const float* cw1 = (const float*)d_in[3];
    const float* cb1 = (const float*)d_in[4];
    const float* cw2 = (const float*)d_in[5];
    const float* cb2 = (const float*)d_in[6];
    const float* cw3 = (const float*)d_in[7];
    const float* cb3 = (const float*)d_in[8];
    const float* cw4 = (const float*)d_in[9];
    const float* cb4 = (const float*)d_in[10];
    const float* rw1 = (const float*)d_in[11];
    const float* rb1 = (const float*)d_in[12];
    const float* rw2 = (const float*)d_in[13];
    const float* rb2 = (const float*)d_in[14];
    const float* rw3 = (const float*)d_in[15];
    const float* rb3 = (const float*)d_in[16];
    const float* rw4 = (const float*)d_in[17];
    const float* rb4 = (const float*)d_in[18];
    const int*   pnum = (const int*)d_in[19];

    float* out = (float*)d_out;
    float* out_cls = out;
    float* out_bin = out + 16384;
    float* out_ctr = out + 16384 + 65536;

    float *bufA, *bufB, *Wt1, *Wt2, *Wt3, *CW1, *CW2, *CW3, *field, *bin;
    cudaGetSymbolAddress((void**)&bufA, g_bufA);
    cudaGetSymbolAddress((void**)&bufB, g_bufB);
    cudaGetSymbolAddress((void**)&Wt1,  g_Wt1);
    cudaGetSymbolAddress((void**)&Wt2,  g_Wt2);
    cudaGetSymbolAddress((void**)&Wt3,  g_Wt3);
    cudaGetSymbolAddress((void**)&CW1,  g_CW1);
    cudaGetSymbolAddress((void**)&CW2,  g_CW2);
    cudaGetSymbolAddress((void**)&CW3,  g_CW3);
    cudaGetSymbolAddress((void**)&field, g_field);
    cudaGetSymbolAddress((void**)&bin,  g_bin);

    // DISJOINT buffer carving (branches run concurrently):
    uint32_t* r1bf = (uint32_t*)bufA;
    uint32_t* f1bf = (uint32_t*)(bufA + 33554432u);
    uint32_t* h1   = (uint32_t*)(bufA + 50331648u);
    uint32_t* h2   = (uint32_t*)(bufA + 58720256u);
    uint32_t* r2bf = (uint32_t*)bufB;
    uint32_t* r3bf = (uint32_t*)(bufB + 16777216u);
    uint32_t* f2h  = (uint32_t*)(bufB + 25165824u);
    uint32_t* h3   = (uint32_t*)(bufB + 29360128u);

    cudaFuncSetAttribute(conv3x3_bf, cudaFuncAttributeMaxDynamicSharedMemorySize, CBF_SMEM);
    cudaFuncSetAttribute(conv3x3_h,  cudaFuncAttributeMaxDynamicSharedMemorySize, CH_SMEM);

    // ---- fork: cls chain on s2 (non-blocking), refine chain on default ----
    cudaStream_t s2;
    cudaStreamCreateWithFlags(&s2, cudaStreamNonBlocking);
    cudaEvent_t evF, evJ;
    cudaEventCreateWithFlags(&evF, cudaEventDisableTiming);
    cudaEventCreateWithFlags(&evJ, cudaEventDisableTiming);
    cudaEventRecord(evF, 0);
    cudaStreamWaitEvent(s2, evF, 0);

    {   // cls chain (s2)
        int b1 = (512 >> 4) * 9 * 4 * (1024 >> 4) * 8;
        int b2 = (1024 >> 4) * 9 * 4 * (512 >> 4) * 8;
        int b3 = (512 >> 4) * 9 * 4 * (256 >> 4) * 8;
        to_f16_pairs<<<16384, 256, 0, s2>>>(f2, f2h);
        wt_pack_f16<<<(b1 + 255) / 256, 256, 0, s2>>>(cw1, (float4*)CW1, 1024, 512);
        wt_pack_f16<<<(b2 + 255) / 256, 256, 0, s2>>>(cw2, (float4*)CW2, 512, 1024);
        wt_pack_f16<<<(b3 + 255) / 256, 256, 0, s2>>>(cw3, (float4*)CW3, 256, 512);
        conv3x3_h<<<dim3(64, 8), 512, CH_SMEM, s2>>>(f2h, (const float4*)CW1, cb1, h1, 512, 1024);
        conv3x3_h<<<dim3(64, 4), 512, CH_SMEM, s2>>>(h1,  (const float4*)CW2, cb2, h2, 1024, 512);
        conv3x3_h<<<dim3(64, 2), 512, CH_SMEM, s2>>>(h2,  (const float4*)CW3, cb3, h3, 512, 256);
        cls_kernel_h<<<64, 256, 0, s2>>>(h3, cw4, cb4, out_cls, bin);
        upsample_kernel<<<256, 256, 0, s2>>>(bin, out_bin);
    }
    {   // refine chain (default stream)
        int b1 = (512 >> 4) * 9 * 4 * (1024 >> 4) * 8;
        int b2 = (1024 >> 4) * 9 * 4 * (512 >> 4) * 8;
        int b3 = (512 >> 4) * 9 * 4 * (256 >> 4) * 8;
        wt_pack_bf16<<<(b1 + 255) / 256, 256>>>(rw1, (float4*)Wt1, 1024, 512);
        wt_pack_bf16<<<(b2 + 255) / 256, 256>>>(rw2, (float4*)Wt2, 512, 1024);
        wt_pack_bf16<<<(b3 + 255) / 256, 256>>>(rw3, (float4*)Wt3, 256, 512);
        to_bf16_pairs<<<65536, 256>>>(f1, f1bf);
        conv3x3_bf<<<dim3(256, 8), 512, CBF_SMEM>>>(f1bf, (const float4*)Wt1, rb1, r1bf, 512, 1024);
        conv3x3_bf<<<dim3(256, 4), 512, CBF_SMEM>>>(r1bf, (const float4*)Wt2, rb2, r2bf, 1024, 512);
        conv3x3_bf<<<dim3(256, 2), 512, CBF_SMEM>>>(r2bf, (const float4*)Wt3, rb3, r3bf, 512, 256);
        field_kernel_bf<<<256, 256>>>(r3bf, rw4, rb4, field);
        contour_kernel<<<(38400 + 255) / 256, 256>>>(cc, field, pnum, out_ctr, 38400);
    }

    // ---- join ----
    cudaEventRecord(evJ, s2);
    cudaStreamWaitEvent(0, evJ, 0);
}